// round 4
// baseline (speedup 1.0000x reference)
#include <cuda_runtime.h>
#include <cuda_bf16.h>
#include <math.h>
#include <stdint.h>

#define HID 128
#define NN 20000
#define NE 640000
#define ND 100000

// scratch (device globals: allocation-free contract)
__device__ float g_hn0[(size_t)NN * HID];
__device__ float g_hn1[(size_t)NN * HID];
__device__ float g_agg[(size_t)NN * HID];
__device__ float g_P1 [(size_t)NN * HID];
__device__ float g_P3 [(size_t)NN * HID];
// pre-split bf16 weight images: [n][k] row-major (n = output col, k contiguous)
__device__ __align__(16) __nv_bfloat16 g_Bh[2][128 * 128];
__device__ __align__(16) __nv_bfloat16 g_Bl[2][128 * 128];

// ======================= warp MMA helpers =======================
__device__ __forceinline__ uint32_t smem_u32(const void* p) {
    uint32_t a;
    asm("{ .reg .u64 t; cvta.to.shared.u64 t, %1; cvt.u32.u64 %0, t; }" : "=r"(a) : "l"(p));
    return a;
}
__device__ __forceinline__ void ldsm4(uint32_t& r0, uint32_t& r1, uint32_t& r2, uint32_t& r3,
                                      uint32_t addr) {
    asm volatile("ldmatrix.sync.aligned.m8n8.x4.shared.b16 {%0,%1,%2,%3}, [%4];"
                 : "=r"(r0), "=r"(r1), "=r"(r2), "=r"(r3) : "r"(addr));
}
__device__ __forceinline__ void mma16816(float* c, uint32_t a0, uint32_t a1, uint32_t a2,
                                         uint32_t a3, uint32_t b0, uint32_t b1) {
    asm volatile("mma.sync.aligned.m16n8k16.row.col.f32.bf16.bf16.f32 "
                 "{%0,%1,%2,%3}, {%4,%5,%6,%7}, {%8,%9}, {%0,%1,%2,%3};"
                 : "+f"(c[0]), "+f"(c[1]), "+f"(c[2]), "+f"(c[3])
                 : "r"(a0), "r"(a1), "r"(a2), "r"(a3), "r"(b0), "r"(b1));
}

// ---------------------------------------------------------------- node embed
__global__ void node_embed(const float* __restrict__ x, const float* __restrict__ W,
                           const float* __restrict__ b)
{
    __shared__ float Ws[32 * HID];
    __shared__ float xs[16][33];
    int tid = threadIdx.x; // 128
    for (int i = tid; i < 32 * HID; i += 128) Ws[i] = W[i];
    int row0 = blockIdx.x * 16;
    for (int i = tid; i < 16 * 32; i += 128) xs[i >> 5][i & 31] = x[(size_t)row0 * 32 + i];
    float bb = b[tid];
    __syncthreads();
#pragma unroll 4
    for (int r = 0; r < 16; r++) {
        float acc = bb;
#pragma unroll
        for (int k = 0; k < 32; k++) acc = fmaf(xs[r][k], Ws[k * HID + tid], acc);
        g_hn0[(size_t)(row0 + r) * HID + tid] = fmaxf(acc, 0.f);
    }
}

// ---------------------------------------------------------------- zero agg
__global__ void zero_agg()
{
    size_t i = (size_t)blockIdx.x * blockDim.x + threadIdx.x;
    if (i < (size_t)NN * HID / 4) ((float4*)g_agg)[i] = make_float4(0.f, 0.f, 0.f, 0.f);
}

// ---------------------------------------- weight prep: split hi/lo, [n][k]
__global__ void prep_w(const float* __restrict__ W0, const float* __restrict__ W1)
{
    const float* W = blockIdx.x ? W1 : W0;
    __nv_bfloat16* bh = g_Bh[blockIdx.x];
    __nv_bfloat16* bl = g_Bl[blockIdx.x];
    for (int idx = threadIdx.x; idx < 128 * 128; idx += blockDim.x) {
        int n = idx >> 7, k = idx & 127;
        float w = W[k * 128 + n];
        __nv_bfloat16 h = __float2bfloat16(w);
        float lo = w - __bfloat162float(h);
        bh[idx] = h;
        bl[idx] = __float2bfloat16(lo);
    }
}

// ------------------------------------------------- node-level GEMM (no act)
__global__ void __launch_bounds__(256, 2)
gemm128(int asel, int osel, const float* __restrict__ W)
{
    const float* __restrict__ A = asel ? g_hn1 : g_hn0;
    float* __restrict__ out = osel ? g_P3 : g_P1;
    __shared__ __align__(16) float As[16][132];
    __shared__ __align__(16) float Bs[16][132];

    const int tid   = threadIdx.x;
    const int nBase = blockIdx.x * 128;
    const int arow  = tid >> 1;
    const int akl   = (tid & 1) * 8;
    const int tx    = tid & 15, ty = tid >> 4;
    const int nrow  = min(nBase + arow, NN - 1);

    float acc[2][4][2][4];
#pragma unroll
    for (int a = 0; a < 2; a++)
#pragma unroll
        for (int i = 0; i < 4; i++)
#pragma unroll
            for (int b2 = 0; b2 < 2; b2++)
#pragma unroll
                for (int j = 0; j < 4; j++) acc[a][i][b2][j] = 0.f;

    float4 apf0, apf1, bpf0, bpf1;
    {
        const float* base = A + (size_t)nrow * HID;
        apf0 = *(const float4*)(base + akl);
        apf1 = *(const float4*)(base + akl + 4);
        const float4* wb = (const float4*)W;
        bpf0 = wb[tid]; bpf1 = wb[tid + 256];
    }

    for (int t = 0; t < 8; t++) {
        As[akl + 0][arow] = apf0.x; As[akl + 1][arow] = apf0.y;
        As[akl + 2][arow] = apf0.z; As[akl + 3][arow] = apf0.w;
        As[akl + 4][arow] = apf1.x; As[akl + 5][arow] = apf1.y;
        As[akl + 6][arow] = apf1.z; As[akl + 7][arow] = apf1.w;
        {
            int k0 = tid >> 5, c0 = (tid & 31) * 4;
            *(float4*)&Bs[k0][c0]     = bpf0;
            *(float4*)&Bs[k0 + 8][c0] = bpf1;
        }
        __syncthreads();
        if (t < 7) {
            int kb = (t + 1) * 16;
            const float* base = A + (size_t)nrow * HID + kb;
            apf0 = *(const float4*)(base + akl);
            apf1 = *(const float4*)(base + akl + 4);
            const float4* wb = (const float4*)(W + (size_t)kb * HID);
            bpf0 = wb[tid]; bpf1 = wb[tid + 256];
        }
#pragma unroll
        for (int k = 0; k < 16; k++) {
            float4 a0 = *(const float4*)&As[k][ty * 4];
            float4 a1 = *(const float4*)&As[k][64 + ty * 4];
            float4 b0 = *(const float4*)&Bs[k][tx * 4];
            float4 b1 = *(const float4*)&Bs[k][64 + tx * 4];
            float ar[8] = {a0.x, a0.y, a0.z, a0.w, a1.x, a1.y, a1.z, a1.w};
            float br[8] = {b0.x, b0.y, b0.z, b0.w, b1.x, b1.y, b1.z, b1.w};
#pragma unroll
            for (int a = 0; a < 2; a++)
#pragma unroll
                for (int i = 0; i < 4; i++)
#pragma unroll
                    for (int b2 = 0; b2 < 2; b2++)
#pragma unroll
                        for (int j = 0; j < 4; j++)
                            acc[a][i][b2][j] = fmaf(ar[a * 4 + i], br[b2 * 4 + j], acc[a][i][b2][j]);
        }
        __syncthreads();
    }

#pragma unroll
    for (int a = 0; a < 2; a++)
#pragma unroll
        for (int i = 0; i < 4; i++) {
            int r = nBase + a * 64 + ty * 4 + i;
            if (r < NN) {
#pragma unroll
                for (int b2 = 0; b2 < 2; b2++) {
                    int c = b2 * 64 + tx * 4;
                    *(float4*)&out[(size_t)r * HID + c] =
                        make_float4(acc[a][i][b2][0], acc[a][i][b2][1],
                                    acc[a][i][b2][2], acc[a][i][b2][3]);
                }
            }
        }
}

// ====================== persistent mma.sync edge kernel ======================
// SMEM layout (bytes). A/B tiles: [128 rows][136 bf16] = 272B stride (conflict-free LDSM)
#define SM_BM   0
#define SM_BE   512
#define SM_SRC  1024
#define SM_DST  1536
#define SM_EFS  2048            // float [128][17]
#define SM_WES  10752           // float [16][128]
#define SM_AH   18944
#define SM_AL   53760
#define SM_BH   88576
#define SM_BL   123392
#define SM_TOTAL 158208
#define TSTRIDE 272             // bytes per row (136 bf16)

__global__ void __launch_bounds__(256)
msg_v4(int layer, const int* __restrict__ eidx, const float* __restrict__ ef,
       const float* __restrict__ We, const float* __restrict__ be,
       const float* __restrict__ bm)
{
    extern __shared__ __align__(16) char smem[];
    const uint32_t sb = smem_u32(smem);
    const int tid = threadIdx.x;
    const int wid = tid >> 5, lane = tid & 31;

    float* sBm = (float*)(smem + SM_BM);
    float* beS = (float*)(smem + SM_BE);
    int*   sSrc = (int*)(smem + SM_SRC);
    int*   sDst = (int*)(smem + SM_DST);
    float* efs = (float*)(smem + SM_EFS);   // [128][17]
    float* Wes = (float*)(smem + SM_WES);   // [16][128]

    // ---- one-time setup
    if (tid < 128) { sBm[tid] = bm[tid]; beS[tid] = be[tid]; }
    {   // stage We [16 x 128]
        const float4* wg = (const float4*)We;
#pragma unroll
        for (int u = 0; u < 2; u++) {
            int g = tid * 2 + u;
            int row = g >> 5, c = (g & 31) * 4;
            *(float4*)&Wes[row * 128 + c] = wg[g];
        }
    }
    {   // stage B hi/lo into padded smem [n][136]
        const uint2* bh = (const uint2*)g_Bh[layer];
        const uint2* bl = (const uint2*)g_Bl[layer];
#pragma unroll
        for (int u = 0; u < 16; u++) {
            int g = tid + u * 256;           // 0..4095
            int n = g >> 5, kq = g & 31;     // 32 uint2 (=128 bf16) per n row
            *(uint2*)(smem + SM_BH + n * TSTRIDE + kq * 8) = bh[g];
            *(uint2*)(smem + SM_BL + n * TSTRIDE + kq * 8) = bl[g];
        }
    }

    const int row   = tid & 127;      // producer: edge row
    const int half  = tid >> 7;       // producer: col half
    const int kbase = half * 64;

    // ldmatrix lane offsets
    const int wm = wid * 16;          // warp's M strip
    const uint32_t aRowOff = (uint32_t)((wm + (lane & 7) + ((lane >> 3) & 1) * 8) * TSTRIDE
                                        + ((lane >> 4) * 8) * 2);
    const uint32_t bRowOff = (uint32_t)(((lane & 7) + (lane >> 4) * 8) * TSTRIDE
                                        + (((lane >> 3) & 1) * 8) * 2);
    const uint32_t aHiA = sb + SM_AH + aRowOff;
    const uint32_t aLoA = sb + SM_AL + aRowOff;
    const uint32_t bHiA = sb + SM_BH + bRowOff;
    const uint32_t bLoA = sb + SM_BL + bRowOff;

    // epilogue mapping
    const int er0 = wm + (lane >> 2);          // rows er0, er0+8
    const int cb  = (lane & 3) * 2;

    __syncthreads();

    for (int t = blockIdx.x; t < NE / 128; t += gridDim.x) {
        const int eBase = t * 128;
        if (tid < 128) sSrc[tid] = eidx[eBase + tid];
        else           sDst[tid - 128] = eidx[NE + eBase + tid - 128];
        {
            const float4* eg = (const float4*)(ef + (size_t)eBase * 16);
#pragma unroll
            for (int u = 0; u < 2; u++) {
                int g = tid * 2 + u;
                float4 v = eg[g];
                int r = g >> 2, c = (g & 3) * 4;
                efs[r * 17 + c + 0] = v.x; efs[r * 17 + c + 1] = v.y;
                efs[r * 17 + c + 2] = v.z; efs[r * 17 + c + 3] = v.w;
            }
        }
        __syncthreads();

        // ---- produce he fp32 (this thread: row, cols kbase..kbase+63)
        {
            float an[64];
#pragma unroll
            for (int j = 0; j < 64; j++) an[j] = beS[kbase + j];
#pragma unroll
            for (int q = 0; q < 16; q++) {
                float e = efs[row * 17 + q];
                const float4* wr = (const float4*)&Wes[q * 128 + kbase];
#pragma unroll
                for (int g = 0; g < 16; g++) {
                    float4 w = wr[g];
                    an[4 * g + 0] = fmaf(e, w.x, an[4 * g + 0]);
                    an[4 * g + 1] = fmaf(e, w.y, an[4 * g + 1]);
                    an[4 * g + 2] = fmaf(e, w.z, an[4 * g + 2]);
                    an[4 * g + 3] = fmaf(e, w.w, an[4 * g + 3]);
                }
            }
            // relu + split hi/lo bf16 into padded A tiles
#pragma unroll
            for (int g = 0; g < 8; g++) {
                uint32_t ph4[4], pl4[4];
#pragma unroll
                for (int p = 0; p < 4; p++) {
                    float v0 = fmaxf(an[8 * g + 2 * p + 0], 0.f);
                    float v1 = fmaxf(an[8 * g + 2 * p + 1], 0.f);
                    __nv_bfloat16 h0 = __float2bfloat16(v0);
                    __nv_bfloat16 h1 = __float2bfloat16(v1);
                    __nv_bfloat16 l0 = __float2bfloat16(v0 - __bfloat162float(h0));
                    __nv_bfloat16 l1 = __float2bfloat16(v1 - __bfloat162float(h1));
                    ph4[p] = (uint32_t)__bfloat16_as_ushort(h0) | ((uint32_t)__bfloat16_as_ushort(h1) << 16);
                    pl4[p] = (uint32_t)__bfloat16_as_ushort(l0) | ((uint32_t)__bfloat16_as_ushort(l1) << 16);
                }
                uint32_t off = (uint32_t)(row * TSTRIDE + (kbase + 8 * g) * 2);
                *(uint4*)(smem + SM_AH + off) = make_uint4(ph4[0], ph4[1], ph4[2], ph4[3]);
                *(uint4*)(smem + SM_AL + off) = make_uint4(pl4[0], pl4[1], pl4[2], pl4[3]);
            }
        }
        __syncthreads();

        // ---- warp MMA: D = Ahi*Bhi + Ahi*Blo + Alo*Bhi
        float acc[16][4];
#pragma unroll
        for (int n = 0; n < 16; n++)
#pragma unroll
            for (int j = 0; j < 4; j++) acc[n][j] = 0.f;

#pragma unroll
        for (int ks = 0; ks < 8; ks++) {
            uint32_t ah0, ah1, ah2, ah3, al0, al1, al2, al3;
            ldsm4(ah0, ah1, ah2, ah3, aHiA + ks * 32);
            ldsm4(al0, al1, al2, al3, aLoA + ks * 32);
#pragma unroll
            for (int np = 0; np < 8; np++) {
                uint32_t bh0, bh1, bh2, bh3, bl0, bl1, bl2, bl3;
                ldsm4(bh0, bh1, bh2, bh3, bHiA + np * (16 * TSTRIDE) + ks * 32);
                ldsm4(bl0, bl1, bl2, bl3, bLoA + np * (16 * TSTRIDE) + ks * 32);
                mma16816(acc[2 * np],     ah0, ah1, ah2, ah3, bh0, bh1);
                mma16816(acc[2 * np],     ah0, ah1, ah2, ah3, bl0, bl1);
                mma16816(acc[2 * np],     al0, al1, al2, al3, bh0, bh1);
                mma16816(acc[2 * np + 1], ah0, ah1, ah2, ah3, bh2, bh3);
                mma16816(acc[2 * np + 1], ah0, ah1, ah2, ah3, bl2, bl3);
                mma16816(acc[2 * np + 1], al0, al1, al2, al3, bh2, bh3);
            }
        }

        // ---- epilogue: rows er0, er0+8; cols nt*8 + cb + {0,1}
        {
            int s0 = sSrc[er0], d0 = sDst[er0];
            int s1 = sSrc[er0 + 8], d1 = sDst[er0 + 8];
            const float* p1a = g_P1 + (size_t)s0 * HID;
            const float* p3a = g_P3 + (size_t)d0 * HID;
            float*       aga = g_agg + (size_t)d0 * HID;
            const float* p1b = g_P1 + (size_t)s1 * HID;
            const float* p3b = g_P3 + (size_t)d1 * HID;
            float*       agb = g_agg + (size_t)d1 * HID;
#pragma unroll
            for (int nt = 0; nt < 16; nt++) {
                int col = nt * 8 + cb;
                float2 q1 = *(const float2*)(p1a + col);
                float2 q3 = *(const float2*)(p3a + col);
                float v0 = acc[nt][0] + sBm[col]     + q1.x + q3.x;
                float v1 = acc[nt][1] + sBm[col + 1] + q1.y + q3.y;
                if (v0 > 0.f) atomicAdd(aga + col,     v0);
                if (v1 > 0.f) atomicAdd(aga + col + 1, v1);
                float2 r1 = *(const float2*)(p1b + col);
                float2 r3 = *(const float2*)(p3b + col);
                float v2 = acc[nt][2] + sBm[col]     + r1.x + r3.x;
                float v3 = acc[nt][3] + sBm[col + 1] + r1.y + r3.y;
                if (v2 > 0.f) atomicAdd(agb + col,     v2);
                if (v3 > 0.f) atomicAdd(agb + col + 1, v3);
            }
        }
        __syncthreads();
    }
}

// ---------------------------------------------------------------- update GEMM
__global__ void __launch_bounds__(256, 2)
upd_gemm(int layer, const float* __restrict__ W, const float* __restrict__ bias)
{
    const float* __restrict__ hn   = layer ? g_hn1 : g_hn0;
    float*       __restrict__ hout = layer ? g_hn0 : g_hn1;
    __shared__ __align__(16) float As[16][132];
    __shared__ __align__(16) float Bs[16][132];
    __shared__ float sB[128];

    const int tid   = threadIdx.x;
    const int nBase = blockIdx.x * 128;
    if (tid < 128) sB[tid] = bias[tid];
    __syncthreads();

    const int arow = tid >> 1;
    const int akl  = (tid & 1) * 8;
    const int tx   = tid & 15, ty = tid >> 4;
    const int nrow = min(nBase + arow, NN - 1);

    float acc[2][4][2][4];
#pragma unroll
    for (int a = 0; a < 2; a++)
#pragma unroll
        for (int i = 0; i < 4; i++)
#pragma unroll
            for (int b2 = 0; b2 < 2; b2++)
#pragma unroll
                for (int j = 0; j < 4; j++) acc[a][i][b2][j] = 0.f;

    float4 apf0, apf1, bpf0, bpf1;
    {
        const float* base = hn + (size_t)nrow * HID;
        apf0 = *(const float4*)(base + akl);
        apf1 = *(const float4*)(base + akl + 4);
        const float4* wb = (const float4*)W;
        bpf0 = wb[tid]; bpf1 = wb[tid + 256];
    }

    for (int t = 0; t < 16; t++) {
        As[akl + 0][arow] = apf0.x; As[akl + 1][arow] = apf0.y;
        As[akl + 2][arow] = apf0.z; As[akl + 3][arow] = apf0.w;
        As[akl + 4][arow] = apf1.x; As[akl + 5][arow] = apf1.y;
        As[akl + 6][arow] = apf1.z; As[akl + 7][arow] = apf1.w;
        {
            int k0 = tid >> 5, c0 = (tid & 31) * 4;
            *(float4*)&Bs[k0][c0]     = bpf0;
            *(float4*)&Bs[k0 + 8][c0] = bpf1;
        }
        __syncthreads();
        if (t < 15) {
            int kb = (t + 1) * 16;
            int seg = kb >> 7, off = kb & 127;
            const float* base = (seg == 0) ? hn + (size_t)nrow * HID + off
                                           : g_agg + (size_t)nrow * HID + off;
            apf0 = *(const float4*)(base + akl);
            apf1 = *(const float4*)(base + akl + 4);
            const float4* wb = (const float4*)(W + (size_t)kb * HID);
            bpf0 = wb[tid]; bpf1 = wb[tid + 256];
        }
#pragma unroll
        for (int k = 0; k < 16; k++) {
            float4 a0 = *(const float4*)&As[k][ty * 4];
            float4 a1 = *(const float4*)&As[k][64 + ty * 4];
            float4 b0 = *(const float4*)&Bs[k][tx * 4];
            float4 b1 = *(const float4*)&Bs[k][64 + tx * 4];
            float ar[8] = {a0.x, a0.y, a0.z, a0.w, a1.x, a1.y, a1.z, a1.w};
            float br[8] = {b0.x, b0.y, b0.z, b0.w, b1.x, b1.y, b1.z, b1.w};
#pragma unroll
            for (int a = 0; a < 2; a++)
#pragma unroll
                for (int i = 0; i < 4; i++)
#pragma unroll
                    for (int b2 = 0; b2 < 2; b2++)
#pragma unroll
                        for (int j = 0; j < 4; j++)
                            acc[a][i][b2][j] = fmaf(ar[a * 4 + i], br[b2 * 4 + j], acc[a][i][b2][j]);
        }
        __syncthreads();
    }

#pragma unroll
    for (int a = 0; a < 2; a++)
#pragma unroll
        for (int i = 0; i < 4; i++) {
            int r = nBase + a * 64 + ty * 4 + i;
            if (r < NN) {
#pragma unroll
                for (int b2 = 0; b2 < 2; b2++)
#pragma unroll
                    for (int j = 0; j < 4; j++) {
                        int c = b2 * 64 + tx * 4 + j;
                        hout[(size_t)r * HID + c] = fmaxf(acc[a][i][b2][j] + sB[c], 0.f);
                    }
            }
        }
}

// --------------------------------------------- fused demand readout
__global__ void __launch_bounds__(256)
dem_v2(const int* __restrict__ pairs, const float* __restrict__ dfeat,
       const float* __restrict__ Wd, const float* __restrict__ br1,
       const float* __restrict__ w2, const float* __restrict__ b2,
       float* __restrict__ out)
{
    __shared__ __align__(16) float Wds[8][132];
    __shared__ float w2s[128], bs[128];
    int tid = threadIdx.x;
    if (tid < 128) { w2s[tid] = w2[tid]; bs[tid] = br1[tid]; }
    {
        int row = tid >> 5, c = (tid & 31) * 4;
        *(float4*)&Wds[row][c] = ((const float4*)Wd)[tid];
    }
    __syncthreads();

    int w = tid >> 5, lane = tid & 31;
    int d = blockIdx.x * 8 + w;
    int ds = pairs[2 * d], dd = pairs[2 * d + 1];
    int c0 = lane * 4;

    float4 q1 = *(const float4*)(g_P1 + (size_t)ds * HID + c0);
    float4 q2 = *(const float4*)(g_P3 + (size_t)dd * HID + c0);
    float s0 = bs[c0 + 0] + q1.x + q2.x;
    float s1 = bs[c0 + 1] + q1.y + q2.y;
    float s2 = bs[c0 + 2] + q1.z + q2.z;
    float s3 = bs[c0 + 3] + q1.w + q2.w;
#pragma unroll
    for (int q = 0; q < 8; q++) {
        float e = dfeat[(size_t)d * 8 + q];
        float4 wv = *(const float4*)&Wds[q][c0];
        s0 = fmaf(e, wv.x, s0); s1 = fmaf(e, wv.y, s1);
        s2 = fmaf(e, wv.z, s2); s3 = fmaf(e, wv.w, s3);
    }
    float p = fmaxf(s0, 0.f) * w2s[c0 + 0] + fmaxf(s1, 0.f) * w2s[c0 + 1]
            + fmaxf(s2, 0.f) * w2s[c0 + 2] + fmaxf(s3, 0.f) * w2s[c0 + 3];
#pragma unroll
    for (int o = 16; o > 0; o >>= 1) p += __shfl_xor_sync(0xffffffffu, p, o);
    if (lane == 0) out[d] = 1.f / (1.f + expf(-(p + b2[0])));
}

// ---------------------------------------------------------------- launch
extern "C" void kernel_launch(void* const* d_in, const int* in_sizes, int n_in,
                              void* d_out, int out_size)
{
    const float* node_feats = (const float*)d_in[0];
    const float* edge_feats = (const float*)d_in[1];
    const float* dem_feats  = (const float*)d_in[2];
    const int*   eidx       = (const int*)d_in[3];
    const int*   pairs      = (const int*)d_in[4];
    const float* W_node = (const float*)d_in[5];
    const float* b_node = (const float*)d_in[6];
    const float* W_edge = (const float*)d_in[7];
    const float* b_edge = (const float*)d_in[8];
    const float* W_msg0 = (const float*)d_in[9];
    const float* b_msg0 = (const float*)d_in[10];
    const float* W_upd0 = (const float*)d_in[11];
    const float* b_upd0 = (const float*)d_in[12];
    const float* W_msg1 = (const float*)d_in[13];
    const float* b_msg1 = (const float*)d_in[14];
    const float* W_upd1 = (const float*)d_in[15];
    const float* b_upd1 = (const float*)d_in[16];
    const float* W_r1   = (const float*)d_in[17];
    const float* b_r1   = (const float*)d_in[18];
    const float* W_r2   = (const float*)d_in[19];
    const float* b_r2   = (const float*)d_in[20];
    float* out = (float*)d_out;

    const int nTiles = (NN + 127) / 128;

    cudaFuncSetAttribute(msg_v4, cudaFuncAttributeMaxDynamicSharedMemorySize, SM_TOTAL);

    node_embed<<<NN / 16, 128>>>(node_feats, W_node, b_node);
    prep_w<<<2, 256>>>(W_msg0 + 128 * HID, W_msg1 + 128 * HID);

    // ---- layer 0
    gemm128<<<nTiles, 256>>>(0, 0, W_msg0);
    gemm128<<<nTiles, 256>>>(0, 1, W_msg0 + 256 * HID);
    zero_agg<<<(NN * HID / 4 + 255) / 256, 256>>>();
    msg_v4<<<152, 256, SM_TOTAL>>>(0, eidx, edge_feats, W_edge, b_edge, b_msg0);
    upd_gemm<<<nTiles, 256>>>(0, W_upd0, b_upd0);

    // ---- layer 1
    gemm128<<<nTiles, 256>>>(1, 0, W_msg1);
    gemm128<<<nTiles, 256>>>(1, 1, W_msg1 + 256 * HID);
    zero_agg<<<(NN * HID / 4 + 255) / 256, 256>>>();
    msg_v4<<<152, 256, SM_TOTAL>>>(1, eidx, edge_feats, W_edge, b_edge, b_msg1);
    upd_gemm<<<nTiles, 256>>>(1, W_upd1, b_upd1);

    // ---- readout
    gemm128<<<nTiles, 256>>>(0, 0, W_r1);
    gemm128<<<nTiles, 256>>>(0, 1, W_r1 + 128 * HID);
    dem_v2<<<ND / 8, 256>>>(pairs, dem_feats, W_r1 + 256 * HID, b_r1, W_r2, b_r2, out);
}

// round 5
// speedup vs baseline: 1.1187x; 1.1187x over previous
#include <cuda_runtime.h>
#include <cuda_bf16.h>
#include <math.h>
#include <stdint.h>

#define HID 128
#define NN 20000
#define NE 640000
#define ND 100000

// scratch (device globals: allocation-free contract)
__device__ float g_hn0[(size_t)NN * HID];
__device__ float g_hn1[(size_t)NN * HID];
__device__ float g_agg[(size_t)NN * HID];
__device__ float g_P1 [(size_t)NN * HID];
__device__ float g_P3 [(size_t)NN * HID];
__device__ __align__(16) __nv_bfloat16 g_Bh[2][128 * 128];
__device__ __align__(16) __nv_bfloat16 g_Bl[2][128 * 128];
// edge sort-by-dst
__device__ int g_cnt[NN + 1];
__device__ int g_srcp[NE];
__device__ int g_dstp[NE];
__device__ int g_eper[NE];

// ======================= warp MMA helpers =======================
__device__ __forceinline__ uint32_t smem_u32(const void* p) {
    uint32_t a;
    asm("{ .reg .u64 t; cvta.to.shared.u64 t, %1; cvt.u32.u64 %0, t; }" : "=r"(a) : "l"(p));
    return a;
}
__device__ __forceinline__ void ldsm4(uint32_t& r0, uint32_t& r1, uint32_t& r2, uint32_t& r3,
                                      uint32_t addr) {
    asm volatile("ldmatrix.sync.aligned.m8n8.x4.shared.b16 {%0,%1,%2,%3}, [%4];"
                 : "=r"(r0), "=r"(r1), "=r"(r2), "=r"(r3) : "r"(addr));
}
__device__ __forceinline__ void mma16816(float* c, uint32_t a0, uint32_t a1, uint32_t a2,
                                         uint32_t a3, uint32_t b0, uint32_t b1) {
    asm volatile("mma.sync.aligned.m16n8k16.row.col.f32.bf16.bf16.f32 "
                 "{%0,%1,%2,%3}, {%4,%5,%6,%7}, {%8,%9}, {%0,%1,%2,%3};"
                 : "+f"(c[0]), "+f"(c[1]), "+f"(c[2]), "+f"(c[3])
                 : "r"(a0), "r"(a1), "r"(a2), "r"(a3), "r"(b0), "r"(b1));
}

// ---------------------------------------------------------------- sort by dst
__global__ void zcnt()
{
    int i = blockIdx.x * 256 + threadIdx.x;
    if (i <= NN) g_cnt[i] = 0;
}
__global__ void hist(const int* __restrict__ eidx)
{
    int e = blockIdx.x * 256 + threadIdx.x;
    atomicAdd(&g_cnt[eidx[NE + e]], 1);
}
__global__ void scan20k()
{
    __shared__ int part[1024];
    __shared__ int wsum[32];
    const int tid = threadIdx.x;
    const int CH = 20;                       // 1024*20 = 20480 >= 20001
    int base = tid * CH;
    int loc[CH];
    int s = 0;
#pragma unroll
    for (int i = 0; i < CH; i++) {
        int v = (base + i <= NN) ? g_cnt[base + i] : 0;
        loc[i] = s; s += v;
    }
    part[tid] = s;
    __syncthreads();
    int lane = tid & 31, w = tid >> 5;
    int v = part[tid];
#pragma unroll
    for (int o = 1; o < 32; o <<= 1) { int t = __shfl_up_sync(~0u, v, o); if (lane >= o) v += t; }
    if (lane == 31) wsum[w] = v;
    __syncthreads();
    if (w == 0) {
        int x = wsum[lane];
#pragma unroll
        for (int o = 1; o < 32; o <<= 1) { int t = __shfl_up_sync(~0u, x, o); if (lane >= o) x += t; }
        wsum[lane] = x;
    }
    __syncthreads();
    int excl = v - part[tid] + (w ? wsum[w - 1] : 0);
#pragma unroll
    for (int i = 0; i < CH; i++)
        if (base + i <= NN) g_cnt[base + i] = excl + loc[i];
}
__global__ void scatter(const int* __restrict__ eidx)
{
    int e = blockIdx.x * 256 + threadIdx.x;
    int s = eidx[e], d = eidx[NE + e];
    int p = atomicAdd(&g_cnt[d], 1);
    g_srcp[p] = s; g_dstp[p] = d; g_eper[p] = e;
}

// ---------------------------------------------------------------- node embed
__global__ void node_embed(const float* __restrict__ x, const float* __restrict__ W,
                           const float* __restrict__ b)
{
    __shared__ float Ws[32 * HID];
    __shared__ float xs[16][33];
    int tid = threadIdx.x; // 128
    for (int i = tid; i < 32 * HID; i += 128) Ws[i] = W[i];
    int row0 = blockIdx.x * 16;
    for (int i = tid; i < 16 * 32; i += 128) xs[i >> 5][i & 31] = x[(size_t)row0 * 32 + i];
    float bb = b[tid];
    __syncthreads();
#pragma unroll 4
    for (int r = 0; r < 16; r++) {
        float acc = bb;
#pragma unroll
        for (int k = 0; k < 32; k++) acc = fmaf(xs[r][k], Ws[k * HID + tid], acc);
        g_hn0[(size_t)(row0 + r) * HID + tid] = fmaxf(acc, 0.f);
    }
}

// ---------------------------------------------------------------- zero agg
__global__ void zero_agg()
{
    size_t i = (size_t)blockIdx.x * blockDim.x + threadIdx.x;
    if (i < (size_t)NN * HID / 4) ((float4*)g_agg)[i] = make_float4(0.f, 0.f, 0.f, 0.f);
}

// ---------------------------------------- weight prep: split hi/lo, [n][k]
__global__ void prep_w(const float* __restrict__ W0, const float* __restrict__ W1)
{
    const float* W = blockIdx.x ? W1 : W0;
    __nv_bfloat16* bh = g_Bh[blockIdx.x];
    __nv_bfloat16* bl = g_Bl[blockIdx.x];
    for (int idx = threadIdx.x; idx < 128 * 128; idx += blockDim.x) {
        int n = idx >> 7, k = idx & 127;
        float w = W[k * 128 + n];
        __nv_bfloat16 h = __float2bfloat16(w);
        float lo = w - __bfloat162float(h);
        bh[idx] = h;
        bl[idx] = __float2bfloat16(lo);
    }
}

// ------------------------------------------------- node-level GEMM (no act)
__global__ void __launch_bounds__(256, 2)
gemm128(int asel, int osel, const float* __restrict__ W)
{
    const float* __restrict__ A = asel ? g_hn1 : g_hn0;
    float* __restrict__ out = osel ? g_P3 : g_P1;
    __shared__ __align__(16) float As[16][132];
    __shared__ __align__(16) float Bs[16][132];

    const int tid   = threadIdx.x;
    const int nBase = blockIdx.x * 128;
    const int arow  = tid >> 1;
    const int akl   = (tid & 1) * 8;
    const int tx    = tid & 15, ty = tid >> 4;
    const int nrow  = min(nBase + arow, NN - 1);

    float acc[2][4][2][4];
#pragma unroll
    for (int a = 0; a < 2; a++)
#pragma unroll
        for (int i = 0; i < 4; i++)
#pragma unroll
            for (int b2 = 0; b2 < 2; b2++)
#pragma unroll
                for (int j = 0; j < 4; j++) acc[a][i][b2][j] = 0.f;

    float4 apf0, apf1, bpf0, bpf1;
    {
        const float* base = A + (size_t)nrow * HID;
        apf0 = *(const float4*)(base + akl);
        apf1 = *(const float4*)(base + akl + 4);
        const float4* wb = (const float4*)W;
        bpf0 = wb[tid]; bpf1 = wb[tid + 256];
    }

    for (int t = 0; t < 8; t++) {
        As[akl + 0][arow] = apf0.x; As[akl + 1][arow] = apf0.y;
        As[akl + 2][arow] = apf0.z; As[akl + 3][arow] = apf0.w;
        As[akl + 4][arow] = apf1.x; As[akl + 5][arow] = apf1.y;
        As[akl + 6][arow] = apf1.z; As[akl + 7][arow] = apf1.w;
        {
            int k0 = tid >> 5, c0 = (tid & 31) * 4;
            *(float4*)&Bs[k0][c0]     = bpf0;
            *(float4*)&Bs[k0 + 8][c0] = bpf1;
        }
        __syncthreads();
        if (t < 7) {
            int kb = (t + 1) * 16;
            const float* base = A + (size_t)nrow * HID + kb;
            apf0 = *(const float4*)(base + akl);
            apf1 = *(const float4*)(base + akl + 4);
            const float4* wb = (const float4*)(W + (size_t)kb * HID);
            bpf0 = wb[tid]; bpf1 = wb[tid + 256];
        }
#pragma unroll
        for (int k = 0; k < 16; k++) {
            float4 a0 = *(const float4*)&As[k][ty * 4];
            float4 a1 = *(const float4*)&As[k][64 + ty * 4];
            float4 b0 = *(const float4*)&Bs[k][tx * 4];
            float4 b1 = *(const float4*)&Bs[k][64 + tx * 4];
            float ar[8] = {a0.x, a0.y, a0.z, a0.w, a1.x, a1.y, a1.z, a1.w};
            float br[8] = {b0.x, b0.y, b0.z, b0.w, b1.x, b1.y, b1.z, b1.w};
#pragma unroll
            for (int a = 0; a < 2; a++)
#pragma unroll
                for (int i = 0; i < 4; i++)
#pragma unroll
                    for (int b2 = 0; b2 < 2; b2++)
#pragma unroll
                        for (int j = 0; j < 4; j++)
                            acc[a][i][b2][j] = fmaf(ar[a * 4 + i], br[b2 * 4 + j], acc[a][i][b2][j]);
        }
        __syncthreads();
    }

#pragma unroll
    for (int a = 0; a < 2; a++)
#pragma unroll
        for (int i = 0; i < 4; i++) {
            int r = nBase + a * 64 + ty * 4 + i;
            if (r < NN) {
#pragma unroll
                for (int b2 = 0; b2 < 2; b2++) {
                    int c = b2 * 64 + tx * 4;
                    *(float4*)&out[(size_t)r * HID + c] =
                        make_float4(acc[a][i][b2][0], acc[a][i][b2][1],
                                    acc[a][i][b2][2], acc[a][i][b2][3]);
                }
            }
        }
}

// ====================== persistent mma.sync edge kernel (dst-sorted) =========
#define SM_BM   0
#define SM_BE   512
#define SM_SRC  1024
#define SM_DST  1536
#define SM_EFS  2048            // float [128][17]
#define SM_WES  10752           // float [16][128]
#define SM_AH   18944
#define SM_AL   53760
#define SM_BH   88576
#define SM_BL   123392
#define SM_TOTAL 158208
#define TSTRIDE 272             // bytes per row (136 bf16)
#define SM_OUT  SM_AH           // aliased: [128][132] fp32 msg tile (67584B)

__global__ void __launch_bounds__(256)
msg_v5(int layer, const float* __restrict__ ef,
       const float* __restrict__ We, const float* __restrict__ be,
       const float* __restrict__ bm)
{
    extern __shared__ __align__(16) char smem[];
    const uint32_t sb = smem_u32(smem);
    const int tid = threadIdx.x;
    const int wid = tid >> 5, lane = tid & 31;

    float* sBm = (float*)(smem + SM_BM);
    float* beS = (float*)(smem + SM_BE);
    int*   sSrc = (int*)(smem + SM_SRC);
    int*   sDst = (int*)(smem + SM_DST);
    float* efs = (float*)(smem + SM_EFS);   // [128][17]
    float* Wes = (float*)(smem + SM_WES);   // [16][128]
    float* OUT = (float*)(smem + SM_OUT);   // [128][132]

    // ---- one-time setup
    if (tid < 128) { sBm[tid] = bm[tid]; beS[tid] = be[tid]; }
    {   // stage We [16 x 128]
        const float4* wg = (const float4*)We;
#pragma unroll
        for (int u = 0; u < 2; u++) {
            int g = tid * 2 + u;
            int row = g >> 5, c = (g & 31) * 4;
            *(float4*)&Wes[row * 128 + c] = wg[g];
        }
    }
    {   // stage B hi/lo into padded smem [n][136]
        const uint2* bh = (const uint2*)g_Bh[layer];
        const uint2* bl = (const uint2*)g_Bl[layer];
#pragma unroll
        for (int u = 0; u < 16; u++) {
            int g = tid + u * 256;
            int n = g >> 5, kq = g & 31;
            *(uint2*)(smem + SM_BH + n * TSTRIDE + kq * 8) = bh[g];
            *(uint2*)(smem + SM_BL + n * TSTRIDE + kq * 8) = bl[g];
        }
    }

    const int row   = tid & 127;
    const int half  = tid >> 7;
    const int kbase = half * 64;

    const int wm = wid * 16;
    const uint32_t aRowOff = (uint32_t)((wm + (lane & 7) + ((lane >> 3) & 1) * 8) * TSTRIDE
                                        + ((lane >> 4) * 8) * 2);
    const uint32_t bRowOff = (uint32_t)(((lane & 7) + (lane >> 4) * 8) * TSTRIDE
                                        + (((lane >> 3) & 1) * 8) * 2);
    const uint32_t aHiA = sb + SM_AH + aRowOff;
    const uint32_t aLoA = sb + SM_AL + aRowOff;
    const uint32_t bHiA = sb + SM_BH + bRowOff;
    const uint32_t bLoA = sb + SM_BL + bRowOff;

    const int er0 = wm + (lane >> 2);
    const int cb  = (lane & 3) * 2;

    __syncthreads();

    for (int t = blockIdx.x; t < NE / 128; t += gridDim.x) {
        const int eBase = t * 128;
        // ---- stage indices (sorted by dst) and permuted ef rows
        if (tid < 128) sSrc[tid] = g_srcp[eBase + tid];
        else           sDst[tid - 128] = g_dstp[eBase + tid - 128];
        {
            int r = tid >> 1, u = tid & 1;
            int eid = g_eper[eBase + r];
            const float4* eg = (const float4*)(ef + (size_t)eid * 16) + u * 2;
            float4 v0 = eg[0], v1 = eg[1];
            float* dstp = &efs[r * 17 + u * 8];
            dstp[0] = v0.x; dstp[1] = v0.y; dstp[2] = v0.z; dstp[3] = v0.w;
            dstp[4] = v1.x; dstp[5] = v1.y; dstp[6] = v1.z; dstp[7] = v1.w;
        }
        __syncthreads();

        // ---- produce he fp32 (this thread: row, cols kbase..kbase+63)
        {
            float an[64];
#pragma unroll
            for (int j = 0; j < 64; j++) an[j] = beS[kbase + j];
#pragma unroll
            for (int q = 0; q < 16; q++) {
                float e = efs[row * 17 + q];
                const float4* wr = (const float4*)&Wes[q * 128 + kbase];
#pragma unroll
                for (int g = 0; g < 16; g++) {
                    float4 w = wr[g];
                    an[4 * g + 0] = fmaf(e, w.x, an[4 * g + 0]);
                    an[4 * g + 1] = fmaf(e, w.y, an[4 * g + 1]);
                    an[4 * g + 2] = fmaf(e, w.z, an[4 * g + 2]);
                    an[4 * g + 3] = fmaf(e, w.w, an[4 * g + 3]);
                }
            }
#pragma unroll
            for (int g = 0; g < 8; g++) {
                uint32_t ph4[4], pl4[4];
#pragma unroll
                for (int p = 0; p < 4; p++) {
                    float v0 = fmaxf(an[8 * g + 2 * p + 0], 0.f);
                    float v1 = fmaxf(an[8 * g + 2 * p + 1], 0.f);
                    __nv_bfloat16 h0 = __float2bfloat16(v0);
                    __nv_bfloat16 h1 = __float2bfloat16(v1);
                    __nv_bfloat16 l0 = __float2bfloat16(v0 - __bfloat162float(h0));
                    __nv_bfloat16 l1 = __float2bfloat16(v1 - __bfloat162float(h1));
                    ph4[p] = (uint32_t)__bfloat16_as_ushort(h0) | ((uint32_t)__bfloat16_as_ushort(h1) << 16);
                    pl4[p] = (uint32_t)__bfloat16_as_ushort(l0) | ((uint32_t)__bfloat16_as_ushort(l1) << 16);
                }
                uint32_t off = (uint32_t)(row * TSTRIDE + (kbase + 8 * g) * 2);
                *(uint4*)(smem + SM_AH + off) = make_uint4(ph4[0], ph4[1], ph4[2], ph4[3]);
                *(uint4*)(smem + SM_AL + off) = make_uint4(pl4[0], pl4[1], pl4[2], pl4[3]);
            }
        }
        __syncthreads();

        // ---- warp MMA: D = Ahi*Bhi + Ahi*Blo + Alo*Bhi
        float acc[16][4];
#pragma unroll
        for (int n = 0; n < 16; n++)
#pragma unroll
            for (int j = 0; j < 4; j++) acc[n][j] = 0.f;

#pragma unroll
        for (int ks = 0; ks < 8; ks++) {
            uint32_t ah0, ah1, ah2, ah3, al0, al1, al2, al3;
            ldsm4(ah0, ah1, ah2, ah3, aHiA + ks * 32);
            ldsm4(al0, al1, al2, al3, aLoA + ks * 32);
#pragma unroll
            for (int np = 0; np < 8; np++) {
                uint32_t bh0, bh1, bh2, bh3, bl0, bl1, bl2, bl3;
                ldsm4(bh0, bh1, bh2, bh3, bHiA + np * (16 * TSTRIDE) + ks * 32);
                ldsm4(bl0, bl1, bl2, bl3, bLoA + np * (16 * TSTRIDE) + ks * 32);
                mma16816(acc[2 * np],     ah0, ah1, ah2, ah3, bh0, bh1);
                mma16816(acc[2 * np],     ah0, ah1, ah2, ah3, bl0, bl1);
                mma16816(acc[2 * np],     al0, al1, al2, al3, bh0, bh1);
                mma16816(acc[2 * np + 1], ah0, ah1, ah2, ah3, bh2, bh3);
                mma16816(acc[2 * np + 1], ah0, ah1, ah2, ah3, bl2, bl3);
                mma16816(acc[2 * np + 1], al0, al1, al2, al3, bh2, bh3);
            }
        }
        __syncthreads();   // all LDSM done -> A region reusable as OUT

        // ---- write msg tile to smem: relu(acc + bias + P1[src] + P3[dst])
        {
            int s0 = sSrc[er0], d0 = sDst[er0];
            int s1 = sSrc[er0 + 8], d1 = sDst[er0 + 8];
            const float* p1a = g_P1 + (size_t)s0 * HID;
            const float* p3a = g_P3 + (size_t)d0 * HID;
            const float* p1b = g_P1 + (size_t)s1 * HID;
            const float* p3b = g_P3 + (size_t)d1 * HID;
#pragma unroll
            for (int nt = 0; nt < 16; nt++) {
                int col = nt * 8 + cb;
                float2 q1 = *(const float2*)(p1a + col);
                float2 q3 = *(const float2*)(p3a + col);
                float2 o0;
                o0.x = fmaxf(acc[nt][0] + sBm[col]     + q1.x + q3.x, 0.f);
                o0.y = fmaxf(acc[nt][1] + sBm[col + 1] + q1.y + q3.y, 0.f);
                *(float2*)&OUT[er0 * 132 + col] = o0;
                float2 r1 = *(const float2*)(p1b + col);
                float2 r3 = *(const float2*)(p3b + col);
                float2 o1;
                o1.x = fmaxf(acc[nt][2] + sBm[col]     + r1.x + r3.x, 0.f);
                o1.y = fmaxf(acc[nt][3] + sBm[col + 1] + r1.y + r3.y, 0.f);
                *(float2*)&OUT[(er0 + 8) * 132 + col] = o1;
            }
        }
        __syncthreads();

        // ---- segmented reduction along rows (dst-sorted): one RED per segment
        {
            int col = tid & 127;
            int rbase = (tid >> 7) * 64;
            float s = 0.f;
            int cur = sDst[rbase];
#pragma unroll 4
            for (int r2 = 0; r2 < 64; r2++) {
                int rr = rbase + r2;
                int dn = sDst[rr];
                if (dn != cur) {
                    if (s != 0.f) atomicAdd(&g_agg[(size_t)cur * HID + col], s);
                    cur = dn; s = 0.f;
                }
                s += OUT[rr * 132 + col];
            }
            if (s != 0.f) atomicAdd(&g_agg[(size_t)cur * HID + col], s);
        }
        __syncthreads();
    }
}

// ---------------------------------------------------------------- update GEMM
__global__ void __launch_bounds__(256, 2)
upd_gemm(int layer, const float* __restrict__ W, const float* __restrict__ bias)
{
    const float* __restrict__ hn   = layer ? g_hn1 : g_hn0;
    float*       __restrict__ hout = layer ? g_hn0 : g_hn1;
    __shared__ __align__(16) float As[16][132];
    __shared__ __align__(16) float Bs[16][132];
    __shared__ float sB[128];

    const int tid   = threadIdx.x;
    const int nBase = blockIdx.x * 128;
    if (tid < 128) sB[tid] = bias[tid];
    __syncthreads();

    const int arow = tid >> 1;
    const int akl  = (tid & 1) * 8;
    const int tx   = tid & 15, ty = tid >> 4;
    const int nrow = min(nBase + arow, NN - 1);

    float acc[2][4][2][4];
#pragma unroll
    for (int a = 0; a < 2; a++)
#pragma unroll
        for (int i = 0; i < 4; i++)
#pragma unroll
            for (int b2 = 0; b2 < 2; b2++)
#pragma unroll
                for (int j = 0; j < 4; j++) acc[a][i][b2][j] = 0.f;

    float4 apf0, apf1, bpf0, bpf1;
    {
        const float* base = hn + (size_t)nrow * HID;
        apf0 = *(const float4*)(base + akl);
        apf1 = *(const float4*)(base + akl + 4);
        const float4* wb = (const float4*)W;
        bpf0 = wb[tid]; bpf1 = wb[tid + 256];
    }

    for (int t = 0; t < 16; t++) {
        As[akl + 0][arow] = apf0.x; As[akl + 1][arow] = apf0.y;
        As[akl + 2][arow] = apf0.z; As[akl + 3][arow] = apf0.w;
        As[akl + 4][arow] = apf1.x; As[akl + 5][arow] = apf1.y;
        As[akl + 6][arow] = apf1.z; As[akl + 7][arow] = apf1.w;
        {
            int k0 = tid >> 5, c0 = (tid & 31) * 4;
            *(float4*)&Bs[k0][c0]     = bpf0;
            *(float4*)&Bs[k0 + 8][c0] = bpf1;
        }
        __syncthreads();
        if (t < 15) {
            int kb = (t + 1) * 16;
            int seg = kb >> 7, off = kb & 127;
            const float* base = (seg == 0) ? hn + (size_t)nrow * HID + off
                                           : g_agg + (size_t)nrow * HID + off;
            apf0 = *(const float4*)(base + akl);
            apf1 = *(const float4*)(base + akl + 4);
            const float4* wb = (const float4*)(W + (size_t)kb * HID);
            bpf0 = wb[tid]; bpf1 = wb[tid + 256];
        }
#pragma unroll
        for (int k = 0; k < 16; k++) {
            float4 a0 = *(const float4*)&As[k][ty * 4];
            float4 a1 = *(const float4*)&As[k][64 + ty * 4];
            float4 b0 = *(const float4*)&Bs[k][tx * 4];
            float4 b1 = *(const float4*)&Bs[k][64 + tx * 4];
            float ar[8] = {a0.x, a0.y, a0.z, a0.w, a1.x, a1.y, a1.z, a1.w};
            float br[8] = {b0.x, b0.y, b0.z, b0.w, b1.x, b1.y, b1.z, b1.w};
#pragma unroll
            for (int a = 0; a < 2; a++)
#pragma unroll
                for (int i = 0; i < 4; i++)
#pragma unroll
                    for (int b2 = 0; b2 < 2; b2++)
#pragma unroll
                        for (int j = 0; j < 4; j++)
                            acc[a][i][b2][j] = fmaf(ar[a * 4 + i], br[b2 * 4 + j], acc[a][i][b2][j]);
        }
        __syncthreads();
    }

#pragma unroll
    for (int a = 0; a < 2; a++)
#pragma unroll
        for (int i = 0; i < 4; i++) {
            int r = nBase + a * 64 + ty * 4 + i;
            if (r < NN) {
#pragma unroll
                for (int b2 = 0; b2 < 2; b2++)
#pragma unroll
                    for (int j = 0; j < 4; j++) {
                        int c = b2 * 64 + tx * 4 + j;
                        hout[(size_t)r * HID + c] = fmaxf(acc[a][i][b2][j] + sB[c], 0.f);
                    }
            }
        }
}

// --------------------------------------------- fused demand readout
__global__ void __launch_bounds__(256)
dem_v2(const int* __restrict__ pairs, const float* __restrict__ dfeat,
       const float* __restrict__ Wd, const float* __restrict__ br1,
       const float* __restrict__ w2, const float* __restrict__ b2,
       float* __restrict__ out)
{
    __shared__ __align__(16) float Wds[8][132];
    __shared__ float w2s[128], bs[128];
    int tid = threadIdx.x;
    if (tid < 128) { w2s[tid] = w2[tid]; bs[tid] = br1[tid]; }
    {
        int row = tid >> 5, c = (tid & 31) * 4;
        *(float4*)&Wds[row][c] = ((const float4*)Wd)[tid];
    }
    __syncthreads();

    int w = tid >> 5, lane = tid & 31;
    int d = blockIdx.x * 8 + w;
    int ds = pairs[2 * d], dd = pairs[2 * d + 1];
    int c0 = lane * 4;

    float4 q1 = *(const float4*)(g_P1 + (size_t)ds * HID + c0);
    float4 q2 = *(const float4*)(g_P3 + (size_t)dd * HID + c0);
    float s0 = bs[c0 + 0] + q1.x + q2.x;
    float s1 = bs[c0 + 1] + q1.y + q2.y;
    float s2 = bs[c0 + 2] + q1.z + q2.z;
    float s3 = bs[c0 + 3] + q1.w + q2.w;
#pragma unroll
    for (int q = 0; q < 8; q++) {
        float e = dfeat[(size_t)d * 8 + q];
        float4 wv = *(const float4*)&Wds[q][c0];
        s0 = fmaf(e, wv.x, s0); s1 = fmaf(e, wv.y, s1);
        s2 = fmaf(e, wv.z, s2); s3 = fmaf(e, wv.w, s3);
    }
    float p = fmaxf(s0, 0.f) * w2s[c0 + 0] + fmaxf(s1, 0.f) * w2s[c0 + 1]
            + fmaxf(s2, 0.f) * w2s[c0 + 2] + fmaxf(s3, 0.f) * w2s[c0 + 3];
#pragma unroll
    for (int o = 16; o > 0; o >>= 1) p += __shfl_xor_sync(0xffffffffu, p, o);
    if (lane == 0) out[d] = 1.f / (1.f + expf(-(p + b2[0])));
}

// ---------------------------------------------------------------- launch
extern "C" void kernel_launch(void* const* d_in, const int* in_sizes, int n_in,
                              void* d_out, int out_size)
{
    const float* node_feats = (const float*)d_in[0];
    const float* edge_feats = (const float*)d_in[1];
    const float* dem_feats  = (const float*)d_in[2];
    const int*   eidx       = (const int*)d_in[3];
    const int*   pairs      = (const int*)d_in[4];
    const float* W_node = (const float*)d_in[5];
    const float* b_node = (const float*)d_in[6];
    const float* W_edge = (const float*)d_in[7];
    const float* b_edge = (const float*)d_in[8];
    const float* W_msg0 = (const float*)d_in[9];
    const float* b_msg0 = (const float*)d_in[10];
    const float* W_upd0 = (const float*)d_in[11];
    const float* b_upd0 = (const float*)d_in[12];
    const float* W_msg1 = (const float*)d_in[13];
    const float* b_msg1 = (const float*)d_in[14];
    const float* W_upd1 = (const float*)d_in[15];
    const float* b_upd1 = (const float*)d_in[16];
    const float* W_r1   = (const float*)d_in[17];
    const float* b_r1   = (const float*)d_in[18];
    const float* W_r2   = (const float*)d_in[19];
    const float* b_r2   = (const float*)d_in[20];
    float* out = (float*)d_out;

    const int nTiles = (NN + 127) / 128;

    cudaFuncSetAttribute(msg_v5, cudaFuncAttributeMaxDynamicSharedMemorySize, SM_TOTAL);

    // ---- edge sort by dst (one-time, reused by both layers)
    zcnt<<<(NN + 256) / 256, 256>>>();
    hist<<<NE / 256, 256>>>(eidx);
    scan20k<<<1, 1024>>>();
    scatter<<<NE / 256, 256>>>(eidx);

    node_embed<<<NN / 16, 128>>>(node_feats, W_node, b_node);
    prep_w<<<2, 256>>>(W_msg0 + 128 * HID, W_msg1 + 128 * HID);

    // ---- layer 0
    gemm128<<<nTiles, 256>>>(0, 0, W_msg0);
    gemm128<<<nTiles, 256>>>(0, 1, W_msg0 + 256 * HID);
    zero_agg<<<(NN * HID / 4 + 255) / 256, 256>>>();
    msg_v5<<<152, 256, SM_TOTAL>>>(0, edge_feats, W_edge, b_edge, b_msg0);
    upd_gemm<<<nTiles, 256>>>(0, W_upd0, b_upd0);

    // ---- layer 1
    gemm128<<<nTiles, 256>>>(1, 0, W_msg1);
    gemm128<<<nTiles, 256>>>(1, 1, W_msg1 + 256 * HID);
    zero_agg<<<(NN * HID / 4 + 255) / 256, 256>>>();
    msg_v5<<<152, 256, SM_TOTAL>>>(1, edge_feats, W_edge, b_edge, b_msg1);
    upd_gemm<<<nTiles, 256>>>(1, W_upd1, b_upd1);

    // ---- readout
    gemm128<<<nTiles, 256>>>(0, 0, W_r1);
    gemm128<<<nTiles, 256>>>(0, 1, W_r1 + 128 * HID);
    dem_v2<<<ND / 8, 256>>>(pairs, dem_feats, W_r1 + 256 * HID, b_r1, W_r2, b_r2, out);
}

// round 6
// speedup vs baseline: 1.3652x; 1.2204x over previous
#include <cuda_runtime.h>
#include <cuda_bf16.h>
#include <math.h>
#include <stdint.h>

#define HID 128
#define NN 20000
#define NE 640000
#define ND 100000

// scratch (device globals: allocation-free contract)
__device__ float g_hn0[(size_t)NN * HID];
__device__ float g_hn1[(size_t)NN * HID];
__device__ float g_agg[(size_t)NN * HID];
__device__ float g_P1 [(size_t)NN * HID];
__device__ float g_P3 [(size_t)NN * HID];
__device__ __align__(16) __nv_bfloat16 g_Bh[2][128 * 128];
__device__ __align__(16) __nv_bfloat16 g_Bl[2][128 * 128];
// edge sort-by-dst
__device__ int g_cnt[NN + 1];
__device__ int g_srcp[NE];
__device__ int g_dstp[NE];
__device__ int g_eper[NE];

// ======================= warp MMA helpers =======================
__device__ __forceinline__ uint32_t smem_u32(const void* p) {
    uint32_t a;
    asm("{ .reg .u64 t; cvta.to.shared.u64 t, %1; cvt.u32.u64 %0, t; }" : "=r"(a) : "l"(p));
    return a;
}
__device__ __forceinline__ void ldsm4(uint32_t& r0, uint32_t& r1, uint32_t& r2, uint32_t& r3,
                                      uint32_t addr) {
    asm volatile("ldmatrix.sync.aligned.m8n8.x4.shared.b16 {%0,%1,%2,%3}, [%4];"
                 : "=r"(r0), "=r"(r1), "=r"(r2), "=r"(r3) : "r"(addr));
}
__device__ __forceinline__ void mma16816(float* c, uint32_t a0, uint32_t a1, uint32_t a2,
                                         uint32_t a3, uint32_t b0, uint32_t b1) {
    asm volatile("mma.sync.aligned.m16n8k16.row.col.f32.bf16.bf16.f32 "
                 "{%0,%1,%2,%3}, {%4,%5,%6,%7}, {%8,%9}, {%0,%1,%2,%3};"
                 : "+f"(c[0]), "+f"(c[1]), "+f"(c[2]), "+f"(c[3])
                 : "r"(a0), "r"(a1), "r"(a2), "r"(a3), "r"(b0), "r"(b1));
}
// split two fp32 into packed bf16 hi pair + lo pair
__device__ __forceinline__ void split2(float v0, float v1, uint32_t& hi, uint32_t& lo) {
    __nv_bfloat16 h0 = __float2bfloat16(v0);
    __nv_bfloat16 h1 = __float2bfloat16(v1);
    float l0 = v0 - __bfloat162float(h0);
    float l1 = v1 - __bfloat162float(h1);
    __nv_bfloat16 m0 = __float2bfloat16(l0);
    __nv_bfloat16 m1 = __float2bfloat16(l1);
    hi = (uint32_t)__bfloat16_as_ushort(h0) | ((uint32_t)__bfloat16_as_ushort(h1) << 16);
    lo = (uint32_t)__bfloat16_as_ushort(m0) | ((uint32_t)__bfloat16_as_ushort(m1) << 16);
}

// ---------------------------------------------------------------- sort by dst
__global__ void zcnt()
{
    int i = blockIdx.x * 256 + threadIdx.x;
    if (i <= NN) g_cnt[i] = 0;
}
__global__ void hist(const int* __restrict__ eidx)
{
    int e = blockIdx.x * 256 + threadIdx.x;
    atomicAdd(&g_cnt[eidx[NE + e]], 1);
}
__global__ void scan20k()
{
    __shared__ int part[1024];
    __shared__ int wsum[32];
    const int tid = threadIdx.x;
    const int CH = 20;
    int base = tid * CH;
    int loc[CH];
    int s = 0;
#pragma unroll
    for (int i = 0; i < CH; i++) {
        int v = (base + i <= NN) ? g_cnt[base + i] : 0;
        loc[i] = s; s += v;
    }
    part[tid] = s;
    __syncthreads();
    int lane = tid & 31, w = tid >> 5;
    int v = part[tid];
#pragma unroll
    for (int o = 1; o < 32; o <<= 1) { int t = __shfl_up_sync(~0u, v, o); if (lane >= o) v += t; }
    if (lane == 31) wsum[w] = v;
    __syncthreads();
    if (w == 0) {
        int x = wsum[lane];
#pragma unroll
        for (int o = 1; o < 32; o <<= 1) { int t = __shfl_up_sync(~0u, x, o); if (lane >= o) x += t; }
        wsum[lane] = x;
    }
    __syncthreads();
    int excl = v - part[tid] + (w ? wsum[w - 1] : 0);
#pragma unroll
    for (int i = 0; i < CH; i++)
        if (base + i <= NN) g_cnt[base + i] = excl + loc[i];
}
__global__ void scatter(const int* __restrict__ eidx)
{
    int e = blockIdx.x * 256 + threadIdx.x;
    int s = eidx[e], d = eidx[NE + e];
    int p = atomicAdd(&g_cnt[d], 1);
    g_srcp[p] = s; g_dstp[p] = d; g_eper[p] = e;
}

// ---------------------------------------------------------------- node embed
__global__ void node_embed(const float* __restrict__ x, const float* __restrict__ W,
                           const float* __restrict__ b)
{
    __shared__ float Ws[32 * HID];
    __shared__ float xs[16][33];
    int tid = threadIdx.x; // 128
    for (int i = tid; i < 32 * HID; i += 128) Ws[i] = W[i];
    int row0 = blockIdx.x * 16;
    for (int i = tid; i < 16 * 32; i += 128) xs[i >> 5][i & 31] = x[(size_t)row0 * 32 + i];
    float bb = b[tid];
    __syncthreads();
#pragma unroll 4
    for (int r = 0; r < 16; r++) {
        float acc = bb;
#pragma unroll
        for (int k = 0; k < 32; k++) acc = fmaf(xs[r][k], Ws[k * HID + tid], acc);
        g_hn0[(size_t)(row0 + r) * HID + tid] = fmaxf(acc, 0.f);
    }
}

// ---------------------------------------------------------------- zero agg
__global__ void zero_agg()
{
    size_t i = (size_t)blockIdx.x * blockDim.x + threadIdx.x;
    if (i < (size_t)NN * HID / 4) ((float4*)g_agg)[i] = make_float4(0.f, 0.f, 0.f, 0.f);
}

// ---------------------------------------- weight prep: split hi/lo, [n][k]
__global__ void prep_w(const float* __restrict__ W0, const float* __restrict__ W1)
{
    const float* W = blockIdx.x ? W1 : W0;
    __nv_bfloat16* bh = g_Bh[blockIdx.x];
    __nv_bfloat16* bl = g_Bl[blockIdx.x];
    for (int idx = threadIdx.x; idx < 128 * 128; idx += blockDim.x) {
        int n = idx >> 7, k = idx & 127;
        float w = W[k * 128 + n];
        __nv_bfloat16 h = __float2bfloat16(w);
        float lo = w - __bfloat162float(h);
        bh[idx] = h;
        bl[idx] = __float2bfloat16(lo);
    }
}

// ------------------------------------- node-level dual GEMM (P1 & P3, no act)
__global__ void __launch_bounds__(256)
gemm128x2(int asel, const float* __restrict__ W1, const float* __restrict__ W3)
{
    const float* __restrict__ A = asel ? g_hn1 : g_hn0;
    __shared__ __align__(16) float As[16][132];
    __shared__ __align__(16) float B1s[16][132];
    __shared__ __align__(16) float B3s[16][132];

    const int tid   = threadIdx.x;
    const int nBase = blockIdx.x * 128;
    const int arow  = tid >> 1;
    const int akl   = (tid & 1) * 8;
    const int tx    = tid & 15, ty = tid >> 4;
    const int nrow  = min(nBase + arow, NN - 1);

    float acc1[2][4][2][4], acc3[2][4][2][4];
#pragma unroll
    for (int a = 0; a < 2; a++)
#pragma unroll
        for (int i = 0; i < 4; i++)
#pragma unroll
            for (int b2 = 0; b2 < 2; b2++)
#pragma unroll
                for (int j = 0; j < 4; j++) { acc1[a][i][b2][j] = 0.f; acc3[a][i][b2][j] = 0.f; }

    float4 apf0, apf1, b1p0, b1p1, b3p0, b3p1;
    {
        const float* base = A + (size_t)nrow * HID;
        apf0 = *(const float4*)(base + akl);
        apf1 = *(const float4*)(base + akl + 4);
        b1p0 = ((const float4*)W1)[tid]; b1p1 = ((const float4*)W1)[tid + 256];
        b3p0 = ((const float4*)W3)[tid]; b3p1 = ((const float4*)W3)[tid + 256];
    }

    for (int t = 0; t < 8; t++) {
        As[akl + 0][arow] = apf0.x; As[akl + 1][arow] = apf0.y;
        As[akl + 2][arow] = apf0.z; As[akl + 3][arow] = apf0.w;
        As[akl + 4][arow] = apf1.x; As[akl + 5][arow] = apf1.y;
        As[akl + 6][arow] = apf1.z; As[akl + 7][arow] = apf1.w;
        {
            int k0 = tid >> 5, c0 = (tid & 31) * 4;
            *(float4*)&B1s[k0][c0]     = b1p0;
            *(float4*)&B1s[k0 + 8][c0] = b1p1;
            *(float4*)&B3s[k0][c0]     = b3p0;
            *(float4*)&B3s[k0 + 8][c0] = b3p1;
        }
        __syncthreads();
        if (t < 7) {
            int kb = (t + 1) * 16;
            const float* base = A + (size_t)nrow * HID + kb;
            apf0 = *(const float4*)(base + akl);
            apf1 = *(const float4*)(base + akl + 4);
            b1p0 = ((const float4*)(W1 + (size_t)kb * HID))[tid];
            b1p1 = ((const float4*)(W1 + (size_t)kb * HID))[tid + 256];
            b3p0 = ((const float4*)(W3 + (size_t)kb * HID))[tid];
            b3p1 = ((const float4*)(W3 + (size_t)kb * HID))[tid + 256];
        }
#pragma unroll
        for (int k = 0; k < 16; k++) {
            float4 a0 = *(const float4*)&As[k][ty * 4];
            float4 a1 = *(const float4*)&As[k][64 + ty * 4];
            float ar[8] = {a0.x, a0.y, a0.z, a0.w, a1.x, a1.y, a1.z, a1.w};
            float4 p0 = *(const float4*)&B1s[k][tx * 4];
            float4 p1 = *(const float4*)&B1s[k][64 + tx * 4];
            float4 q0 = *(const float4*)&B3s[k][tx * 4];
            float4 q1 = *(const float4*)&B3s[k][64 + tx * 4];
            float br1[8] = {p0.x, p0.y, p0.z, p0.w, p1.x, p1.y, p1.z, p1.w};
            float br3[8] = {q0.x, q0.y, q0.z, q0.w, q1.x, q1.y, q1.z, q1.w};
#pragma unroll
            for (int a = 0; a < 2; a++)
#pragma unroll
                for (int i = 0; i < 4; i++)
#pragma unroll
                    for (int b2 = 0; b2 < 2; b2++)
#pragma unroll
                        for (int j = 0; j < 4; j++) {
                            acc1[a][i][b2][j] = fmaf(ar[a * 4 + i], br1[b2 * 4 + j], acc1[a][i][b2][j]);
                            acc3[a][i][b2][j] = fmaf(ar[a * 4 + i], br3[b2 * 4 + j], acc3[a][i][b2][j]);
                        }
        }
        __syncthreads();
    }

#pragma unroll
    for (int a = 0; a < 2; a++)
#pragma unroll
        for (int i = 0; i < 4; i++) {
            int r = nBase + a * 64 + ty * 4 + i;
            if (r < NN) {
#pragma unroll
                for (int b2 = 0; b2 < 2; b2++) {
                    int c = b2 * 64 + tx * 4;
                    *(float4*)&g_P1[(size_t)r * HID + c] =
                        make_float4(acc1[a][i][b2][0], acc1[a][i][b2][1],
                                    acc1[a][i][b2][2], acc1[a][i][b2][3]);
                    *(float4*)&g_P3[(size_t)r * HID + c] =
                        make_float4(acc3[a][i][b2][0], acc3[a][i][b2][1],
                                    acc3[a][i][b2][2], acc3[a][i][b2][3]);
                }
            }
        }
}

// ====================== persistent MMA-chain edge kernel (dst-sorted) ========
#define SM_BM   0
#define SM_BE   512
#define SM_SRC  1024
#define SM_DST  1536
#define SM_EFH  2048            // bf16 [128][24]  (ef hi, 48B stride)
#define SM_EFL  8192
#define SM_WBH  14336           // bf16 [128][24]  (We^T hi: [n][k=16])
#define SM_WBL  20480
#define SM_BH   26624           // bf16 [128][136] main B hi
#define SM_BL   61440
#define SM_OUT  96256           // fp32 [128][132]
#define SM_TOTAL 163840
#define TSTRIDE 272
#define EFST    48

__global__ void __launch_bounds__(256)
msg_v6(int layer, const float* __restrict__ ef,
       const float* __restrict__ We, const float* __restrict__ be,
       const float* __restrict__ bm)
{
    extern __shared__ __align__(16) char smem[];
    const uint32_t sb = smem_u32(smem);
    const int tid = threadIdx.x;
    const int wid = tid >> 5, lane = tid & 31;

    float* sBm = (float*)(smem + SM_BM);
    float* beS = (float*)(smem + SM_BE);
    int*   sSrc = (int*)(smem + SM_SRC);
    int*   sDst = (int*)(smem + SM_DST);
    float* OUT = (float*)(smem + SM_OUT);   // [128][132]

    // ---- one-time setup
    if (tid < 128) { sBm[tid] = bm[tid]; beS[tid] = be[tid]; }
    if (tid < 128) {   // stage We^T hi/lo: row n, 16 k values (column n of We)
        int n = tid;
        uint32_t h8[8], l8[8];
#pragma unroll
        for (int p = 0; p < 8; p++) {
            float w0 = We[(2 * p) * 128 + n];
            float w1 = We[(2 * p + 1) * 128 + n];
            split2(w0, w1, h8[p], l8[p]);
        }
        *(uint4*)(smem + SM_WBH + n * EFST)      = make_uint4(h8[0], h8[1], h8[2], h8[3]);
        *(uint4*)(smem + SM_WBH + n * EFST + 16) = make_uint4(h8[4], h8[5], h8[6], h8[7]);
        *(uint4*)(smem + SM_WBL + n * EFST)      = make_uint4(l8[0], l8[1], l8[2], l8[3]);
        *(uint4*)(smem + SM_WBL + n * EFST + 16) = make_uint4(l8[4], l8[5], l8[6], l8[7]);
    }
    {   // stage main B hi/lo into padded smem [n][136]
        const uint2* bh = (const uint2*)g_Bh[layer];
        const uint2* bl = (const uint2*)g_Bl[layer];
#pragma unroll
        for (int u = 0; u < 16; u++) {
            int g = tid + u * 256;
            int n = g >> 5, kq = g & 31;
            *(uint2*)(smem + SM_BH + n * TSTRIDE + kq * 8) = bh[g];
            *(uint2*)(smem + SM_BL + n * TSTRIDE + kq * 8) = bl[g];
        }
    }

    const int wm = wid * 16;
    // ldmatrix offsets
    const uint32_t aEfOff = (uint32_t)((wm + (lane & 7) + ((lane >> 3) & 1) * 8) * EFST
                                       + (lane >> 4) * 16);
    const uint32_t bEfOff = (uint32_t)(((lane & 7) + (lane >> 4) * 8) * EFST
                                       + ((lane >> 3) & 1) * 16);
    const uint32_t bMnOff = (uint32_t)(((lane & 7) + (lane >> 4) * 8) * TSTRIDE
                                       + (((lane >> 3) & 1) * 8) * 2);
    const uint32_t efhA = sb + SM_EFH + aEfOff;
    const uint32_t eflA = sb + SM_EFL + aEfOff;
    const uint32_t wbhA = sb + SM_WBH + bEfOff;
    const uint32_t wblA = sb + SM_WBL + bEfOff;
    const uint32_t bHiA = sb + SM_BH + bMnOff;
    const uint32_t bLoA = sb + SM_BL + bMnOff;

    const int er0 = wm + (lane >> 2);
    const int cb  = (lane & 3) * 2;

    __syncthreads();

    for (int t = blockIdx.x; t < NE / 128; t += gridDim.x) {
        const int eBase = t * 128;
        // ---- stage indices (sorted by dst) and permuted ef rows (bf16 hi/lo)
        if (tid < 128) sSrc[tid] = g_srcp[eBase + tid];
        else           sDst[tid - 128] = g_dstp[eBase + tid - 128];
        {
            int r = tid >> 1, u = tid & 1;
            int eid = g_eper[eBase + r];
            const float4* eg = (const float4*)(ef + (size_t)eid * 16) + u * 2;
            float4 v0 = eg[0], v1 = eg[1];
            uint32_t h4[4], l4[4];
            split2(v0.x, v0.y, h4[0], l4[0]);
            split2(v0.z, v0.w, h4[1], l4[1]);
            split2(v1.x, v1.y, h4[2], l4[2]);
            split2(v1.z, v1.w, h4[3], l4[3]);
            uint32_t off = (uint32_t)(r * EFST + u * 16);
            *(uint4*)(smem + SM_EFH + off) = make_uint4(h4[0], h4[1], h4[2], h4[3]);
            *(uint4*)(smem + SM_EFL + off) = make_uint4(l4[0], l4[1], l4[2], l4[3]);
        }
        __syncthreads();

        // ---- he GEMM (K=16, 3-product split) -> acc2 in registers
        float acc2[16][4];
#pragma unroll
        for (int n = 0; n < 16; n++)
#pragma unroll
            for (int j = 0; j < 4; j++) acc2[n][j] = 0.f;
        {
            uint32_t eh0, eh1, eh2, eh3, el0, el1, el2, el3;
            ldsm4(eh0, eh1, eh2, eh3, efhA);
            ldsm4(el0, el1, el2, el3, eflA);
#pragma unroll
            for (int g = 0; g < 8; g++) {
                uint32_t wh0, wh1, wh2, wh3, wl0, wl1, wl2, wl3;
                ldsm4(wh0, wh1, wh2, wh3, wbhA + g * (16 * EFST));
                ldsm4(wl0, wl1, wl2, wl3, wblA + g * (16 * EFST));
                mma16816(acc2[2 * g],     eh0, eh1, eh2, eh3, wh0, wh1);
                mma16816(acc2[2 * g],     eh0, eh1, eh2, eh3, wl0, wl1);
                mma16816(acc2[2 * g],     el0, el1, el2, el3, wh0, wh1);
                mma16816(acc2[2 * g + 1], eh0, eh1, eh2, eh3, wh2, wh3);
                mma16816(acc2[2 * g + 1], eh0, eh1, eh2, eh3, wl2, wl3);
                mma16816(acc2[2 * g + 1], el0, el1, el2, el3, wh2, wh3);
            }
        }

        // ---- bias + relu + hi/lo split -> main-GEMM A fragments (registers)
        uint32_t aH[8][4], aL[8][4];
#pragma unroll
        for (int nt = 0; nt < 16; nt++) {
            int col = nt * 8 + cb;
            float be0 = beS[col], be1 = beS[col + 1];
            float v0 = fmaxf(acc2[nt][0] + be0, 0.f);
            float v1 = fmaxf(acc2[nt][1] + be1, 0.f);
            float v2 = fmaxf(acc2[nt][2] + be0, 0.f);
            float v3 = fmaxf(acc2[nt][3] + be1, 0.f);
            int ks = nt >> 1, j0 = (nt & 1) * 2;
            split2(v0, v1, aH[ks][j0],     aL[ks][j0]);
            split2(v2, v3, aH[ks][j0 + 1], aL[ks][j0 + 1]);
        }

        // ---- main GEMM: D = Ahi*Bhi + Ahi*Blo + Alo*Bhi
        float acc[16][4];
#pragma unroll
        for (int n = 0; n < 16; n++)
#pragma unroll
            for (int j = 0; j < 4; j++) acc[n][j] = 0.f;
#pragma unroll
        for (int ks = 0; ks < 8; ks++) {
#pragma unroll
            for (int np = 0; np < 8; np++) {
                uint32_t bh0, bh1, bh2, bh3, bl0, bl1, bl2, bl3;
                ldsm4(bh0, bh1, bh2, bh3, bHiA + np * (16 * TSTRIDE) + ks * 32);
                ldsm4(bl0, bl1, bl2, bl3, bLoA + np * (16 * TSTRIDE) + ks * 32);
                mma16816(acc[2 * np],     aH[ks][0], aH[ks][1], aH[ks][2], aH[ks][3], bh0, bh1);
                mma16816(acc[2 * np],     aH[ks][0], aH[ks][1], aH[ks][2], aH[ks][3], bl0, bl1);
                mma16816(acc[2 * np],     aL[ks][0], aL[ks][1], aL[ks][2], aL[ks][3], bh0, bh1);
                mma16816(acc[2 * np + 1], aH[ks][0], aH[ks][1], aH[ks][2], aH[ks][3], bh2, bh3);
                mma16816(acc[2 * np + 1], aH[ks][0], aH[ks][1], aH[ks][2], aH[ks][3], bl2, bl3);
                mma16816(acc[2 * np + 1], aL[ks][0], aL[ks][1], aL[ks][2], aL[ks][3], bh2, bh3);
            }
        }

        // ---- write msg tile to smem: relu(acc + bias + P1[src] + P3[dst])
        {
            int s0 = sSrc[er0], d0 = sDst[er0];
            int s1 = sSrc[er0 + 8], d1 = sDst[er0 + 8];
            const float* p1a = g_P1 + (size_t)s0 * HID;
            const float* p3a = g_P3 + (size_t)d0 * HID;
            const float* p1b = g_P1 + (size_t)s1 * HID;
            const float* p3b = g_P3 + (size_t)d1 * HID;
#pragma unroll
            for (int nt = 0; nt < 16; nt++) {
                int col = nt * 8 + cb;
                float2 q1 = *(const float2*)(p1a + col);
                float2 q3 = *(const float2*)(p3a + col);
                float2 o0;
                o0.x = fmaxf(acc[nt][0] + sBm[col]     + q1.x + q3.x, 0.f);
                o0.y = fmaxf(acc[nt][1] + sBm[col + 1] + q1.y + q3.y, 0.f);
                *(float2*)&OUT[er0 * 132 + col] = o0;
                float2 r1 = *(const float2*)(p1b + col);
                float2 r3 = *(const float2*)(p3b + col);
                float2 o1;
                o1.x = fmaxf(acc[nt][2] + sBm[col]     + r1.x + r3.x, 0.f);
                o1.y = fmaxf(acc[nt][3] + sBm[col + 1] + r1.y + r3.y, 0.f);
                *(float2*)&OUT[(er0 + 8) * 132 + col] = o1;
            }
        }
        __syncthreads();

        // ---- segmented reduction along rows (dst-sorted): one RED per segment
        {
            int col = tid & 127;
            int rbase = (tid >> 7) * 64;
            float s = 0.f;
            int cur = sDst[rbase];
#pragma unroll 4
            for (int r2 = 0; r2 < 64; r2++) {
                int rr = rbase + r2;
                int dn = sDst[rr];
                if (dn != cur) {
                    if (s != 0.f) atomicAdd(&g_agg[(size_t)cur * HID + col], s);
                    cur = dn; s = 0.f;
                }
                s += OUT[rr * 132 + col];
            }
            if (s != 0.f) atomicAdd(&g_agg[(size_t)cur * HID + col], s);
        }
        __syncthreads();
    }
}

// ---------------------------------------------------------------- update GEMM
__global__ void __launch_bounds__(256, 2)
upd_gemm(int layer, const float* __restrict__ W, const float* __restrict__ bias)
{
    const float* __restrict__ hn   = layer ? g_hn1 : g_hn0;
    float*       __restrict__ hout = layer ? g_hn0 : g_hn1;
    __shared__ __align__(16) float As[16][132];
    __shared__ __align__(16) float Bs[16][132];
    __shared__ float sB[128];

    const int tid   = threadIdx.x;
    const int nBase = blockIdx.x * 128;
    if (tid < 128) sB[tid] = bias[tid];
    __syncthreads();

    const int arow = tid >> 1;
    const int akl  = (tid & 1) * 8;
    const int tx   = tid & 15, ty = tid >> 4;
    const int nrow = min(nBase + arow, NN - 1);

    float acc[2][4][2][4];
#pragma unroll
    for (int a = 0; a < 2; a++)
#pragma unroll
        for (int i = 0; i < 4; i++)
#pragma unroll
            for (int b2 = 0; b2 < 2; b2++)
#pragma unroll
                for (int j = 0; j < 4; j++) acc[a][i][b2][j] = 0.f;

    float4 apf0, apf1, bpf0, bpf1;
    {
        const float* base = hn + (size_t)nrow * HID;
        apf0 = *(const float4*)(base + akl);
        apf1 = *(const float4*)(base + akl + 4);
        const float4* wb = (const float4*)W;
        bpf0 = wb[tid]; bpf1 = wb[tid + 256];
    }

    for (int t = 0; t < 16; t++) {
        As[akl + 0][arow] = apf0.x; As[akl + 1][arow] = apf0.y;
        As[akl + 2][arow] = apf0.z; As[akl + 3][arow] = apf0.w;
        As[akl + 4][arow] = apf1.x; As[akl + 5][arow] = apf1.y;
        As[akl + 6][arow] = apf1.z; As[akl + 7][arow] = apf1.w;
        {
            int k0 = tid >> 5, c0 = (tid & 31) * 4;
            *(float4*)&Bs[k0][c0]     = bpf0;
            *(float4*)&Bs[k0 + 8][c0] = bpf1;
        }
        __syncthreads();
        if (t < 15) {
            int kb = (t + 1) * 16;
            int seg = kb >> 7, off = kb & 127;
            const float* base = (seg == 0) ? hn + (size_t)nrow * HID + off
                                           : g_agg + (size_t)nrow * HID + off;
            apf0 = *(const float4*)(base + akl);
            apf1 = *(const float4*)(base + akl + 4);
            const float4* wb = (const float4*)(W + (size_t)kb * HID);
            bpf0 = wb[tid]; bpf1 = wb[tid + 256];
        }
#pragma unroll
        for (int k = 0; k < 16; k++) {
            float4 a0 = *(const float4*)&As[k][ty * 4];
            float4 a1 = *(const float4*)&As[k][64 + ty * 4];
            float4 b0 = *(const float4*)&Bs[k][tx * 4];
            float4 b1 = *(const float4*)&Bs[k][64 + tx * 4];
            float ar[8] = {a0.x, a0.y, a0.z, a0.w, a1.x, a1.y, a1.z, a1.w};
            float br[8] = {b0.x, b0.y, b0.z, b0.w, b1.x, b1.y, b1.z, b1.w};
#pragma unroll
            for (int a = 0; a < 2; a++)
#pragma unroll
                for (int i = 0; i < 4; i++)
#pragma unroll
                    for (int b2 = 0; b2 < 2; b2++)
#pragma unroll
                        for (int j = 0; j < 4; j++)
                            acc[a][i][b2][j] = fmaf(ar[a * 4 + i], br[b2 * 4 + j], acc[a][i][b2][j]);
        }
        __syncthreads();
    }

#pragma unroll
    for (int a = 0; a < 2; a++)
#pragma unroll
        for (int i = 0; i < 4; i++) {
            int r = nBase + a * 64 + ty * 4 + i;
            if (r < NN) {
#pragma unroll
                for (int b2 = 0; b2 < 2; b2++)
#pragma unroll
                    for (int j = 0; j < 4; j++) {
                        int c = b2 * 64 + tx * 4 + j;
                        hout[(size_t)r * HID + c] = fmaxf(acc[a][i][b2][j] + sB[c], 0.f);
                    }
            }
        }
}

// --------------------------------------------- fused demand readout
__global__ void __launch_bounds__(256)
dem_v2(const int* __restrict__ pairs, const float* __restrict__ dfeat,
       const float* __restrict__ Wd, const float* __restrict__ br1,
       const float* __restrict__ w2, const float* __restrict__ b2,
       float* __restrict__ out)
{
    __shared__ __align__(16) float Wds[8][132];
    __shared__ float w2s[128], bs[128];
    int tid = threadIdx.x;
    if (tid < 128) { w2s[tid] = w2[tid]; bs[tid] = br1[tid]; }
    {
        int row = tid >> 5, c = (tid & 31) * 4;
        *(float4*)&Wds[row][c] = ((const float4*)Wd)[tid];
    }
    __syncthreads();

    int w = tid >> 5, lane = tid & 31;
    int d = blockIdx.x * 8 + w;
    int ds = pairs[2 * d], dd = pairs[2 * d + 1];
    int c0 = lane * 4;

    float4 q1 = *(const float4*)(g_P1 + (size_t)ds * HID + c0);
    float4 q2 = *(const float4*)(g_P3 + (size_t)dd * HID + c0);
    float s0 = bs[c0 + 0] + q1.x + q2.x;
    float s1 = bs[c0 + 1] + q1.y + q2.y;
    float s2 = bs[c0 + 2] + q1.z + q2.z;
    float s3 = bs[c0 + 3] + q1.w + q2.w;
#pragma unroll
    for (int q = 0; q < 8; q++) {
        float e = dfeat[(size_t)d * 8 + q];
        float4 wv = *(const float4*)&Wds[q][c0];
        s0 = fmaf(e, wv.x, s0); s1 = fmaf(e, wv.y, s1);
        s2 = fmaf(e, wv.z, s2); s3 = fmaf(e, wv.w, s3);
    }
    float p = fmaxf(s0, 0.f) * w2s[c0 + 0] + fmaxf(s1, 0.f) * w2s[c0 + 1]
            + fmaxf(s2, 0.f) * w2s[c0 + 2] + fmaxf(s3, 0.f) * w2s[c0 + 3];
#pragma unroll
    for (int o = 16; o > 0; o >>= 1) p += __shfl_xor_sync(0xffffffffu, p, o);
    if (lane == 0) out[d] = 1.f / (1.f + expf(-(p + b2[0])));
}

// ---------------------------------------------------------------- launch
extern "C" void kernel_launch(void* const* d_in, const int* in_sizes, int n_in,
                              void* d_out, int out_size)
{
    const float* node_feats = (const float*)d_in[0];
    const float* edge_feats = (const float*)d_in[1];
    const float* dem_feats  = (const float*)d_in[2];
    const int*   eidx       = (const int*)d_in[3];
    const int*   pairs      = (const int*)d_in[4];
    const float* W_node = (const float*)d_in[5];
    const float* b_node = (const float*)d_in[6];
    const float* W_edge = (const float*)d_in[7];
    const float* b_edge = (const float*)d_in[8];
    const float* W_msg0 = (const float*)d_in[9];
    const float* b_msg0 = (const float*)d_in[10];
    const float* W_upd0 = (const float*)d_in[11];
    const float* b_upd0 = (const float*)d_in[12];
    const float* W_msg1 = (const float*)d_in[13];
    const float* b_msg1 = (const float*)d_in[14];
    const float* W_upd1 = (const float*)d_in[15];
    const float* b_upd1 = (const float*)d_in[16];
    const float* W_r1   = (const float*)d_in[17];
    const float* b_r1   = (const float*)d_in[18];
    const float* W_r2   = (const float*)d_in[19];
    const float* b_r2   = (const float*)d_in[20];
    float* out = (float*)d_out;

    const int nTiles = (NN + 127) / 128;

    cudaFuncSetAttribute(msg_v6, cudaFuncAttributeMaxDynamicSharedMemorySize, SM_TOTAL);

    // ---- edge sort by dst (one-time, reused by both layers)
    zcnt<<<(NN + 256) / 256, 256>>>();
    hist<<<NE / 256, 256>>>(eidx);
    scan20k<<<1, 1024>>>();
    scatter<<<NE / 256, 256>>>(eidx);

    node_embed<<<NN / 16, 128>>>(node_feats, W_node, b_node);
    prep_w<<<2, 256>>>(W_msg0 + 128 * HID, W_msg1 + 128 * HID);

    // ---- layer 0
    gemm128x2<<<nTiles, 256>>>(0, W_msg0, W_msg0 + 256 * HID);
    zero_agg<<<(NN * HID / 4 + 255) / 256, 256>>>();
    msg_v6<<<152, 256, SM_TOTAL>>>(0, edge_feats, W_edge, b_edge, b_msg0);
    upd_gemm<<<nTiles, 256>>>(0, W_upd0, b_upd0);

    // ---- layer 1
    gemm128x2<<<nTiles, 256>>>(1, W_msg1, W_msg1 + 256 * HID);
    zero_agg<<<(NN * HID / 4 + 255) / 256, 256>>>();
    msg_v6<<<152, 256, SM_TOTAL>>>(1, edge_feats, W_edge, b_edge, b_msg1);
    upd_gemm<<<nTiles, 256>>>(1, W_upd1, b_upd1);

    // ---- readout
    gemm128x2<<<nTiles, 256>>>(0, W_r1, W_r1 + 128 * HID);
    dem_v2<<<ND / 8, 256>>>(pairs, dem_feats, W_r1 + 256 * HID, b_r1, W_r2, b_r2, out);
}

// round 7
// speedup vs baseline: 1.6955x; 1.2420x over previous
#include <cuda_runtime.h>
#include <cuda_fp16.h>
#include <math.h>
#include <stdint.h>

#define HID 128
#define NN 20000
#define NE 640000
#define ND 100000

// scratch (device globals: allocation-free contract)
__device__ float g_hn0[(size_t)NN * HID];
__device__ float g_hn1[(size_t)NN * HID];
__device__ float g_agg[(size_t)NN * HID];
__device__ float g_P1 [(size_t)NN * HID];
__device__ float g_P3 [(size_t)NN * HID];
__device__ __align__(16) __half g_Wh[2][128 * 128];   // fp16 W_mid, [n][k]
// edge sort-by-dst
__device__ int g_cnt[NN + 1];
__device__ int g_srcp[NE];
__device__ int g_dstp[NE];
__device__ int g_eper[NE];

// ======================= warp MMA helpers =======================
__device__ __forceinline__ uint32_t smem_u32(const void* p) {
    uint32_t a;
    asm("{ .reg .u64 t; cvta.to.shared.u64 t, %1; cvt.u32.u64 %0, t; }" : "=r"(a) : "l"(p));
    return a;
}
__device__ __forceinline__ void ldsm4(uint32_t& r0, uint32_t& r1, uint32_t& r2, uint32_t& r3,
                                      uint32_t addr) {
    asm volatile("ldmatrix.sync.aligned.m8n8.x4.shared.b16 {%0,%1,%2,%3}, [%4];"
                 : "=r"(r0), "=r"(r1), "=r"(r2), "=r"(r3) : "r"(addr));
}
__device__ __forceinline__ void mma16816h(float* c, uint32_t a0, uint32_t a1, uint32_t a2,
                                          uint32_t a3, uint32_t b0, uint32_t b1) {
    asm volatile("mma.sync.aligned.m16n8k16.row.col.f32.f16.f16.f32 "
                 "{%0,%1,%2,%3}, {%4,%5,%6,%7}, {%8,%9}, {%0,%1,%2,%3};"
                 : "+f"(c[0]), "+f"(c[1]), "+f"(c[2]), "+f"(c[3])
                 : "r"(a0), "r"(a1), "r"(a2), "r"(a3), "r"(b0), "r"(b1));
}
// split two fp32 into packed fp16 hi pair + fp16 residual pair
__device__ __forceinline__ void split2h(float v0, float v1, uint32_t& hi, uint32_t& lo) {
    __half h0 = __float2half_rn(v0);
    __half h1 = __float2half_rn(v1);
    __half m0 = __float2half_rn(v0 - __half2float(h0));
    __half m1 = __float2half_rn(v1 - __half2float(h1));
    hi = (uint32_t)__half_as_ushort(h0) | ((uint32_t)__half_as_ushort(h1) << 16);
    lo = (uint32_t)__half_as_ushort(m0) | ((uint32_t)__half_as_ushort(m1) << 16);
}

// ---------------------------------------------------------------- sort by dst
__global__ void zcnt()
{
    int i = blockIdx.x * 256 + threadIdx.x;
    if (i <= NN) g_cnt[i] = 0;
}
__global__ void hist(const int* __restrict__ eidx)
{
    int e = blockIdx.x * 256 + threadIdx.x;
    atomicAdd(&g_cnt[eidx[NE + e]], 1);
}
__global__ void scan20k()
{
    __shared__ int part[1024];
    __shared__ int wsum[32];
    const int tid = threadIdx.x;
    const int CH = 20;
    int base = tid * CH;
    int loc[CH];
    int s = 0;
#pragma unroll
    for (int i = 0; i < CH; i++) {
        int v = (base + i <= NN) ? g_cnt[base + i] : 0;
        loc[i] = s; s += v;
    }
    part[tid] = s;
    __syncthreads();
    int lane = tid & 31, w = tid >> 5;
    int v = part[tid];
#pragma unroll
    for (int o = 1; o < 32; o <<= 1) { int t = __shfl_up_sync(~0u, v, o); if (lane >= o) v += t; }
    if (lane == 31) wsum[w] = v;
    __syncthreads();
    if (w == 0) {
        int x = wsum[lane];
#pragma unroll
        for (int o = 1; o < 32; o <<= 1) { int t = __shfl_up_sync(~0u, x, o); if (lane >= o) x += t; }
        wsum[lane] = x;
    }
    __syncthreads();
    int excl = v - part[tid] + (w ? wsum[w - 1] : 0);
#pragma unroll
    for (int i = 0; i < CH; i++)
        if (base + i <= NN) g_cnt[base + i] = excl + loc[i];
}
__global__ void scatter(const int* __restrict__ eidx)
{
    int e = blockIdx.x * 256 + threadIdx.x;
    int s = eidx[e], d = eidx[NE + e];
    int p = atomicAdd(&g_cnt[d], 1);
    g_srcp[p] = s; g_dstp[p] = d; g_eper[p] = e;
}

// ---------------------------------------------------------------- node embed
__global__ void node_embed(const float* __restrict__ x, const float* __restrict__ W,
                           const float* __restrict__ b)
{
    __shared__ float Ws[32 * HID];
    __shared__ float xs[16][33];
    int tid = threadIdx.x; // 128
    for (int i = tid; i < 32 * HID; i += 128) Ws[i] = W[i];
    int row0 = blockIdx.x * 16;
    for (int i = tid; i < 16 * 32; i += 128) xs[i >> 5][i & 31] = x[(size_t)row0 * 32 + i];
    float bb = b[tid];
    __syncthreads();
#pragma unroll 4
    for (int r = 0; r < 16; r++) {
        float acc = bb;
#pragma unroll
        for (int k = 0; k < 32; k++) acc = fmaf(xs[r][k], Ws[k * HID + tid], acc);
        g_hn0[(size_t)(row0 + r) * HID + tid] = fmaxf(acc, 0.f);
    }
}

// ---------------------------------------------------------------- zero agg
__global__ void zero_agg()
{
    size_t i = (size_t)blockIdx.x * blockDim.x + threadIdx.x;
    if (i < (size_t)NN * HID / 4) ((float4*)g_agg)[i] = make_float4(0.f, 0.f, 0.f, 0.f);
}

// ---------------------------------------- weight prep: fp16 image, [n][k]
__global__ void prep_w(const float* __restrict__ W0, const float* __restrict__ W1)
{
    const float* W = blockIdx.x ? W1 : W0;
    __half* wh = g_Wh[blockIdx.x];
    for (int idx = threadIdx.x; idx < 128 * 128; idx += blockDim.x) {
        int n = idx >> 7, k = idx & 127;
        wh[idx] = __float2half_rn(W[k * 128 + n]);
    }
}

// ------------------------------------- node-level dual GEMM (P1 & P3, no act)
__global__ void __launch_bounds__(256)
gemm128x2(int asel, const float* __restrict__ W1, const float* __restrict__ W3)
{
    const float* __restrict__ A = asel ? g_hn1 : g_hn0;
    __shared__ __align__(16) float As[16][132];
    __shared__ __align__(16) float B1s[16][132];
    __shared__ __align__(16) float B3s[16][132];

    const int tid   = threadIdx.x;
    const int nBase = blockIdx.x * 128;
    const int arow  = tid >> 1;
    const int akl   = (tid & 1) * 8;
    const int tx    = tid & 15, ty = tid >> 4;
    const int nrow  = min(nBase + arow, NN - 1);

    float acc1[2][4][2][4], acc3[2][4][2][4];
#pragma unroll
    for (int a = 0; a < 2; a++)
#pragma unroll
        for (int i = 0; i < 4; i++)
#pragma unroll
            for (int b2 = 0; b2 < 2; b2++)
#pragma unroll
                for (int j = 0; j < 4; j++) { acc1[a][i][b2][j] = 0.f; acc3[a][i][b2][j] = 0.f; }

    float4 apf0, apf1, b1p0, b1p1, b3p0, b3p1;
    {
        const float* base = A + (size_t)nrow * HID;
        apf0 = *(const float4*)(base + akl);
        apf1 = *(const float4*)(base + akl + 4);
        b1p0 = ((const float4*)W1)[tid]; b1p1 = ((const float4*)W1)[tid + 256];
        b3p0 = ((const float4*)W3)[tid]; b3p1 = ((const float4*)W3)[tid + 256];
    }

    for (int t = 0; t < 8; t++) {
        As[akl + 0][arow] = apf0.x; As[akl + 1][arow] = apf0.y;
        As[akl + 2][arow] = apf0.z; As[akl + 3][arow] = apf0.w;
        As[akl + 4][arow] = apf1.x; As[akl + 5][arow] = apf1.y;
        As[akl + 6][arow] = apf1.z; As[akl + 7][arow] = apf1.w;
        {
            int k0 = tid >> 5, c0 = (tid & 31) * 4;
            *(float4*)&B1s[k0][c0]     = b1p0;
            *(float4*)&B1s[k0 + 8][c0] = b1p1;
            *(float4*)&B3s[k0][c0]     = b3p0;
            *(float4*)&B3s[k0 + 8][c0] = b3p1;
        }
        __syncthreads();
        if (t < 7) {
            int kb = (t + 1) * 16;
            const float* base = A + (size_t)nrow * HID + kb;
            apf0 = *(const float4*)(base + akl);
            apf1 = *(const float4*)(base + akl + 4);
            b1p0 = ((const float4*)(W1 + (size_t)kb * HID))[tid];
            b1p1 = ((const float4*)(W1 + (size_t)kb * HID))[tid + 256];
            b3p0 = ((const float4*)(W3 + (size_t)kb * HID))[tid];
            b3p1 = ((const float4*)(W3 + (size_t)kb * HID))[tid + 256];
        }
#pragma unroll
        for (int k = 0; k < 16; k++) {
            float4 a0 = *(const float4*)&As[k][ty * 4];
            float4 a1 = *(const float4*)&As[k][64 + ty * 4];
            float ar[8] = {a0.x, a0.y, a0.z, a0.w, a1.x, a1.y, a1.z, a1.w};
            float4 p0 = *(const float4*)&B1s[k][tx * 4];
            float4 p1 = *(const float4*)&B1s[k][64 + tx * 4];
            float4 q0 = *(const float4*)&B3s[k][tx * 4];
            float4 q1 = *(const float4*)&B3s[k][64 + tx * 4];
            float br1[8] = {p0.x, p0.y, p0.z, p0.w, p1.x, p1.y, p1.z, p1.w};
            float br3[8] = {q0.x, q0.y, q0.z, q0.w, q1.x, q1.y, q1.z, q1.w};
#pragma unroll
            for (int a = 0; a < 2; a++)
#pragma unroll
                for (int i = 0; i < 4; i++)
#pragma unroll
                    for (int b2 = 0; b2 < 2; b2++)
#pragma unroll
                        for (int j = 0; j < 4; j++) {
                            acc1[a][i][b2][j] = fmaf(ar[a * 4 + i], br1[b2 * 4 + j], acc1[a][i][b2][j]);
                            acc3[a][i][b2][j] = fmaf(ar[a * 4 + i], br3[b2 * 4 + j], acc3[a][i][b2][j]);
                        }
        }
        __syncthreads();
    }

#pragma unroll
    for (int a = 0; a < 2; a++)
#pragma unroll
        for (int i = 0; i < 4; i++) {
            int r = nBase + a * 64 + ty * 4 + i;
            if (r < NN) {
#pragma unroll
                for (int b2 = 0; b2 < 2; b2++) {
                    int c = b2 * 64 + tx * 4;
                    *(float4*)&g_P1[(size_t)r * HID + c] =
                        make_float4(acc1[a][i][b2][0], acc1[a][i][b2][1],
                                    acc1[a][i][b2][2], acc1[a][i][b2][3]);
                    *(float4*)&g_P3[(size_t)r * HID + c] =
                        make_float4(acc3[a][i][b2][0], acc3[a][i][b2][1],
                                    acc3[a][i][b2][2], acc3[a][i][b2][3]);
                }
            }
        }
}

// ====================== persistent fp16 MMA-chain edge kernel ================
// M=64 tile, 128 threads, 2 CTAs/SM
#define SM_BM   0
#define SM_BE   512
#define SM_SRC  1024
#define SM_DST  1280
#define SM_EFH  1536            // fp16 [64][24]  (48B stride)
#define SM_EFL  4608
#define SM_WEH  7680            // fp16 [128][24] (We^T hi, [n][k=16])
#define SM_WEL  13824
#define SM_BW   19968           // fp16 [128][136] W_mid image
#define SM_OUT  54784           // fp32 [64][132]
#define SM_TOTAL 88576
#define TSTRIDE 272
#define EFST    48

__global__ void __launch_bounds__(128, 2)
msg_v7(int layer, const float* __restrict__ ef,
       const float* __restrict__ We, const float* __restrict__ be,
       const float* __restrict__ bm)
{
    extern __shared__ __align__(16) char smem[];
    const uint32_t sb = smem_u32(smem);
    const int tid = threadIdx.x;
    const int wid = tid >> 5, lane = tid & 31;

    float* sBm = (float*)(smem + SM_BM);
    float* beS = (float*)(smem + SM_BE);
    int*   sSrc = (int*)(smem + SM_SRC);
    int*   sDst = (int*)(smem + SM_DST);
    float* OUT = (float*)(smem + SM_OUT);   // [64][132]

    // ---- one-time setup (128 threads)
    sBm[tid] = bm[tid]; beS[tid] = be[tid];
    {   // stage We^T hi/lo fp16: row n = tid, 16 k values (column n of We)
        int n = tid;
        uint32_t h8[8], l8[8];
#pragma unroll
        for (int p = 0; p < 8; p++) {
            float w0 = We[(2 * p) * 128 + n];
            float w1 = We[(2 * p + 1) * 128 + n];
            split2h(w0, w1, h8[p], l8[p]);
        }
        *(uint4*)(smem + SM_WEH + n * EFST)      = make_uint4(h8[0], h8[1], h8[2], h8[3]);
        *(uint4*)(smem + SM_WEH + n * EFST + 16) = make_uint4(h8[4], h8[5], h8[6], h8[7]);
        *(uint4*)(smem + SM_WEL + n * EFST)      = make_uint4(l8[0], l8[1], l8[2], l8[3]);
        *(uint4*)(smem + SM_WEL + n * EFST + 16) = make_uint4(l8[4], l8[5], l8[6], l8[7]);
    }
    {   // stage W_mid fp16 image into padded smem [n][136]
        const uint4* wsrc = (const uint4*)g_Wh[layer];
#pragma unroll
        for (int u = 0; u < 16; u++) {
            int g = tid + u * 128;           // 0..2047
            int n = g >> 4, q = g & 15;      // 16 uint4 per 128-fp16 row
            *(uint4*)(smem + SM_BW + n * TSTRIDE + q * 16) = wsrc[g];
        }
    }

    const int wm = wid * 16;
    // ldmatrix offsets
    const uint32_t aEfOff = (uint32_t)((wm + (lane & 7) + ((lane >> 3) & 1) * 8) * EFST
                                       + (lane >> 4) * 16);
    const uint32_t bEfOff = (uint32_t)(((lane & 7) + (lane >> 4) * 8) * EFST
                                       + ((lane >> 3) & 1) * 16);
    const uint32_t bMnOff = (uint32_t)(((lane & 7) + (lane >> 4) * 8) * TSTRIDE
                                       + (((lane >> 3) & 1) * 8) * 2);
    const uint32_t efhA = sb + SM_EFH + aEfOff;
    const uint32_t eflA = sb + SM_EFL + aEfOff;
    const uint32_t wehA = sb + SM_WEH + bEfOff;
    const uint32_t welA = sb + SM_WEL + bEfOff;
    const uint32_t bwA  = sb + SM_BW + bMnOff;

    const int er0 = wm + (lane >> 2);        // rows er0, er0+8 (0..63)
    const int cb  = (lane & 3) * 2;

    __syncthreads();

    for (int t = blockIdx.x; t < NE / 64; t += gridDim.x) {
        const int eBase = t * 64;
        // ---- stage indices (sorted by dst) and permuted ef rows (fp16 hi/lo)
        if (tid < 64) sSrc[tid] = g_srcp[eBase + tid];
        else          sDst[tid - 64] = g_dstp[eBase + tid - 64];
        {
            int r = tid >> 1, u = tid & 1;   // rows 0..63
            int eid = g_eper[eBase + r];
            const float4* eg = (const float4*)(ef + (size_t)eid * 16) + u * 2;
            float4 v0 = eg[0], v1 = eg[1];
            uint32_t h4[4], l4[4];
            split2h(v0.x, v0.y, h4[0], l4[0]);
            split2h(v0.z, v0.w, h4[1], l4[1]);
            split2h(v1.x, v1.y, h4[2], l4[2]);
            split2h(v1.z, v1.w, h4[3], l4[3]);
            uint32_t off = (uint32_t)(r * EFST + u * 16);
            *(uint4*)(smem + SM_EFH + off) = make_uint4(h4[0], h4[1], h4[2], h4[3]);
            *(uint4*)(smem + SM_EFL + off) = make_uint4(l4[0], l4[1], l4[2], l4[3]);
        }
        __syncthreads();

        // ---- he GEMM (K=16, 3-product fp16: hh + hL + lH) -> acc2 registers
        float acc2[16][4];
#pragma unroll
        for (int n = 0; n < 16; n++)
#pragma unroll
            for (int j = 0; j < 4; j++) acc2[n][j] = 0.f;
        {
            uint32_t eh0, eh1, eh2, eh3, el0, el1, el2, el3;
            ldsm4(eh0, eh1, eh2, eh3, efhA);
            ldsm4(el0, el1, el2, el3, eflA);
#pragma unroll
            for (int g = 0; g < 8; g++) {
                uint32_t wh0, wh1, wh2, wh3, wl0, wl1, wl2, wl3;
                ldsm4(wh0, wh1, wh2, wh3, wehA + g * (16 * EFST));
                ldsm4(wl0, wl1, wl2, wl3, welA + g * (16 * EFST));
                mma16816h(acc2[2 * g],     eh0, eh1, eh2, eh3, wh0, wh1);
                mma16816h(acc2[2 * g],     eh0, eh1, eh2, eh3, wl0, wl1);
                mma16816h(acc2[2 * g],     el0, el1, el2, el3, wh0, wh1);
                mma16816h(acc2[2 * g + 1], eh0, eh1, eh2, eh3, wh2, wh3);
                mma16816h(acc2[2 * g + 1], eh0, eh1, eh2, eh3, wl2, wl3);
                mma16816h(acc2[2 * g + 1], el0, el1, el2, el3, wh2, wh3);
            }
        }

        // ---- bias + relu + fp16 hi/lo split -> main-GEMM A fragments (regs)
        uint32_t aH[8][4], aL[8][4];
#pragma unroll
        for (int nt = 0; nt < 16; nt++) {
            int col = nt * 8 + cb;
            float be0 = beS[col], be1 = beS[col + 1];
            float v0 = fmaxf(acc2[nt][0] + be0, 0.f);
            float v1 = fmaxf(acc2[nt][1] + be1, 0.f);
            float v2 = fmaxf(acc2[nt][2] + be0, 0.f);
            float v3 = fmaxf(acc2[nt][3] + be1, 0.f);
            int ks = nt >> 1, j0 = (nt & 1) * 2;
            split2h(v0, v1, aH[ks][j0],     aL[ks][j0]);
            split2h(v2, v3, aH[ks][j0 + 1], aL[ks][j0 + 1]);
        }

        // ---- main GEMM: D = Ah*W + Al*W (W = fp16 image, single copy)
        float acc[16][4];
#pragma unroll
        for (int n = 0; n < 16; n++)
#pragma unroll
            for (int j = 0; j < 4; j++) acc[n][j] = 0.f;
#pragma unroll
        for (int ks = 0; ks < 8; ks++) {
#pragma unroll
            for (int np = 0; np < 8; np++) {
                uint32_t b0, b1, b2, b3;
                ldsm4(b0, b1, b2, b3, bwA + np * (16 * TSTRIDE) + ks * 32);
                mma16816h(acc[2 * np],     aH[ks][0], aH[ks][1], aH[ks][2], aH[ks][3], b0, b1);
                mma16816h(acc[2 * np],     aL[ks][0], aL[ks][1], aL[ks][2], aL[ks][3], b0, b1);
                mma16816h(acc[2 * np + 1], aH[ks][0], aH[ks][1], aH[ks][2], aH[ks][3], b2, b3);
                mma16816h(acc[2 * np + 1], aL[ks][0], aL[ks][1], aL[ks][2], aL[ks][3], b2, b3);
            }
        }

        // ---- write msg tile to smem: relu(acc + bias + P1[src] + P3[dst])
        {
            int s0 = sSrc[er0], d0 = sDst[er0];
            int s1 = sSrc[er0 + 8], d1 = sDst[er0 + 8];
            const float* p1a = g_P1 + (size_t)s0 * HID;
            const float* p3a = g_P3 + (size_t)d0 * HID;
            const float* p1b = g_P1 + (size_t)s1 * HID;
            const float* p3b = g_P3 + (size_t)d1 * HID;
#pragma unroll
            for (int nt = 0; nt < 16; nt++) {
                int col = nt * 8 + cb;
                float2 q1 = *(const float2*)(p1a + col);
                float2 q3 = *(const float2*)(p3a + col);
                float2 o0;
                o0.x = fmaxf(acc[nt][0] + sBm[col]     + q1.x + q3.x, 0.f);
                o0.y = fmaxf(acc[nt][1] + sBm[col + 1] + q1.y + q3.y, 0.f);
                *(float2*)&OUT[er0 * 132 + col] = o0;
                float2 r1 = *(const float2*)(p1b + col);
                float2 r3 = *(const float2*)(p3b + col);
                float2 o1;
                o1.x = fmaxf(acc[nt][2] + sBm[col]     + r1.x + r3.x, 0.f);
                o1.y = fmaxf(acc[nt][3] + sBm[col + 1] + r1.y + r3.y, 0.f);
                *(float2*)&OUT[(er0 + 8) * 132 + col] = o1;
            }
        }
        __syncthreads();

        // ---- segmented reduction (dst-sorted): one RED per (segment, col)
        {
            int col = tid;   // 0..127
            float s = 0.f;
            int cur = sDst[0];
#pragma unroll 4
            for (int r2 = 0; r2 < 64; r2++) {
                int dn = sDst[r2];
                if (dn != cur) {
                    if (s != 0.f) atomicAdd(&g_agg[(size_t)cur * HID + col], s);
                    cur = dn; s = 0.f;
                }
                s += OUT[r2 * 132 + col];
            }
            if (s != 0.f) atomicAdd(&g_agg[(size_t)cur * HID + col], s);
        }
        __syncthreads();
    }
}

// ---------------------------------------------------------------- update GEMM
__global__ void __launch_bounds__(256, 2)
upd_gemm(int layer, const float* __restrict__ W, const float* __restrict__ bias)
{
    const float* __restrict__ hn   = layer ? g_hn1 : g_hn0;
    float*       __restrict__ hout = layer ? g_hn0 : g_hn1;
    __shared__ __align__(16) float As[16][132];
    __shared__ __align__(16) float Bs[16][132];
    __shared__ float sB[128];

    const int tid   = threadIdx.x;
    const int nBase = blockIdx.x * 128;
    if (tid < 128) sB[tid] = bias[tid];
    __syncthreads();

    const int arow = tid >> 1;
    const int akl  = (tid & 1) * 8;
    const int tx   = tid & 15, ty = tid >> 4;
    const int nrow = min(nBase + arow, NN - 1);

    float acc[2][4][2][4];
#pragma unroll
    for (int a = 0; a < 2; a++)
#pragma unroll
        for (int i = 0; i < 4; i++)
#pragma unroll
            for (int b2 = 0; b2 < 2; b2++)
#pragma unroll
                for (int j = 0; j < 4; j++) acc[a][i][b2][j] = 0.f;

    float4 apf0, apf1, bpf0, bpf1;
    {
        const float* base = hn + (size_t)nrow * HID;
        apf0 = *(const float4*)(base + akl);
        apf1 = *(const float4*)(base + akl + 4);
        const float4* wb = (const float4*)W;
        bpf0 = wb[tid]; bpf1 = wb[tid + 256];
    }

    for (int t = 0; t < 16; t++) {
        As[akl + 0][arow] = apf0.x; As[akl + 1][arow] = apf0.y;
        As[akl + 2][arow] = apf0.z; As[akl + 3][arow] = apf0.w;
        As[akl + 4][arow] = apf1.x; As[akl + 5][arow] = apf1.y;
        As[akl + 6][arow] = apf1.z; As[akl + 7][arow] = apf1.w;
        {
            int k0 = tid >> 5, c0 = (tid & 31) * 4;
            *(float4*)&Bs[k0][c0]     = bpf0;
            *(float4*)&Bs[k0 + 8][c0] = bpf1;
        }
        __syncthreads();
        if (t < 15) {
            int kb = (t + 1) * 16;
            int seg = kb >> 7, off = kb & 127;
            const float* base = (seg == 0) ? hn + (size_t)nrow * HID + off
                                           : g_agg + (size_t)nrow * HID + off;
            apf0 = *(const float4*)(base + akl);
            apf1 = *(const float4*)(base + akl + 4);
            const float4* wb = (const float4*)(W + (size_t)kb * HID);
            bpf0 = wb[tid]; bpf1 = wb[tid + 256];
        }
#pragma unroll
        for (int k = 0; k < 16; k++) {
            float4 a0 = *(const float4*)&As[k][ty * 4];
            float4 a1 = *(const float4*)&As[k][64 + ty * 4];
            float4 b0 = *(const float4*)&Bs[k][tx * 4];
            float4 b1 = *(const float4*)&Bs[k][64 + tx * 4];
            float ar[8] = {a0.x, a0.y, a0.z, a0.w, a1.x, a1.y, a1.z, a1.w};
            float br[8] = {b0.x, b0.y, b0.z, b0.w, b1.x, b1.y, b1.z, b1.w};
#pragma unroll
            for (int a = 0; a < 2; a++)
#pragma unroll
                for (int i = 0; i < 4; i++)
#pragma unroll
                    for (int b2 = 0; b2 < 2; b2++)
#pragma unroll
                        for (int j = 0; j < 4; j++)
                            acc[a][i][b2][j] = fmaf(ar[a * 4 + i], br[b2 * 4 + j], acc[a][i][b2][j]);
        }
        __syncthreads();
    }

#pragma unroll
    for (int a = 0; a < 2; a++)
#pragma unroll
        for (int i = 0; i < 4; i++) {
            int r = nBase + a * 64 + ty * 4 + i;
            if (r < NN) {
#pragma unroll
                for (int b2 = 0; b2 < 2; b2++)
#pragma unroll
                    for (int j = 0; j < 4; j++) {
                        int c = b2 * 64 + tx * 4 + j;
                        hout[(size_t)r * HID + c] = fmaxf(acc[a][i][b2][j] + sB[c], 0.f);
                    }
            }
        }
}

// --------------------------------------------- fused demand readout
__global__ void __launch_bounds__(256)
dem_v2(const int* __restrict__ pairs, const float* __restrict__ dfeat,
       const float* __restrict__ Wd, const float* __restrict__ br1,
       const float* __restrict__ w2, const float* __restrict__ b2,
       float* __restrict__ out)
{
    __shared__ __align__(16) float Wds[8][132];
    __shared__ float w2s[128], bs[128];
    int tid = threadIdx.x;
    if (tid < 128) { w2s[tid] = w2[tid]; bs[tid] = br1[tid]; }
    {
        int row = tid >> 5, c = (tid & 31) * 4;
        *(float4*)&Wds[row][c] = ((const float4*)Wd)[tid];
    }
    __syncthreads();

    int w = tid >> 5, lane = tid & 31;
    int d = blockIdx.x * 8 + w;
    int ds = pairs[2 * d], dd = pairs[2 * d + 1];
    int c0 = lane * 4;

    float4 q1 = *(const float4*)(g_P1 + (size_t)ds * HID + c0);
    float4 q2 = *(const float4*)(g_P3 + (size_t)dd * HID + c0);
    float s0 = bs[c0 + 0] + q1.x + q2.x;
    float s1 = bs[c0 + 1] + q1.y + q2.y;
    float s2 = bs[c0 + 2] + q1.z + q2.z;
    float s3 = bs[c0 + 3] + q1.w + q2.w;
#pragma unroll
    for (int q = 0; q < 8; q++) {
        float e = dfeat[(size_t)d * 8 + q];
        float4 wv = *(const float4*)&Wds[q][c0];
        s0 = fmaf(e, wv.x, s0); s1 = fmaf(e, wv.y, s1);
        s2 = fmaf(e, wv.z, s2); s3 = fmaf(e, wv.w, s3);
    }
    float p = fmaxf(s0, 0.f) * w2s[c0 + 0] + fmaxf(s1, 0.f) * w2s[c0 + 1]
            + fmaxf(s2, 0.f) * w2s[c0 + 2] + fmaxf(s3, 0.f) * w2s[c0 + 3];
#pragma unroll
    for (int o = 16; o > 0; o >>= 1) p += __shfl_xor_sync(0xffffffffu, p, o);
    if (lane == 0) out[d] = 1.f / (1.f + expf(-(p + b2[0])));
}

// ---------------------------------------------------------------- launch
extern "C" void kernel_launch(void* const* d_in, const int* in_sizes, int n_in,
                              void* d_out, int out_size)
{
    const float* node_feats = (const float*)d_in[0];
    const float* edge_feats = (const float*)d_in[1];
    const float* dem_feats  = (const float*)d_in[2];
    const int*   eidx       = (const int*)d_in[3];
    const int*   pairs      = (const int*)d_in[4];
    const float* W_node = (const float*)d_in[5];
    const float* b_node = (const float*)d_in[6];
    const float* W_edge = (const float*)d_in[7];
    const float* b_edge = (const float*)d_in[8];
    const float* W_msg0 = (const float*)d_in[9];
    const float* b_msg0 = (const float*)d_in[10];
    const float* W_upd0 = (const float*)d_in[11];
    const float* b_upd0 = (const float*)d_in[12];
    const float* W_msg1 = (const float*)d_in[13];
    const float* b_msg1 = (const float*)d_in[14];
    const float* W_upd1 = (const float*)d_in[15];
    const float* b_upd1 = (const float*)d_in[16];
    const float* W_r1   = (const float*)d_in[17];
    const float* b_r1   = (const float*)d_in[18];
    const float* W_r2   = (const float*)d_in[19];
    const float* b_r2   = (const float*)d_in[20];
    float* out = (float*)d_out;

    const int nTiles = (NN + 127) / 128;

    cudaFuncSetAttribute(msg_v7, cudaFuncAttributeMaxDynamicSharedMemorySize, SM_TOTAL);

    // ---- edge sort by dst (one-time, reused by both layers)
    zcnt<<<(NN + 256) / 256, 256>>>();
    hist<<<NE / 256, 256>>>(eidx);
    scan20k<<<1, 1024>>>();
    scatter<<<NE / 256, 256>>>(eidx);

    node_embed<<<NN / 16, 128>>>(node_feats, W_node, b_node);
    prep_w<<<2, 256>>>(W_msg0 + 128 * HID, W_msg1 + 128 * HID);

    // ---- layer 0
    gemm128x2<<<nTiles, 256>>>(0, W_msg0, W_msg0 + 256 * HID);
    zero_agg<<<(NN * HID / 4 + 255) / 256, 256>>>();
    msg_v7<<<304, 128, SM_TOTAL>>>(0, edge_feats, W_edge, b_edge, b_msg0);
    upd_gemm<<<nTiles, 256>>>(0, W_upd0, b_upd0);

    // ---- layer 1
    gemm128x2<<<nTiles, 256>>>(1, W_msg1, W_msg1 + 256 * HID);
    zero_agg<<<(NN * HID / 4 + 255) / 256, 256>>>();
    msg_v7<<<304, 128, SM_TOTAL>>>(1, edge_feats, W_edge, b_edge, b_msg1);
    upd_gemm<<<nTiles, 256>>>(1, W_upd1, b_upd1);

    // ---- readout
    gemm128x2<<<nTiles, 256>>>(0, W_r1, W_r1 + 128 * HID);
    dem_v2<<<ND / 8, 256>>>(pairs, dem_feats, W_r1 + 256 * HID, b_r1, W_r2, b_r2, out);
}

// round 8
// speedup vs baseline: 1.7518x; 1.0332x over previous
#include <cuda_runtime.h>
#include <cuda_fp16.h>
#include <math.h>
#include <stdint.h>

#define HID 128
#define NN 20000
#define NE 640000
#define ND 100000

// scratch (device globals: allocation-free contract)
__device__ float g_hn0[(size_t)NN * HID];
__device__ float g_hn1[(size_t)NN * HID];
__device__ float g_agg[(size_t)NN * HID];
__device__ float g_P1 [(size_t)NN * HID];
__device__ float g_P3 [(size_t)NN * HID];
__device__ __align__(16) __half g_Wh[2][128 * 128];   // fp16 W_mid, [n][k]
// edge sort-by-dst
__device__ int g_cnt[NN + 1];
__device__ int g_srcp[NE];
__device__ int g_dstp[NE];
__device__ int g_eper[NE];

// ======================= warp MMA helpers =======================
__device__ __forceinline__ uint32_t smem_u32(const void* p) {
    uint32_t a;
    asm("{ .reg .u64 t; cvta.to.shared.u64 t, %1; cvt.u32.u64 %0, t; }" : "=r"(a) : "l"(p));
    return a;
}
__device__ __forceinline__ void ldsm4(uint32_t& r0, uint32_t& r1, uint32_t& r2, uint32_t& r3,
                                      uint32_t addr) {
    asm volatile("ldmatrix.sync.aligned.m8n8.x4.shared.b16 {%0,%1,%2,%3}, [%4];"
                 : "=r"(r0), "=r"(r1), "=r"(r2), "=r"(r3) : "r"(addr));
}
__device__ __forceinline__ void mma16816h(float* c, uint32_t a0, uint32_t a1, uint32_t a2,
                                          uint32_t a3, uint32_t b0, uint32_t b1) {
    asm volatile("mma.sync.aligned.m16n8k16.row.col.f32.f16.f16.f32 "
                 "{%0,%1,%2,%3}, {%4,%5,%6,%7}, {%8,%9}, {%0,%1,%2,%3};"
                 : "+f"(c[0]), "+f"(c[1]), "+f"(c[2]), "+f"(c[3])
                 : "r"(a0), "r"(a1), "r"(a2), "r"(a3), "r"(b0), "r"(b1));
}
// split two fp32 into packed fp16 hi pair + fp16 residual pair
__device__ __forceinline__ void split2h(float v0, float v1, uint32_t& hi, uint32_t& lo) {
    __half h0 = __float2half_rn(v0);
    __half h1 = __float2half_rn(v1);
    __half m0 = __float2half_rn(v0 - __half2float(h0));
    __half m1 = __float2half_rn(v1 - __half2float(h1));
    hi = (uint32_t)__half_as_ushort(h0) | ((uint32_t)__half_as_ushort(h1) << 16);
    lo = (uint32_t)__half_as_ushort(m0) | ((uint32_t)__half_as_ushort(m1) << 16);
}
// pack two fp32 to fp16 pair (no residual)
__device__ __forceinline__ uint32_t pack2h(float v0, float v1) {
    __half h0 = __float2half_rn(v0);
    __half h1 = __float2half_rn(v1);
    return (uint32_t)__half_as_ushort(h0) | ((uint32_t)__half_as_ushort(h1) << 16);
}

// ---------------------------------------------------------------- sort by dst
__global__ void zcnt()
{
    int i = blockIdx.x * 256 + threadIdx.x;
    if (i <= NN) g_cnt[i] = 0;
}
__global__ void hist(const int* __restrict__ eidx)
{
    int e = blockIdx.x * 256 + threadIdx.x;
    atomicAdd(&g_cnt[eidx[NE + e]], 1);
}
__global__ void scan20k()
{
    __shared__ int part[1024];
    __shared__ int wsum[32];
    const int tid = threadIdx.x;
    const int CH = 20;
    int base = tid * CH;
    int loc[CH];
    int s = 0;
#pragma unroll
    for (int i = 0; i < CH; i++) {
        int v = (base + i <= NN) ? g_cnt[base + i] : 0;
        loc[i] = s; s += v;
    }
    part[tid] = s;
    __syncthreads();
    int lane = tid & 31, w = tid >> 5;
    int v = part[tid];
#pragma unroll
    for (int o = 1; o < 32; o <<= 1) { int t = __shfl_up_sync(~0u, v, o); if (lane >= o) v += t; }
    if (lane == 31) wsum[w] = v;
    __syncthreads();
    if (w == 0) {
        int x = wsum[lane];
#pragma unroll
        for (int o = 1; o < 32; o <<= 1) { int t = __shfl_up_sync(~0u, x, o); if (lane >= o) x += t; }
        wsum[lane] = x;
    }
    __syncthreads();
    int excl = v - part[tid] + (w ? wsum[w - 1] : 0);
#pragma unroll
    for (int i = 0; i < CH; i++)
        if (base + i <= NN) g_cnt[base + i] = excl + loc[i];
}
__global__ void scatter(const int* __restrict__ eidx)
{
    int e = blockIdx.x * 256 + threadIdx.x;
    int s = eidx[e], d = eidx[NE + e];
    int p = atomicAdd(&g_cnt[d], 1);
    g_srcp[p] = s; g_dstp[p] = d; g_eper[p] = e;
}

// ---------------------------------------------------------------- node embed
__global__ void node_embed(const float* __restrict__ x, const float* __restrict__ W,
                           const float* __restrict__ b)
{
    __shared__ float Ws[32 * HID];
    __shared__ float xs[16][33];
    int tid = threadIdx.x; // 128
    for (int i = tid; i < 32 * HID; i += 128) Ws[i] = W[i];
    int row0 = blockIdx.x * 16;
    for (int i = tid; i < 16 * 32; i += 128) xs[i >> 5][i & 31] = x[(size_t)row0 * 32 + i];
    float bb = b[tid];
    __syncthreads();
#pragma unroll 4
    for (int r = 0; r < 16; r++) {
        float acc = bb;
#pragma unroll
        for (int k = 0; k < 32; k++) acc = fmaf(xs[r][k], Ws[k * HID + tid], acc);
        g_hn0[(size_t)(row0 + r) * HID + tid] = fmaxf(acc, 0.f);
    }
}

// ---------------------------------------------------------------- zero agg
__global__ void zero_agg()
{
    size_t i = (size_t)blockIdx.x * blockDim.x + threadIdx.x;
    if (i < (size_t)NN * HID / 4) ((float4*)g_agg)[i] = make_float4(0.f, 0.f, 0.f, 0.f);
}

// ---------------------------------------- weight prep: fp16 image, [n][k]
__global__ void prep_w(const float* __restrict__ W0, const float* __restrict__ W1)
{
    const float* W = blockIdx.x ? W1 : W0;
    __half* wh = g_Wh[blockIdx.x];
    for (int idx = threadIdx.x; idx < 128 * 128; idx += blockDim.x) {
        int n = idx >> 7, k = idx & 127;
        wh[idx] = __float2half_rn(W[k * 128 + n]);
    }
}

// ------------------------------------- node-level dual GEMM (P1 & P3, no act)
__global__ void __launch_bounds__(256)
gemm128x2(int asel, const float* __restrict__ W1, const float* __restrict__ W3)
{
    const float* __restrict__ A = asel ? g_hn1 : g_hn0;
    __shared__ __align__(16) float As[16][132];
    __shared__ __align__(16) float B1s[16][132];
    __shared__ __align__(16) float B3s[16][132];

    const int tid   = threadIdx.x;
    const int nBase = blockIdx.x * 128;
    const int arow  = tid >> 1;
    const int akl   = (tid & 1) * 8;
    const int tx    = tid & 15, ty = tid >> 4;
    const int nrow  = min(nBase + arow, NN - 1);

    float acc1[2][4][2][4], acc3[2][4][2][4];
#pragma unroll
    for (int a = 0; a < 2; a++)
#pragma unroll
        for (int i = 0; i < 4; i++)
#pragma unroll
            for (int b2 = 0; b2 < 2; b2++)
#pragma unroll
                for (int j = 0; j < 4; j++) { acc1[a][i][b2][j] = 0.f; acc3[a][i][b2][j] = 0.f; }

    float4 apf0, apf1, b1p0, b1p1, b3p0, b3p1;
    {
        const float* base = A + (size_t)nrow * HID;
        apf0 = *(const float4*)(base + akl);
        apf1 = *(const float4*)(base + akl + 4);
        b1p0 = ((const float4*)W1)[tid]; b1p1 = ((const float4*)W1)[tid + 256];
        b3p0 = ((const float4*)W3)[tid]; b3p1 = ((const float4*)W3)[tid + 256];
    }

    for (int t = 0; t < 8; t++) {
        As[akl + 0][arow] = apf0.x; As[akl + 1][arow] = apf0.y;
        As[akl + 2][arow] = apf0.z; As[akl + 3][arow] = apf0.w;
        As[akl + 4][arow] = apf1.x; As[akl + 5][arow] = apf1.y;
        As[akl + 6][arow] = apf1.z; As[akl + 7][arow] = apf1.w;
        {
            int k0 = tid >> 5, c0 = (tid & 31) * 4;
            *(float4*)&B1s[k0][c0]     = b1p0;
            *(float4*)&B1s[k0 + 8][c0] = b1p1;
            *(float4*)&B3s[k0][c0]     = b3p0;
            *(float4*)&B3s[k0 + 8][c0] = b3p1;
        }
        __syncthreads();
        if (t < 7) {
            int kb = (t + 1) * 16;
            const float* base = A + (size_t)nrow * HID + kb;
            apf0 = *(const float4*)(base + akl);
            apf1 = *(const float4*)(base + akl + 4);
            b1p0 = ((const float4*)(W1 + (size_t)kb * HID))[tid];
            b1p1 = ((const float4*)(W1 + (size_t)kb * HID))[tid + 256];
            b3p0 = ((const float4*)(W3 + (size_t)kb * HID))[tid];
            b3p1 = ((const float4*)(W3 + (size_t)kb * HID))[tid + 256];
        }
#pragma unroll
        for (int k = 0; k < 16; k++) {
            float4 a0 = *(const float4*)&As[k][ty * 4];
            float4 a1 = *(const float4*)&As[k][64 + ty * 4];
            float ar[8] = {a0.x, a0.y, a0.z, a0.w, a1.x, a1.y, a1.z, a1.w};
            float4 p0 = *(const float4*)&B1s[k][tx * 4];
            float4 p1 = *(const float4*)&B1s[k][64 + tx * 4];
            float4 q0 = *(const float4*)&B3s[k][tx * 4];
            float4 q1 = *(const float4*)&B3s[k][64 + tx * 4];
            float br1[8] = {p0.x, p0.y, p0.z, p0.w, p1.x, p1.y, p1.z, p1.w};
            float br3[8] = {q0.x, q0.y, q0.z, q0.w, q1.x, q1.y, q1.z, q1.w};
#pragma unroll
            for (int a = 0; a < 2; a++)
#pragma unroll
                for (int i = 0; i < 4; i++)
#pragma unroll
                    for (int b2 = 0; b2 < 2; b2++)
#pragma unroll
                        for (int j = 0; j < 4; j++) {
                            acc1[a][i][b2][j] = fmaf(ar[a * 4 + i], br1[b2 * 4 + j], acc1[a][i][b2][j]);
                            acc3[a][i][b2][j] = fmaf(ar[a * 4 + i], br3[b2 * 4 + j], acc3[a][i][b2][j]);
                        }
        }
        __syncthreads();
    }

#pragma unroll
    for (int a = 0; a < 2; a++)
#pragma unroll
        for (int i = 0; i < 4; i++) {
            int r = nBase + a * 64 + ty * 4 + i;
            if (r < NN) {
#pragma unroll
                for (int b2 = 0; b2 < 2; b2++) {
                    int c = b2 * 64 + tx * 4;
                    *(float4*)&g_P1[(size_t)r * HID + c] =
                        make_float4(acc1[a][i][b2][0], acc1[a][i][b2][1],
                                    acc1[a][i][b2][2], acc1[a][i][b2][3]);
                    *(float4*)&g_P3[(size_t)r * HID + c] =
                        make_float4(acc3[a][i][b2][0], acc3[a][i][b2][1],
                                    acc3[a][i][b2][2], acc3[a][i][b2][3]);
                }
            }
        }
}

// ====================== persistent fp16 MMA-chain edge kernel ================
// M=64 tile, 128 threads, 2 CTAs/SM
#define SM_BM   0
#define SM_BE   512
#define SM_SRC  1024
#define SM_DST  1280
#define SM_EFH  1536            // fp16 [64][24]  (48B stride)
#define SM_EFL  4608
#define SM_WEH  7680            // fp16 [128][24] (We^T hi, [n][k=16])
#define SM_WEL  13824
#define SM_BW   19968           // fp16 [128][136] W_mid image
#define SM_OUT  54784           // fp32 [64][132]
#define SM_TOTAL 88576
#define TSTRIDE 272
#define EFST    48

__global__ void __launch_bounds__(128, 2)
msg_v8(int layer, const float* __restrict__ ef,
       const float* __restrict__ We, const float* __restrict__ be,
       const float* __restrict__ bm)
{
    extern __shared__ __align__(16) char smem[];
    const uint32_t sb = smem_u32(smem);
    const int tid = threadIdx.x;
    const int wid = tid >> 5, lane = tid & 31;

    float* sBm = (float*)(smem + SM_BM);
    float* beS = (float*)(smem + SM_BE);
    int*   sSrc = (int*)(smem + SM_SRC);
    int*   sDst = (int*)(smem + SM_DST);
    float* OUT = (float*)(smem + SM_OUT);   // [64][132]

    // ---- one-time setup (128 threads)
    sBm[tid] = bm[tid]; beS[tid] = be[tid];
    {   // stage We^T hi/lo fp16: row n = tid, 16 k values (column n of We)
        int n = tid;
        uint32_t h8[8], l8[8];
#pragma unroll
        for (int p = 0; p < 8; p++) {
            float w0 = We[(2 * p) * 128 + n];
            float w1 = We[(2 * p + 1) * 128 + n];
            split2h(w0, w1, h8[p], l8[p]);
        }
        *(uint4*)(smem + SM_WEH + n * EFST)      = make_uint4(h8[0], h8[1], h8[2], h8[3]);
        *(uint4*)(smem + SM_WEH + n * EFST + 16) = make_uint4(h8[4], h8[5], h8[6], h8[7]);
        *(uint4*)(smem + SM_WEL + n * EFST)      = make_uint4(l8[0], l8[1], l8[2], l8[3]);
        *(uint4*)(smem + SM_WEL + n * EFST + 16) = make_uint4(l8[4], l8[5], l8[6], l8[7]);
    }
    {   // stage W_mid fp16 image into padded smem [n][136]
        const uint4* wsrc = (const uint4*)g_Wh[layer];
#pragma unroll
        for (int u = 0; u < 16; u++) {
            int g = tid + u * 128;           // 0..2047
            int n = g >> 4, q = g & 15;      // 16 uint4 per 128-fp16 row
            *(uint4*)(smem + SM_BW + n * TSTRIDE + q * 16) = wsrc[g];
        }
    }

    const int wm = wid * 16;
    // ldmatrix offsets
    const uint32_t aEfOff = (uint32_t)((wm + (lane & 7) + ((lane >> 3) & 1) * 8) * EFST
                                       + (lane >> 4) * 16);
    const uint32_t bEfOff = (uint32_t)(((lane & 7) + (lane >> 4) * 8) * EFST
                                       + ((lane >> 3) & 1) * 16);
    const uint32_t bMnOff = (uint32_t)(((lane & 7) + (lane >> 4) * 8) * TSTRIDE
                                       + (((lane >> 3) & 1) * 8) * 2);
    const uint32_t efhA = sb + SM_EFH + aEfOff;
    const uint32_t eflA = sb + SM_EFL + aEfOff;
    const uint32_t wehA = sb + SM_WEH + bEfOff;
    const uint32_t welA = sb + SM_WEL + bEfOff;
    const uint32_t bwA  = sb + SM_BW + bMnOff;

    const int er0 = wm + (lane >> 2);        // rows er0, er0+8 (0..63)
    const int cb  = (lane & 3) * 2;

    __syncthreads();

    for (int t = blockIdx.x; t < NE / 64; t += gridDim.x) {
        const int eBase = t * 64;
        // ---- stage indices (sorted by dst) and permuted ef rows (fp16 hi/lo)
        if (tid < 64) sSrc[tid] = g_srcp[eBase + tid];
        else          sDst[tid - 64] = g_dstp[eBase + tid - 64];
        {
            int r = tid >> 1, u = tid & 1;   // rows 0..63
            int eid = g_eper[eBase + r];
            const float4* eg = (const float4*)(ef + (size_t)eid * 16) + u * 2;
            float4 v0 = eg[0], v1 = eg[1];
            uint32_t h4[4], l4[4];
            split2h(v0.x, v0.y, h4[0], l4[0]);
            split2h(v0.z, v0.w, h4[1], l4[1]);
            split2h(v1.x, v1.y, h4[2], l4[2]);
            split2h(v1.z, v1.w, h4[3], l4[3]);
            uint32_t off = (uint32_t)(r * EFST + u * 16);
            *(uint4*)(smem + SM_EFH + off) = make_uint4(h4[0], h4[1], h4[2], h4[3]);
            *(uint4*)(smem + SM_EFL + off) = make_uint4(l4[0], l4[1], l4[2], l4[3]);
        }
        __syncthreads();

        // ---- he GEMM (K=16, 3-product fp16: hh + hL + lH) -> acc2 registers
        float acc2[16][4];
#pragma unroll
        for (int n = 0; n < 16; n++)
#pragma unroll
            for (int j = 0; j < 4; j++) acc2[n][j] = 0.f;
        {
            uint32_t eh0, eh1, eh2, eh3, el0, el1, el2, el3;
            ldsm4(eh0, eh1, eh2, eh3, efhA);
            ldsm4(el0, el1, el2, el3, eflA);
#pragma unroll
            for (int g = 0; g < 8; g++) {
                uint32_t wh0, wh1, wh2, wh3, wl0, wl1, wl2, wl3;
                ldsm4(wh0, wh1, wh2, wh3, wehA + g * (16 * EFST));
                ldsm4(wl0, wl1, wl2, wl3, welA + g * (16 * EFST));
                mma16816h(acc2[2 * g],     eh0, eh1, eh2, eh3, wh0, wh1);
                mma16816h(acc2[2 * g],     eh0, eh1, eh2, eh3, wl0, wl1);
                mma16816h(acc2[2 * g],     el0, el1, el2, el3, wh0, wh1);
                mma16816h(acc2[2 * g + 1], eh0, eh1, eh2, eh3, wh2, wh3);
                mma16816h(acc2[2 * g + 1], eh0, eh1, eh2, eh3, wl2, wl3);
                mma16816h(acc2[2 * g + 1], el0, el1, el2, el3, wh2, wh3);
            }
        }

        // ---- bias + relu + fp16 round -> main-GEMM A fragments (registers)
        uint32_t aH[8][4];
#pragma unroll
        for (int nt = 0; nt < 16; nt++) {
            int col = nt * 8 + cb;
            float be0 = beS[col], be1 = beS[col + 1];
            float v0 = fmaxf(acc2[nt][0] + be0, 0.f);
            float v1 = fmaxf(acc2[nt][1] + be1, 0.f);
            float v2 = fmaxf(acc2[nt][2] + be0, 0.f);
            float v3 = fmaxf(acc2[nt][3] + be1, 0.f);
            int ks = nt >> 1, j0 = (nt & 1) * 2;
            aH[ks][j0]     = pack2h(v0, v1);
            aH[ks][j0 + 1] = pack2h(v2, v3);
        }

        // ---- main GEMM: D = Ah*W (single product; error ~1e-4 acceptable)
        float acc[16][4];
#pragma unroll
        for (int n = 0; n < 16; n++)
#pragma unroll
            for (int j = 0; j < 4; j++) acc[n][j] = 0.f;
#pragma unroll
        for (int ks = 0; ks < 8; ks++) {
#pragma unroll
            for (int np = 0; np < 8; np++) {
                uint32_t b0, b1, b2, b3;
                ldsm4(b0, b1, b2, b3, bwA + np * (16 * TSTRIDE) + ks * 32);
                mma16816h(acc[2 * np],     aH[ks][0], aH[ks][1], aH[ks][2], aH[ks][3], b0, b1);
                mma16816h(acc[2 * np + 1], aH[ks][0], aH[ks][1], aH[ks][2], aH[ks][3], b2, b3);
            }
        }

        // ---- write msg tile to smem: relu(acc + bias + P1[src] + P3[dst])
        {
            int s0 = sSrc[er0], d0 = sDst[er0];
            int s1 = sSrc[er0 + 8], d1 = sDst[er0 + 8];
            const float* p1a = g_P1 + (size_t)s0 * HID;
            const float* p3a = g_P3 + (size_t)d0 * HID;
            const float* p1b = g_P1 + (size_t)s1 * HID;
            const float* p3b = g_P3 + (size_t)d1 * HID;
#pragma unroll
            for (int nt = 0; nt < 16; nt++) {
                int col = nt * 8 + cb;
                float2 q1 = *(const float2*)(p1a + col);
                float2 q3 = *(const float2*)(p3a + col);
                float2 o0;
                o0.x = fmaxf(acc[nt][0] + sBm[col]     + q1.x + q3.x, 0.f);
                o0.y = fmaxf(acc[nt][1] + sBm[col + 1] + q1.y + q3.y, 0.f);
                *(float2*)&OUT[er0 * 132 + col] = o0;
                float2 r1 = *(const float2*)(p1b + col);
                float2 r3 = *(const float2*)(p3b + col);
                float2 o1;
                o1.x = fmaxf(acc[nt][2] + sBm[col]     + r1.x + r3.x, 0.f);
                o1.y = fmaxf(acc[nt][3] + sBm[col + 1] + r1.y + r3.y, 0.f);
                *(float2*)&OUT[(er0 + 8) * 132 + col] = o1;
            }
        }
        __syncthreads();

        // ---- segmented reduction (dst-sorted): one RED per (segment, col)
        {
            int col = tid;   // 0..127
            float s = 0.f;
            int cur = sDst[0];
#pragma unroll 4
            for (int r2 = 0; r2 < 64; r2++) {
                int dn = sDst[r2];
                if (dn != cur) {
                    if (s != 0.f) atomicAdd(&g_agg[(size_t)cur * HID + col], s);
                    cur = dn; s = 0.f;
                }
                s += OUT[r2 * 132 + col];
            }
            if (s != 0.f) atomicAdd(&g_agg[(size_t)cur * HID + col], s);
        }
        __syncthreads();
    }
}

// ---------------------------------------------------------------- update GEMM
__global__ void __launch_bounds__(256, 2)
upd_gemm(int layer, const float* __restrict__ W, const float* __restrict__ bias)
{
    const float* __restrict__ hn   = layer ? g_hn1 : g_hn0;
    float*       __restrict__ hout = layer ? g_hn0 : g_hn1;
    __shared__ __align__(16) float As[16][132];
    __shared__ __align__(16) float Bs[16][132];
    __shared__ float sB[128];

    const int tid   = threadIdx.x;
    const int nBase = blockIdx.x * 128;
    if (tid < 128) sB[tid] = bias[tid];
    __syncthreads();

    const int arow = tid >> 1;
    const int akl  = (tid & 1) * 8;
    const int tx   = tid & 15, ty = tid >> 4;
    const int nrow = min(nBase + arow, NN - 1);

    float acc[2][4][2][4];
#pragma unroll
    for (int a = 0; a < 2; a++)
#pragma unroll
        for (int i = 0; i < 4; i++)
#pragma unroll
            for (int b2 = 0; b2 < 2; b2++)
#pragma unroll
                for (int j = 0; j < 4; j++) acc[a][i][b2][j] = 0.f;

    float4 apf0, apf1, bpf0, bpf1;
    {
        const float* base = hn + (size_t)nrow * HID;
        apf0 = *(const float4*)(base + akl);
        apf1 = *(const float4*)(base + akl + 4);
        const float4* wb = (const float4*)W;
        bpf0 = wb[tid]; bpf1 = wb[tid + 256];
    }

    for (int t = 0; t < 16; t++) {
        As[akl + 0][arow] = apf0.x; As[akl + 1][arow] = apf0.y;
        As[akl + 2][arow] = apf0.z; As[akl + 3][arow] = apf0.w;
        As[akl + 4][arow] = apf1.x; As[akl + 5][arow] = apf1.y;
        As[akl + 6][arow] = apf1.z; As[akl + 7][arow] = apf1.w;
        {
            int k0 = tid >> 5, c0 = (tid & 31) * 4;
            *(float4*)&Bs[k0][c0]     = bpf0;
            *(float4*)&Bs[k0 + 8][c0] = bpf1;
        }
        __syncthreads();
        if (t < 15) {
            int kb = (t + 1) * 16;
            int seg = kb >> 7, off = kb & 127;
            const float* base = (seg == 0) ? hn + (size_t)nrow * HID + off
                                           : g_agg + (size_t)nrow * HID + off;
            apf0 = *(const float4*)(base + akl);
            apf1 = *(const float4*)(base + akl + 4);
            const float4* wb = (const float4*)(W + (size_t)kb * HID);
            bpf0 = wb[tid]; bpf1 = wb[tid + 256];
        }
#pragma unroll
        for (int k = 0; k < 16; k++) {
            float4 a0 = *(const float4*)&As[k][ty * 4];
            float4 a1 = *(const float4*)&As[k][64 + ty * 4];
            float4 b0 = *(const float4*)&Bs[k][tx * 4];
            float4 b1 = *(const float4*)&Bs[k][64 + tx * 4];
            float ar[8] = {a0.x, a0.y, a0.z, a0.w, a1.x, a1.y, a1.z, a1.w};
            float br[8] = {b0.x, b0.y, b0.z, b0.w, b1.x, b1.y, b1.z, b1.w};
#pragma unroll
            for (int a = 0; a < 2; a++)
#pragma unroll
                for (int i = 0; i < 4; i++)
#pragma unroll
                    for (int b2 = 0; b2 < 2; b2++)
#pragma unroll
                        for (int j = 0; j < 4; j++)
                            acc[a][i][b2][j] = fmaf(ar[a * 4 + i], br[b2 * 4 + j], acc[a][i][b2][j]);
        }
        __syncthreads();
    }

#pragma unroll
    for (int a = 0; a < 2; a++)
#pragma unroll
        for (int i = 0; i < 4; i++) {
            int r = nBase + a * 64 + ty * 4 + i;
            if (r < NN) {
#pragma unroll
                for (int b2 = 0; b2 < 2; b2++)
#pragma unroll
                    for (int j = 0; j < 4; j++) {
                        int c = b2 * 64 + tx * 4 + j;
                        hout[(size_t)r * HID + c] = fmaxf(acc[a][i][b2][j] + sB[c], 0.f);
                    }
            }
        }
}

// --------------------------------------------- fused demand readout
__global__ void __launch_bounds__(256)
dem_v2(const int* __restrict__ pairs, const float* __restrict__ dfeat,
       const float* __restrict__ Wd, const float* __restrict__ br1,
       const float* __restrict__ w2, const float* __restrict__ b2,
       float* __restrict__ out)
{
    __shared__ __align__(16) float Wds[8][132];
    __shared__ float w2s[128], bs[128];
    int tid = threadIdx.x;
    if (tid < 128) { w2s[tid] = w2[tid]; bs[tid] = br1[tid]; }
    {
        int row = tid >> 5, c = (tid & 31) * 4;
        *(float4*)&Wds[row][c] = ((const float4*)Wd)[tid];
    }
    __syncthreads();

    int w = tid >> 5, lane = tid & 31;
    int d = blockIdx.x * 8 + w;
    int ds = pairs[2 * d], dd = pairs[2 * d + 1];
    int c0 = lane * 4;

    float4 q1 = *(const float4*)(g_P1 + (size_t)ds * HID + c0);
    float4 q2 = *(const float4*)(g_P3 + (size_t)dd * HID + c0);
    float s0 = bs[c0 + 0] + q1.x + q2.x;
    float s1 = bs[c0 + 1] + q1.y + q2.y;
    float s2 = bs[c0 + 2] + q1.z + q2.z;
    float s3 = bs[c0 + 3] + q1.w + q2.w;
#pragma unroll
    for (int q = 0; q < 8; q++) {
        float e = dfeat[(size_t)d * 8 + q];
        float4 wv = *(const float4*)&Wds[q][c0];
        s0 = fmaf(e, wv.x, s0); s1 = fmaf(e, wv.y, s1);
        s2 = fmaf(e, wv.z, s2); s3 = fmaf(e, wv.w, s3);
    }
    float p = fmaxf(s0, 0.f) * w2s[c0 + 0] + fmaxf(s1, 0.f) * w2s[c0 + 1]
            + fmaxf(s2, 0.f) * w2s[c0 + 2] + fmaxf(s3, 0.f) * w2s[c0 + 3];
#pragma unroll
    for (int o = 16; o > 0; o >>= 1) p += __shfl_xor_sync(0xffffffffu, p, o);
    if (lane == 0) out[d] = 1.f / (1.f + expf(-(p + b2[0])));
}

// ---------------------------------------------------------------- launch
extern "C" void kernel_launch(void* const* d_in, const int* in_sizes, int n_in,
                              void* d_out, int out_size)
{
    const float* node_feats = (const float*)d_in[0];
    const float* edge_feats = (const float*)d_in[1];
    const float* dem_feats  = (const float*)d_in[2];
    const int*   eidx       = (const int*)d_in[3];
    const int*   pairs      = (const int*)d_in[4];
    const float* W_node = (const float*)d_in[5];
    const float* b_node = (const float*)d_in[6];
    const float* W_edge = (const float*)d_in[7];
    const float* b_edge = (const float*)d_in[8];
    const float* W_msg0 = (const float*)d_in[9];
    const float* b_msg0 = (const float*)d_in[10];
    const float* W_upd0 = (const float*)d_in[11];
    const float* b_upd0 = (const float*)d_in[12];
    const float* W_msg1 = (const float*)d_in[13];
    const float* b_msg1 = (const float*)d_in[14];
    const float* W_upd1 = (const float*)d_in[15];
    const float* b_upd1 = (const float*)d_in[16];
    const float* W_r1   = (const float*)d_in[17];
    const float* b_r1   = (const float*)d_in[18];
    const float* W_r2   = (const float*)d_in[19];
    const float* b_r2   = (const float*)d_in[20];
    float* out = (float*)d_out;

    const int nTiles = (NN + 127) / 128;

    cudaFuncSetAttribute(msg_v8, cudaFuncAttributeMaxDynamicSharedMemorySize, SM_TOTAL);

    // ---- edge sort by dst (one-time, reused by both layers)
    zcnt<<<(NN + 256) / 256, 256>>>();
    hist<<<NE / 256, 256>>>(eidx);
    scan20k<<<1, 1024>>>();
    scatter<<<NE / 256, 256>>>(eidx);

    node_embed<<<NN / 16, 128>>>(node_feats, W_node, b_node);
    prep_w<<<2, 256>>>(W_msg0 + 128 * HID, W_msg1 + 128 * HID);

    // ---- layer 0
    gemm128x2<<<nTiles, 256>>>(0, W_msg0, W_msg0 + 256 * HID);
    zero_agg<<<(NN * HID / 4 + 255) / 256, 256>>>();
    msg_v8<<<304, 128, SM_TOTAL>>>(0, edge_feats, W_edge, b_edge, b_msg0);
    upd_gemm<<<nTiles, 256>>>(0, W_upd0, b_upd0);

    // ---- layer 1
    gemm128x2<<<nTiles, 256>>>(1, W_msg1, W_msg1 + 256 * HID);
    zero_agg<<<(NN * HID / 4 + 255) / 256, 256>>>();
    msg_v8<<<304, 128, SM_TOTAL>>>(1, edge_feats, W_edge, b_edge, b_msg1);
    upd_gemm<<<nTiles, 256>>>(1, W_upd1, b_upd1);

    // ---- readout
    gemm128x2<<<nTiles, 256>>>(0, W_r1, W_r1 + 128 * HID);
    dem_v2<<<ND / 8, 256>>>(pairs, dem_feats, W_r1 + 256 * HID, b_r1, W_r2, b_r2, out);
}

// round 9
// speedup vs baseline: 1.8551x; 1.0590x over previous
#include <cuda_runtime.h>
#include <cuda_fp16.h>
#include <math.h>
#include <stdint.h>

#define HID 128
#define NN 20000
#define NE 640000
#define ND 100000

// scratch (device globals: allocation-free contract)
__device__ float g_hn0[(size_t)NN * HID];
__device__ float g_hn1[(size_t)NN * HID];
__device__ float g_agg[(size_t)NN * HID];
__device__ float g_P1 [(size_t)NN * HID];
__device__ float g_P3 [(size_t)NN * HID];
__device__ __align__(16) __half g_Wh[2][128 * 128];   // fp16 W_mid, [n][k]
// edge sort-by-dst (+ pre-permuted fp16 hi/lo edge features)
__device__ int g_cnt[NN + 1];
__device__ int g_srcp[NE];
__device__ int g_dstp[NE];
__device__ __align__(16) __half g_efh[(size_t)NE * 16];
__device__ __align__(16) __half g_efl[(size_t)NE * 16];

// ======================= helpers =======================
__device__ __forceinline__ uint32_t smem_u32(const void* p) {
    uint32_t a;
    asm("{ .reg .u64 t; cvta.to.shared.u64 t, %1; cvt.u32.u64 %0, t; }" : "=r"(a) : "l"(p));
    return a;
}
__device__ __forceinline__ void ldsm4(uint32_t& r0, uint32_t& r1, uint32_t& r2, uint32_t& r3,
                                      uint32_t addr) {
    asm volatile("ldmatrix.sync.aligned.m8n8.x4.shared.b16 {%0,%1,%2,%3}, [%4];"
                 : "=r"(r0), "=r"(r1), "=r"(r2), "=r"(r3) : "r"(addr));
}
__device__ __forceinline__ void mma16816h(float* c, uint32_t a0, uint32_t a1, uint32_t a2,
                                          uint32_t a3, uint32_t b0, uint32_t b1) {
    asm volatile("mma.sync.aligned.m16n8k16.row.col.f32.f16.f16.f32 "
                 "{%0,%1,%2,%3}, {%4,%5,%6,%7}, {%8,%9}, {%0,%1,%2,%3};"
                 : "+f"(c[0]), "+f"(c[1]), "+f"(c[2]), "+f"(c[3])
                 : "r"(a0), "r"(a1), "r"(a2), "r"(a3), "r"(b0), "r"(b1));
}
__device__ __forceinline__ void split2h(float v0, float v1, uint32_t& hi, uint32_t& lo) {
    __half h0 = __float2half_rn(v0);
    __half h1 = __float2half_rn(v1);
    __half m0 = __float2half_rn(v0 - __half2float(h0));
    __half m1 = __float2half_rn(v1 - __half2float(h1));
    hi = (uint32_t)__half_as_ushort(h0) | ((uint32_t)__half_as_ushort(h1) << 16);
    lo = (uint32_t)__half_as_ushort(m0) | ((uint32_t)__half_as_ushort(m1) << 16);
}
__device__ __forceinline__ uint32_t pack2h(float v0, float v1) {
    __half h0 = __float2half_rn(v0);
    __half h1 = __float2half_rn(v1);
    return (uint32_t)__half_as_ushort(h0) | ((uint32_t)__half_as_ushort(h1) << 16);
}
__device__ __forceinline__ void cp16(uint32_t smem_dst, const void* gsrc) {
    asm volatile("cp.async.cg.shared.global [%0], [%1], 16;"
                 :: "r"(smem_dst), "l"(gsrc) : "memory");
}
#define CP_COMMIT()  asm volatile("cp.async.commit_group;" ::: "memory")
#define CP_WAIT(N)   asm volatile("cp.async.wait_group %0;" :: "n"(N) : "memory")

// ---------------------------------------------------------------- sort by dst
__global__ void zcnt()
{
    int i = blockIdx.x * 256 + threadIdx.x;
    if (i <= NN) g_cnt[i] = 0;
}
__global__ void hist(const int* __restrict__ eidx)
{
    int e = blockIdx.x * 256 + threadIdx.x;
    atomicAdd(&g_cnt[eidx[NE + e]], 1);
}
__global__ void scan20k()
{
    __shared__ int part[1024];
    __shared__ int wsum[32];
    const int tid = threadIdx.x;
    const int CH = 20;
    int base = tid * CH;
    int loc[CH];
    int s = 0;
#pragma unroll
    for (int i = 0; i < CH; i++) {
        int v = (base + i <= NN) ? g_cnt[base + i] : 0;
        loc[i] = s; s += v;
    }
    part[tid] = s;
    __syncthreads();
    int lane = tid & 31, w = tid >> 5;
    int v = part[tid];
#pragma unroll
    for (int o = 1; o < 32; o <<= 1) { int t = __shfl_up_sync(~0u, v, o); if (lane >= o) v += t; }
    if (lane == 31) wsum[w] = v;
    __syncthreads();
    if (w == 0) {
        int x = wsum[lane];
#pragma unroll
        for (int o = 1; o < 32; o <<= 1) { int t = __shfl_up_sync(~0u, x, o); if (lane >= o) x += t; }
        wsum[lane] = x;
    }
    __syncthreads();
    int excl = v - part[tid] + (w ? wsum[w - 1] : 0);
#pragma unroll
    for (int i = 0; i < CH; i++)
        if (base + i <= NN) g_cnt[base + i] = excl + loc[i];
}
// scatter: sort edges by dst AND pre-permute ef rows as fp16 hi/lo
__global__ void scatter(const int* __restrict__ eidx, const float* __restrict__ ef)
{
    int e = blockIdx.x * 256 + threadIdx.x;
    int s = eidx[e], d = eidx[NE + e];
    int p = atomicAdd(&g_cnt[d], 1);
    g_srcp[p] = s; g_dstp[p] = d;
    const float4* eg = (const float4*)(ef + (size_t)e * 16);
    float4 v0 = eg[0], v1 = eg[1], v2 = eg[2], v3 = eg[3];
    uint32_t h[8], l[8];
    split2h(v0.x, v0.y, h[0], l[0]); split2h(v0.z, v0.w, h[1], l[1]);
    split2h(v1.x, v1.y, h[2], l[2]); split2h(v1.z, v1.w, h[3], l[3]);
    split2h(v2.x, v2.y, h[4], l[4]); split2h(v2.z, v2.w, h[5], l[5]);
    split2h(v3.x, v3.y, h[6], l[6]); split2h(v3.z, v3.w, h[7], l[7]);
    uint4* dh = (uint4*)(g_efh + (size_t)p * 16);
    uint4* dl = (uint4*)(g_efl + (size_t)p * 16);
    dh[0] = make_uint4(h[0], h[1], h[2], h[3]);
    dh[1] = make_uint4(h[4], h[5], h[6], h[7]);
    dl[0] = make_uint4(l[0], l[1], l[2], l[3]);
    dl[1] = make_uint4(l[4], l[5], l[6], l[7]);
}

// ---------------------------------------------------------------- node embed
__global__ void node_embed(const float* __restrict__ x, const float* __restrict__ W,
                           const float* __restrict__ b)
{
    __shared__ float Ws[32 * HID];
    __shared__ float xs[16][33];
    int tid = threadIdx.x; // 128
    for (int i = tid; i < 32 * HID; i += 128) Ws[i] = W[i];
    int row0 = blockIdx.x * 16;
    for (int i = tid; i < 16 * 32; i += 128) xs[i >> 5][i & 31] = x[(size_t)row0 * 32 + i];
    float bb = b[tid];
    __syncthreads();
#pragma unroll 4
    for (int r = 0; r < 16; r++) {
        float acc = bb;
#pragma unroll
        for (int k = 0; k < 32; k++) acc = fmaf(xs[r][k], Ws[k * HID + tid], acc);
        g_hn0[(size_t)(row0 + r) * HID + tid] = fmaxf(acc, 0.f);
    }
}

// ---------------------------------------------------------------- zero agg
__global__ void zero_agg()
{
    size_t i = (size_t)blockIdx.x * blockDim.x + threadIdx.x;
    if (i < (size_t)NN * HID / 4) ((float4*)g_agg)[i] = make_float4(0.f, 0.f, 0.f, 0.f);
}

// ---------------------------------------- weight prep: fp16 image, [n][k]
__global__ void prep_w(const float* __restrict__ W0, const float* __restrict__ W1)
{
    const float* W = blockIdx.x ? W1 : W0;
    __half* wh = g_Wh[blockIdx.x];
    for (int idx = threadIdx.x; idx < 128 * 128; idx += blockDim.x) {
        int n = idx >> 7, k = idx & 127;
        wh[idx] = __float2half_rn(W[k * 128 + n]);
    }
}

// ------------------------------------- node-level dual GEMM (P1 & P3, no act)
__global__ void __launch_bounds__(256)
gemm128x2(int asel, const float* __restrict__ W1, const float* __restrict__ W3)
{
    const float* __restrict__ A = asel ? g_hn1 : g_hn0;
    __shared__ __align__(16) float As[16][132];
    __shared__ __align__(16) float B1s[16][132];
    __shared__ __align__(16) float B3s[16][132];

    const int tid   = threadIdx.x;
    const int nBase = blockIdx.x * 128;
    const int arow  = tid >> 1;
    const int akl   = (tid & 1) * 8;
    const int tx    = tid & 15, ty = tid >> 4;
    const int nrow  = min(nBase + arow, NN - 1);

    float acc1[2][4][2][4], acc3[2][4][2][4];
#pragma unroll
    for (int a = 0; a < 2; a++)
#pragma unroll
        for (int i = 0; i < 4; i++)
#pragma unroll
            for (int b2 = 0; b2 < 2; b2++)
#pragma unroll
                for (int j = 0; j < 4; j++) { acc1[a][i][b2][j] = 0.f; acc3[a][i][b2][j] = 0.f; }

    float4 apf0, apf1, b1p0, b1p1, b3p0, b3p1;
    {
        const float* base = A + (size_t)nrow * HID;
        apf0 = *(const float4*)(base + akl);
        apf1 = *(const float4*)(base + akl + 4);
        b1p0 = ((const float4*)W1)[tid]; b1p1 = ((const float4*)W1)[tid + 256];
        b3p0 = ((const float4*)W3)[tid]; b3p1 = ((const float4*)W3)[tid + 256];
    }

    for (int t = 0; t < 8; t++) {
        As[akl + 0][arow] = apf0.x; As[akl + 1][arow] = apf0.y;
        As[akl + 2][arow] = apf0.z; As[akl + 3][arow] = apf0.w;
        As[akl + 4][arow] = apf1.x; As[akl + 5][arow] = apf1.y;
        As[akl + 6][arow] = apf1.z; As[akl + 7][arow] = apf1.w;
        {
            int k0 = tid >> 5, c0 = (tid & 31) * 4;
            *(float4*)&B1s[k0][c0]     = b1p0;
            *(float4*)&B1s[k0 + 8][c0] = b1p1;
            *(float4*)&B3s[k0][c0]     = b3p0;
            *(float4*)&B3s[k0 + 8][c0] = b3p1;
        }
        __syncthreads();
        if (t < 7) {
            int kb = (t + 1) * 16;
            const float* base = A + (size_t)nrow * HID + kb;
            apf0 = *(const float4*)(base + akl);
            apf1 = *(const float4*)(base + akl + 4);
            b1p0 = ((const float4*)(W1 + (size_t)kb * HID))[tid];
            b1p1 = ((const float4*)(W1 + (size_t)kb * HID))[tid + 256];
            b3p0 = ((const float4*)(W3 + (size_t)kb * HID))[tid];
            b3p1 = ((const float4*)(W3 + (size_t)kb * HID))[tid + 256];
        }
#pragma unroll
        for (int k = 0; k < 16; k++) {
            float4 a0 = *(const float4*)&As[k][ty * 4];
            float4 a1 = *(const float4*)&As[k][64 + ty * 4];
            float ar[8] = {a0.x, a0.y, a0.z, a0.w, a1.x, a1.y, a1.z, a1.w};
            float4 p0 = *(const float4*)&B1s[k][tx * 4];
            float4 p1 = *(const float4*)&B1s[k][64 + tx * 4];
            float4 q0 = *(const float4*)&B3s[k][tx * 4];
            float4 q1 = *(const float4*)&B3s[k][64 + tx * 4];
            float br1[8] = {p0.x, p0.y, p0.z, p0.w, p1.x, p1.y, p1.z, p1.w};
            float br3[8] = {q0.x, q0.y, q0.z, q0.w, q1.x, q1.y, q1.z, q1.w};
#pragma unroll
            for (int a = 0; a < 2; a++)
#pragma unroll
                for (int i = 0; i < 4; i++)
#pragma unroll
                    for (int b2 = 0; b2 < 2; b2++)
#pragma unroll
                        for (int j = 0; j < 4; j++) {
                            acc1[a][i][b2][j] = fmaf(ar[a * 4 + i], br1[b2 * 4 + j], acc1[a][i][b2][j]);
                            acc3[a][i][b2][j] = fmaf(ar[a * 4 + i], br3[b2 * 4 + j], acc3[a][i][b2][j]);
                        }
        }
        __syncthreads();
    }

#pragma unroll
    for (int a = 0; a < 2; a++)
#pragma unroll
        for (int i = 0; i < 4; i++) {
            int r = nBase + a * 64 + ty * 4 + i;
            if (r < NN) {
#pragma unroll
                for (int b2 = 0; b2 < 2; b2++) {
                    int c = b2 * 64 + tx * 4;
                    *(float4*)&g_P1[(size_t)r * HID + c] =
                        make_float4(acc1[a][i][b2][0], acc1[a][i][b2][1],
                                    acc1[a][i][b2][2], acc1[a][i][b2][3]);
                    *(float4*)&g_P3[(size_t)r * HID + c] =
                        make_float4(acc3[a][i][b2][0], acc3[a][i][b2][1],
                                    acc3[a][i][b2][2], acc3[a][i][b2][3]);
                }
            }
        }
}

// ====================== pipelined fp16 MMA-chain edge kernel ================
// M=64 tile, 128 threads, 2 CTAs/SM, cp.async double-buffered staging
#define SM_BM    0
#define SM_BE    512
#define SM_IDX   1024           // 2 bufs x (src 256B + dst 256B) = 1024
#define SM_WEH   2048           // fp16 [128][24] (48B stride)
#define SM_WEL   8192
#define SM_EFH0  14336          // fp16 [64][24] x2 bufs (3072 each)
#define SM_EFL0  17408
#define SM_EFH1  20480
#define SM_EFL1  23552
#define SM_BW    26624          // fp16 [128][136] W_mid image (34816)
#define SM_OUT   61440          // fp32 [64][132] (33792) — doubles as P1 buffer
#define SM_TOTAL 95232
#define TSTRIDE  272
#define EFST     48

__global__ void __launch_bounds__(128, 2)
msg_v9(int layer, const float* __restrict__ We, const float* __restrict__ be,
       const float* __restrict__ bm)
{
    extern __shared__ __align__(16) char smem[];
    const uint32_t sb = smem_u32(smem);
    const int tid = threadIdx.x;
    const int wid = tid >> 5, lane = tid & 31;

    float* sBm = (float*)(smem + SM_BM);
    float* beS = (float*)(smem + SM_BE);
    float* OUT = (float*)(smem + SM_OUT);   // [64][132], aliased P1 buffer

    // ---- one-time setup (128 threads)
    sBm[tid] = bm[tid]; beS[tid] = be[tid];
    {   // stage We^T hi/lo fp16: row n = tid, 16 k values (column n of We)
        int n = tid;
        uint32_t h8[8], l8[8];
#pragma unroll
        for (int p = 0; p < 8; p++) {
            float w0 = We[(2 * p) * 128 + n];
            float w1 = We[(2 * p + 1) * 128 + n];
            split2h(w0, w1, h8[p], l8[p]);
        }
        *(uint4*)(smem + SM_WEH + n * EFST)      = make_uint4(h8[0], h8[1], h8[2], h8[3]);
        *(uint4*)(smem + SM_WEH + n * EFST + 16) = make_uint4(h8[4], h8[5], h8[6], h8[7]);
        *(uint4*)(smem + SM_WEL + n * EFST)      = make_uint4(l8[0], l8[1], l8[2], l8[3]);
        *(uint4*)(smem + SM_WEL + n * EFST + 16) = make_uint4(l8[4], l8[5], l8[6], l8[7]);
    }
    {   // stage W_mid fp16 image into padded smem [n][136]
        const uint4* wsrc = (const uint4*)g_Wh[layer];
#pragma unroll
        for (int u = 0; u < 16; u++) {
            int g = tid + u * 128;
            int n = g >> 4, q = g & 15;
            *(uint4*)(smem + SM_BW + n * TSTRIDE + q * 16) = wsrc[g];
        }
    }

    const int wm = wid * 16;
    const uint32_t aEfOff = (uint32_t)((wm + (lane & 7) + ((lane >> 3) & 1) * 8) * EFST
                                       + (lane >> 4) * 16);
    const uint32_t bEfOff = (uint32_t)(((lane & 7) + (lane >> 4) * 8) * EFST
                                       + ((lane >> 3) & 1) * 16);
    const uint32_t bMnOff = (uint32_t)(((lane & 7) + (lane >> 4) * 8) * TSTRIDE
                                       + (((lane >> 3) & 1) * 8) * 2);
    const uint32_t wehA = sb + SM_WEH + bEfOff;
    const uint32_t welA = sb + SM_WEL + bEfOff;
    const uint32_t bwA  = sb + SM_BW + bMnOff;

    const int er0 = wm + (lane >> 2);        // rows er0, er0+8 (0..63)
    const int cb  = (lane & 3) * 2;

    const int NT = NE / 64;

    // ---- stage helper offsets
    // stage(t, b): EFH/EFL 64 rows x 32B each -> 128 chunks of 16B per array
    //              src/dst idx: 64 ints each -> 16 chunks of 16B each
    auto stage_async = [&](int t, int b) {
        const int eBase = t * 64;
        uint32_t efh = sb + (b ? SM_EFH1 : SM_EFH0);
        uint32_t efl = sb + (b ? SM_EFL1 : SM_EFL0);
        // ef: each thread 1 chunk per array: row = tid>>1, half = tid&1
        {
            int r = tid >> 1, u = tid & 1;
            cp16(efh + r * EFST + u * 16, (const char*)(g_efh + (size_t)(eBase + r) * 16) + u * 16);
            cp16(efl + r * EFST + u * 16, (const char*)(g_efl + (size_t)(eBase + r) * 16) + u * 16);
        }
        // indices: 32 chunks total
        if (tid < 16)
            cp16(sb + SM_IDX + b * 512 + tid * 16, (const char*)(g_srcp + eBase) + tid * 16);
        else if (tid < 32)
            cp16(sb + SM_IDX + b * 512 + 256 + (tid - 16) * 16, (const char*)(g_dstp + eBase) + (tid - 16) * 16);
    };

    int t = blockIdx.x;
    int buf = 0;
    if (t < NT) stage_async(t, 0);
    CP_COMMIT();

    for (; t < NT; t += gridDim.x, buf ^= 1) {
        CP_WAIT(0);
        __syncthreads();     // stage(t) + prior tile's epilogue all visible

        int* sSrc = (int*)(smem + SM_IDX + buf * 512);
        int* sDst = (int*)(smem + SM_IDX + buf * 512 + 256);

        // ---- P1 gather prefetch into OUT buffer (group 1, oldest)
        {
#pragma unroll
            for (int i = 0; i < 16; i++) {
                int g = tid + i * 128;            // 0..2047
                int r = g >> 5, c = g & 31;       // row, 16B-chunk
                const char* src = (const char*)(g_P1 + (size_t)sSrc[r] * HID) + c * 16;
                cp16(sb + SM_OUT + r * 528 + c * 16, src);
            }
        }
        CP_COMMIT();

        // ---- stage(t+grid) into alternate buffer (group 2, newest)
        int tn = t + gridDim.x;
        if (tn < NT) stage_async(tn, buf ^ 1);
        CP_COMMIT();

        // ---- he GEMM (K=16, 3-product fp16) from buf
        const uint32_t efhA = sb + (buf ? SM_EFH1 : SM_EFH0) + aEfOff;
        const uint32_t eflA = sb + (buf ? SM_EFL1 : SM_EFL0) + aEfOff;
        float acc2[16][4];
#pragma unroll
        for (int n = 0; n < 16; n++)
#pragma unroll
            for (int j = 0; j < 4; j++) acc2[n][j] = 0.f;
        {
            uint32_t eh0, eh1, eh2, eh3, el0, el1, el2, el3;
            ldsm4(eh0, eh1, eh2, eh3, efhA);
            ldsm4(el0, el1, el2, el3, eflA);
#pragma unroll
            for (int g = 0; g < 8; g++) {
                uint32_t wh0, wh1, wh2, wh3, wl0, wl1, wl2, wl3;
                ldsm4(wh0, wh1, wh2, wh3, wehA + g * (16 * EFST));
                ldsm4(wl0, wl1, wl2, wl3, welA + g * (16 * EFST));
                mma16816h(acc2[2 * g],     eh0, eh1, eh2, eh3, wh0, wh1);
                mma16816h(acc2[2 * g],     eh0, eh1, eh2, eh3, wl0, wl1);
                mma16816h(acc2[2 * g],     el0, el1, el2, el3, wh0, wh1);
                mma16816h(acc2[2 * g + 1], eh0, eh1, eh2, eh3, wh2, wh3);
                mma16816h(acc2[2 * g + 1], eh0, eh1, eh2, eh3, wl2, wl3);
                mma16816h(acc2[2 * g + 1], el0, el1, el2, el3, wh2, wh3);
            }
        }

        // ---- bias + relu + fp16 round -> main-GEMM A fragments
        uint32_t aH[8][4];
#pragma unroll
        for (int nt = 0; nt < 16; nt++) {
            int col = nt * 8 + cb;
            float be0 = beS[col], be1 = beS[col + 1];
            float v0 = fmaxf(acc2[nt][0] + be0, 0.f);
            float v1 = fmaxf(acc2[nt][1] + be1, 0.f);
            float v2 = fmaxf(acc2[nt][2] + be0, 0.f);
            float v3 = fmaxf(acc2[nt][3] + be1, 0.f);
            int ks = nt >> 1, j0 = (nt & 1) * 2;
            aH[ks][j0]     = pack2h(v0, v1);
            aH[ks][j0 + 1] = pack2h(v2, v3);
        }

        // ---- main GEMM: D = Ah*W
        float acc[16][4];
#pragma unroll
        for (int n = 0; n < 16; n++)
#pragma unroll
            for (int j = 0; j < 4; j++) acc[n][j] = 0.f;
#pragma unroll
        for (int ks = 0; ks < 8; ks++) {
#pragma unroll
            for (int np = 0; np < 8; np++) {
                uint32_t b0, b1, b2, b3;
                ldsm4(b0, b1, b2, b3, bwA + np * (16 * TSTRIDE) + ks * 32);
                mma16816h(acc[2 * np],     aH[ks][0], aH[ks][1], aH[ks][2], aH[ks][3], b0, b1);
                mma16816h(acc[2 * np + 1], aH[ks][0], aH[ks][1], aH[ks][2], aH[ks][3], b2, b3);
            }
        }

        // ---- wait P1 prefetch (all but newest group = P1 done; stage may pend)
        CP_WAIT(1);
        __syncthreads();

        // ---- epilogue: read P1 from smem, P3 from global (L1-hot), write OUT
        {
            int d0 = sDst[er0], d1 = sDst[er0 + 8];
            const float* p3a = g_P3 + (size_t)d0 * HID;
            const float* p3b = g_P3 + (size_t)d1 * HID;
            const float* p1a = &OUT[er0 * 132];
            const float* p1b = &OUT[(er0 + 8) * 132];
#pragma unroll
            for (int nt = 0; nt < 16; nt++) {
                int col = nt * 8 + cb;
                float2 q1 = *(const float2*)(p1a + col);
                float2 q3 = *(const float2*)(p3a + col);
                float2 o0;
                o0.x = fmaxf(acc[nt][0] + sBm[col]     + q1.x + q3.x, 0.f);
                o0.y = fmaxf(acc[nt][1] + sBm[col + 1] + q1.y + q3.y, 0.f);
                *(float2*)&OUT[er0 * 132 + col] = o0;
                float2 r1 = *(const float2*)(p1b + col);
                float2 r3 = *(const float2*)(p3b + col);
                float2 o1;
                o1.x = fmaxf(acc[nt][2] + sBm[col]     + r1.x + r3.x, 0.f);
                o1.y = fmaxf(acc[nt][3] + sBm[col + 1] + r1.y + r3.y, 0.f);
                *(float2*)&OUT[(er0 + 8) * 132 + col] = o1;
            }
        }
        __syncthreads();

        // ---- segmented reduction (dst-sorted): one RED per (segment, col)
        {
            int col = tid;   // 0..127
            float s = 0.f;
            int cur = sDst[0];
#pragma unroll 4
            for (int r2 = 0; r2 < 64; r2++) {
                int dn = sDst[r2];
                if (dn != cur) {
                    if (s != 0.f) atomicAdd(&g_agg[(size_t)cur * HID + col], s);
                    cur = dn; s = 0.f;
                }
                s += OUT[r2 * 132 + col];
            }
            if (s != 0.f) atomicAdd(&g_agg[(size_t)cur * HID + col], s);
        }
        __syncthreads();
    }
}

// ---------------------------------------------------------------- update GEMM
__global__ void __launch_bounds__(256, 2)
upd_gemm(int layer, const float* __restrict__ W, const float* __restrict__ bias)
{
    const float* __restrict__ hn   = layer ? g_hn1 : g_hn0;
    float*       __restrict__ hout = layer ? g_hn0 : g_hn1;
    __shared__ __align__(16) float As[16][132];
    __shared__ __align__(16) float Bs[16][132];
    __shared__ float sB[128];

    const int tid   = threadIdx.x;
    const int nBase = blockIdx.x * 128;
    if (tid < 128) sB[tid] = bias[tid];
    __syncthreads();

    const int arow = tid >> 1;
    const int akl  = (tid & 1) * 8;
    const int tx   = tid & 15, ty = tid >> 4;
    const int nrow = min(nBase + arow, NN - 1);

    float acc[2][4][2][4];
#pragma unroll
    for (int a = 0; a < 2; a++)
#pragma unroll
        for (int i = 0; i < 4; i++)
#pragma unroll
            for (int b2 = 0; b2 < 2; b2++)
#pragma unroll
                for (int j = 0; j < 4; j++) acc[a][i][b2][j] = 0.f;

    float4 apf0, apf1, bpf0, bpf1;
    {
        const float* base = hn + (size_t)nrow * HID;
        apf0 = *(const float4*)(base + akl);
        apf1 = *(const float4*)(base + akl + 4);
        const float4* wb = (const float4*)W;
        bpf0 = wb[tid]; bpf1 = wb[tid + 256];
    }

    for (int t = 0; t < 16; t++) {
        As[akl + 0][arow] = apf0.x; As[akl + 1][arow] = apf0.y;
        As[akl + 2][arow] = apf0.z; As[akl + 3][arow] = apf0.w;
        As[akl + 4][arow] = apf1.x; As[akl + 5][arow] = apf1.y;
        As[akl + 6][arow] = apf1.z; As[akl + 7][arow] = apf1.w;
        {
            int k0 = tid >> 5, c0 = (tid & 31) * 4;
            *(float4*)&Bs[k0][c0]     = bpf0;
            *(float4*)&Bs[k0 + 8][c0] = bpf1;
        }
        __syncthreads();
        if (t < 15) {
            int kb = (t + 1) * 16;
            int seg = kb >> 7, off = kb & 127;
            const float* base = (seg == 0) ? hn + (size_t)nrow * HID + off
                                           : g_agg + (size_t)nrow * HID + off;
            apf0 = *(const float4*)(base + akl);
            apf1 = *(const float4*)(base + akl + 4);
            const float4* wb = (const float4*)(W + (size_t)kb * HID);
            bpf0 = wb[tid]; bpf1 = wb[tid + 256];
        }
#pragma unroll
        for (int k = 0; k < 16; k++) {
            float4 a0 = *(const float4*)&As[k][ty * 4];
            float4 a1 = *(const float4*)&As[k][64 + ty * 4];
            float4 b0 = *(const float4*)&Bs[k][tx * 4];
            float4 b1 = *(const float4*)&Bs[k][64 + tx * 4];
            float ar[8] = {a0.x, a0.y, a0.z, a0.w, a1.x, a1.y, a1.z, a1.w};
            float br[8] = {b0.x, b0.y, b0.z, b0.w, b1.x, b1.y, b1.z, b1.w};
#pragma unroll
            for (int a = 0; a < 2; a++)
#pragma unroll
                for (int i = 0; i < 4; i++)
#pragma unroll
                    for (int b2 = 0; b2 < 2; b2++)
#pragma unroll
                        for (int j = 0; j < 4; j++)
                            acc[a][i][b2][j] = fmaf(ar[a * 4 + i], br[b2 * 4 + j], acc[a][i][b2][j]);
        }
        __syncthreads();
    }

#pragma unroll
    for (int a = 0; a < 2; a++)
#pragma unroll
        for (int i = 0; i < 4; i++) {
            int r = nBase + a * 64 + ty * 4 + i;
            if (r < NN) {
#pragma unroll
                for (int b2 = 0; b2 < 2; b2++)
#pragma unroll
                    for (int j = 0; j < 4; j++) {
                        int c = b2 * 64 + tx * 4 + j;
                        hout[(size_t)r * HID + c] = fmaxf(acc[a][i][b2][j] + sB[c], 0.f);
                    }
            }
        }
}

// --------------------------------------------- fused demand readout
__global__ void __launch_bounds__(256)
dem_v2(const int* __restrict__ pairs, const float* __restrict__ dfeat,
       const float* __restrict__ Wd, const float* __restrict__ br1,
       const float* __restrict__ w2, const float* __restrict__ b2,
       float* __restrict__ out)
{
    __shared__ __align__(16) float Wds[8][132];
    __shared__ float w2s[128], bs[128];
    int tid = threadIdx.x;
    if (tid < 128) { w2s[tid] = w2[tid]; bs[tid] = br1[tid]; }
    {
        int row = tid >> 5, c = (tid & 31) * 4;
        *(float4*)&Wds[row][c] = ((const float4*)Wd)[tid];
    }
    __syncthreads();

    int w = tid >> 5, lane = tid & 31;
    int d = blockIdx.x * 8 + w;
    int ds = pairs[2 * d], dd = pairs[2 * d + 1];
    int c0 = lane * 4;

    float4 q1 = *(const float4*)(g_P1 + (size_t)ds * HID + c0);
    float4 q2 = *(const float4*)(g_P3 + (size_t)dd * HID + c0);
    float s0 = bs[c0 + 0] + q1.x + q2.x;
    float s1 = bs[c0 + 1] + q1.y + q2.y;
    float s2 = bs[c0 + 2] + q1.z + q2.z;
    float s3 = bs[c0 + 3] + q1.w + q2.w;
#pragma unroll
    for (int q = 0; q < 8; q++) {
        float e = dfeat[(size_t)d * 8 + q];
        float4 wv = *(const float4*)&Wds[q][c0];
        s0 = fmaf(e, wv.x, s0); s1 = fmaf(e, wv.y, s1);
        s2 = fmaf(e, wv.z, s2); s3 = fmaf(e, wv.w, s3);
    }
    float p = fmaxf(s0, 0.f) * w2s[c0 + 0] + fmaxf(s1, 0.f) * w2s[c0 + 1]
            + fmaxf(s2, 0.f) * w2s[c0 + 2] + fmaxf(s3, 0.f) * w2s[c0 + 3];
#pragma unroll
    for (int o = 16; o > 0; o >>= 1) p += __shfl_xor_sync(0xffffffffu, p, o);
    if (lane == 0) out[d] = 1.f / (1.f + expf(-(p + b2[0])));
}

// ---------------------------------------------------------------- launch
extern "C" void kernel_launch(void* const* d_in, const int* in_sizes, int n_in,
                              void* d_out, int out_size)
{
    const float* node_feats = (const float*)d_in[0];
    const float* edge_feats = (const float*)d_in[1];
    const float* dem_feats  = (const float*)d_in[2];
    const int*   eidx       = (const int*)d_in[3];
    const int*   pairs      = (const int*)d_in[4];
    const float* W_node = (const float*)d_in[5];
    const float* b_node = (const float*)d_in[6];
    const float* W_edge = (const float*)d_in[7];
    const float* b_edge = (const float*)d_in[8];
    const float* W_msg0 = (const float*)d_in[9];
    const float* b_msg0 = (const float*)d_in[10];
    const float* W_upd0 = (const float*)d_in[11];
    const float* b_upd0 = (const float*)d_in[12];
    const float* W_msg1 = (const float*)d_in[13];
    const float* b_msg1 = (const float*)d_in[14];
    const float* W_upd1 = (const float*)d_in[15];
    const float* b_upd1 = (const float*)d_in[16];
    const float* W_r1   = (const float*)d_in[17];
    const float* b_r1   = (const float*)d_in[18];
    const float* W_r2   = (const float*)d_in[19];
    const float* b_r2   = (const float*)d_in[20];
    float* out = (float*)d_out;

    const int nTiles = (NN + 127) / 128;

    cudaFuncSetAttribute(msg_v9, cudaFuncAttributeMaxDynamicSharedMemorySize, SM_TOTAL);

    // ---- edge sort by dst + ef fp16 pre-permute (one-time, reused by layers)
    zcnt<<<(NN + 256) / 256, 256>>>();
    hist<<<NE / 256, 256>>>(eidx);
    scan20k<<<1, 1024>>>();
    scatter<<<NE / 256, 256>>>(eidx, edge_feats);

    node_embed<<<NN / 16, 128>>>(node_feats, W_node, b_node);
    prep_w<<<2, 256>>>(W_msg0 + 128 * HID, W_msg1 + 128 * HID);

    // ---- layer 0
    gemm128x2<<<nTiles, 256>>>(0, W_msg0, W_msg0 + 256 * HID);
    zero_agg<<<(NN * HID / 4 + 255) / 256, 256>>>();
    msg_v9<<<304, 128, SM_TOTAL>>>(0, W_edge, b_edge, b_msg0);
    upd_gemm<<<nTiles, 256>>>(0, W_upd0, b_upd0);

    // ---- layer 1
    gemm128x2<<<nTiles, 256>>>(1, W_msg1, W_msg1 + 256 * HID);
    zero_agg<<<(NN * HID / 4 + 255) / 256, 256>>>();
    msg_v9<<<304, 128, SM_TOTAL>>>(1, W_edge, b_edge, b_msg1);
    upd_gemm<<<nTiles, 256>>>(1, W_upd1, b_upd1);

    // ---- readout
    gemm128x2<<<nTiles, 256>>>(0, W_r1, W_r1 + 128 * HID);
    dem_v2<<<ND / 8, 256>>>(pairs, dem_feats, W_r1 + 256 * HID, b_r1, W_r2, b_r2, out);
}

// round 10
// speedup vs baseline: 2.4014x; 1.2945x over previous
#include <cuda_runtime.h>
#include <cuda_fp16.h>
#include <math.h>
#include <stdint.h>

#define HID 128
#define NN 20000
#define NE 640000
#define ND 100000

// scratch (device globals: allocation-free contract)
__device__ float g_hn0[(size_t)NN * HID];
__device__ float g_hn1[(size_t)NN * HID];
__device__ float g_agg[(size_t)NN * HID];
__device__ float g_P1 [(size_t)NN * HID];
__device__ float g_P3 [(size_t)NN * HID];
// fp16 weight images, [n][k] row-major
__device__ __align__(16) __half g_Wh [2][128 * 128];  // W_mid
__device__ __align__(16) __half g_Wp1[3][128 * 128];  // P1 / Q1 weights
__device__ __align__(16) __half g_Wp3[3][128 * 128];  // P3 / Q2 weights
__device__ __align__(16) __half g_Wu [2][128 * 256];  // W_upd, [n][k=256]
// edge sort-by-dst (+ pre-permuted fp16 edge features)
__device__ int g_cnt[NN + 1];
__device__ int g_srcp[NE];
__device__ int g_dstp[NE];
__device__ __align__(16) __half g_efh[(size_t)NE * 16];

// ======================= helpers =======================
__device__ __forceinline__ uint32_t smem_u32(const void* p) {
    uint32_t a;
    asm("{ .reg .u64 t; cvta.to.shared.u64 t, %1; cvt.u32.u64 %0, t; }" : "=r"(a) : "l"(p));
    return a;
}
__device__ __forceinline__ void ldsm4(uint32_t& r0, uint32_t& r1, uint32_t& r2, uint32_t& r3,
                                      uint32_t addr) {
    asm volatile("ldmatrix.sync.aligned.m8n8.x4.shared.b16 {%0,%1,%2,%3}, [%4];"
                 : "=r"(r0), "=r"(r1), "=r"(r2), "=r"(r3) : "r"(addr));
}
__device__ __forceinline__ void mma16816h(float* c, uint32_t a0, uint32_t a1, uint32_t a2,
                                          uint32_t a3, uint32_t b0, uint32_t b1) {
    asm volatile("mma.sync.aligned.m16n8k16.row.col.f32.f16.f16.f32 "
                 "{%0,%1,%2,%3}, {%4,%5,%6,%7}, {%8,%9}, {%0,%1,%2,%3};"
                 : "+f"(c[0]), "+f"(c[1]), "+f"(c[2]), "+f"(c[3])
                 : "r"(a0), "r"(a1), "r"(a2), "r"(a3), "r"(b0), "r"(b1));
}
__device__ __forceinline__ uint32_t pack2h(float v0, float v1) {
    __half h0 = __float2half_rn(v0);
    __half h1 = __float2half_rn(v1);
    return (uint32_t)__half_as_ushort(h0) | ((uint32_t)__half_as_ushort(h1) << 16);
}
__device__ __forceinline__ void cp16(uint32_t smem_dst, const void* gsrc) {
    asm volatile("cp.async.cg.shared.global [%0], [%1], 16;"
                 :: "r"(smem_dst), "l"(gsrc) : "memory");
}
#define CP_COMMIT()  asm volatile("cp.async.commit_group;" ::: "memory")
#define CP_WAIT(N)   asm volatile("cp.async.wait_group %0;" :: "n"(N) : "memory")

// ---------------------------------------------------------------- sort by dst
__global__ void zcnt()
{
    int i = blockIdx.x * 256 + threadIdx.x;
    if (i <= NN) g_cnt[i] = 0;
}
__global__ void hist(const int* __restrict__ eidx)
{
    int e = blockIdx.x * 256 + threadIdx.x;
    atomicAdd(&g_cnt[eidx[NE + e]], 1);
}
__global__ void scan20k()
{
    __shared__ int part[1024];
    __shared__ int wsum[32];
    const int tid = threadIdx.x;
    const int CH = 20;
    int base = tid * CH;
    int loc[CH];
    int s = 0;
#pragma unroll
    for (int i = 0; i < CH; i++) {
        int v = (base + i <= NN) ? g_cnt[base + i] : 0;
        loc[i] = s; s += v;
    }
    part[tid] = s;
    __syncthreads();
    int lane = tid & 31, w = tid >> 5;
    int v = part[tid];
#pragma unroll
    for (int o = 1; o < 32; o <<= 1) { int t = __shfl_up_sync(~0u, v, o); if (lane >= o) v += t; }
    if (lane == 31) wsum[w] = v;
    __syncthreads();
    if (w == 0) {
        int x = wsum[lane];
#pragma unroll
        for (int o = 1; o < 32; o <<= 1) { int t = __shfl_up_sync(~0u, x, o); if (lane >= o) x += t; }
        wsum[lane] = x;
    }
    __syncthreads();
    int excl = v - part[tid] + (w ? wsum[w - 1] : 0);
#pragma unroll
    for (int i = 0; i < CH; i++)
        if (base + i <= NN) g_cnt[base + i] = excl + loc[i];
}
// scatter: sort edges by dst AND pre-permute ef rows as fp16
__global__ void scatter(const int* __restrict__ eidx, const float* __restrict__ ef)
{
    int e = blockIdx.x * 256 + threadIdx.x;
    int s = eidx[e], d = eidx[NE + e];
    int p = atomicAdd(&g_cnt[d], 1);
    g_srcp[p] = s; g_dstp[p] = d;
    const float4* eg = (const float4*)(ef + (size_t)e * 16);
    float4 v0 = eg[0], v1 = eg[1], v2 = eg[2], v3 = eg[3];
    uint4* dh = (uint4*)(g_efh + (size_t)p * 16);
    dh[0] = make_uint4(pack2h(v0.x, v0.y), pack2h(v0.z, v0.w),
                       pack2h(v1.x, v1.y), pack2h(v1.z, v1.w));
    dh[1] = make_uint4(pack2h(v2.x, v2.y), pack2h(v2.z, v2.w),
                       pack2h(v3.x, v3.y), pack2h(v3.z, v3.w));
}

// ---------------------------------------------------------------- node embed
__global__ void node_embed(const float* __restrict__ x, const float* __restrict__ W,
                           const float* __restrict__ b)
{
    __shared__ float Ws[32 * HID];
    __shared__ float xs[16][33];
    int tid = threadIdx.x; // 128
    for (int i = tid; i < 32 * HID; i += 128) Ws[i] = W[i];
    int row0 = blockIdx.x * 16;
    for (int i = tid; i < 16 * 32; i += 128) xs[i >> 5][i & 31] = x[(size_t)row0 * 32 + i];
    float bb = b[tid];
    __syncthreads();
#pragma unroll 4
    for (int r = 0; r < 16; r++) {
        float acc = bb;
#pragma unroll
        for (int k = 0; k < 32; k++) acc = fmaf(xs[r][k], Ws[k * HID + tid], acc);
        g_hn0[(size_t)(row0 + r) * HID + tid] = fmaxf(acc, 0.f);
    }
}

// ------------------------------ weight prep: all fp16 [n][k] images
__global__ void prep_all(const float* __restrict__ Wm0, const float* __restrict__ Wm1,
                         const float* __restrict__ Wu0, const float* __restrict__ Wu1,
                         const float* __restrict__ Wr1)
{
    int b = blockIdx.x;
    if (b < 8) {
        const float* src; __half* dst;
        switch (b) {
            case 0: src = Wm0 + 128 * 128; dst = g_Wh[0];  break;
            case 1: src = Wm1 + 128 * 128; dst = g_Wh[1];  break;
            case 2: src = Wm0;             dst = g_Wp1[0]; break;
            case 3: src = Wm1;             dst = g_Wp1[1]; break;
            case 4: src = Wm0 + 256 * 128; dst = g_Wp3[0]; break;
            case 5: src = Wm1 + 256 * 128; dst = g_Wp3[1]; break;
            case 6: src = Wr1;             dst = g_Wp1[2]; break;
            default: src = Wr1 + 128 * 128; dst = g_Wp3[2]; break;
        }
        for (int idx = threadIdx.x; idx < 128 * 128; idx += 256) {
            int n = idx >> 7, k = idx & 127;
            dst[idx] = __float2half_rn(src[k * 128 + n]);
        }
    } else {
        const float* src = (b == 8) ? Wu0 : Wu1;
        __half* dst = g_Wu[b - 8];
        for (int idx = threadIdx.x; idx < 128 * 256; idx += 256) {
            int n = idx >> 8, k = idx & 255;
            dst[idx] = __float2half_rn(src[k * 128 + n]);
        }
    }
}

// ---------------- fp16 node-level dual GEMM: P1 = A@W1, P3 = A@W3 (+agg zero)
#define GX_A 0
#define GX_W 34816            // [256 rows][136 fp16] (W1 rows 0-127, W3 128-255)
#define GX_TOTAL 104448
#define GXST 272

__global__ void __launch_bounds__(256)
gemmx2h(int asel, int img, int zflag)
{
    extern __shared__ __align__(16) char smem[];
    const uint32_t sb = smem_u32(smem);
    const float* __restrict__ A = asel ? g_hn1 : g_hn0;
    const int tid = threadIdx.x;
    const int wid = tid >> 5, lane = tid & 31;
    const int nBase = blockIdx.x * 128;

    // stage A (fp32 -> fp16) [128][136]
    {
        int r = tid >> 1, u = tid & 1;
        int nrow = min(nBase + r, NN - 1);
        const float4* src = (const float4*)(A + (size_t)nrow * HID) + u * 16;
        uint32_t dst = sb + GX_A + r * GXST + u * 128;
#pragma unroll
        for (int q = 0; q < 8; q++) {
            float4 a = src[2 * q], bv = src[2 * q + 1];
            *(uint4*)(smem + (dst - sb) + q * 16) =
                make_uint4(pack2h(a.x, a.y), pack2h(a.z, a.w),
                           pack2h(bv.x, bv.y), pack2h(bv.z, bv.w));
        }
    }
    // stage W1/W3 images (copy, contiguous)
    {
        const uint4* w1 = (const uint4*)g_Wp1[img];
        const uint4* w3 = (const uint4*)g_Wp3[img];
#pragma unroll
        for (int i = 0; i < 8; i++) {
            int g = tid + i * 256;              // 0..2047
            int n = g >> 4, q = g & 15;
            *(uint4*)(smem + GX_W + n * GXST + q * 16) = w1[g];
            *(uint4*)(smem + GX_W + (n + 128) * GXST + q * 16) = w3[g];
        }
    }
    // zero agg rows for this tile
    if (zflag) {
#pragma unroll
        for (int i = 0; i < 16; i++) {
            int g = tid + i * 256;              // 0..4095
            int r = g >> 5, c = (g & 31) * 4;
            int row = nBase + r;
            if (row < NN)
                *(float4*)&g_agg[(size_t)row * HID + c] = make_float4(0.f, 0.f, 0.f, 0.f);
        }
    }
    __syncthreads();

    const int wm = wid * 16;
    const uint32_t aA = sb + GX_A + (uint32_t)((wm + (lane & 7) + ((lane >> 3) & 1) * 8) * GXST
                                               + (lane >> 4) * 16);
    const uint32_t bOff = (uint32_t)(((lane & 7) + (lane >> 4) * 8) * GXST
                                     + (((lane >> 3) & 1) * 8) * 2);
    const int er0 = wm + (lane >> 2);
    const int cb  = (lane & 3) * 2;
    const int row0 = nBase + er0, row1 = row0 + 8;

    uint32_t aH[8][4];
#pragma unroll
    for (int ks = 0; ks < 8; ks++)
        ldsm4(aH[ks][0], aH[ks][1], aH[ks][2], aH[ks][3], aA + ks * 32);

#pragma unroll
    for (int half = 0; half < 2; half++) {
        const uint32_t bA = sb + GX_W + half * (128 * GXST) + bOff;
        float acc[16][4];
#pragma unroll
        for (int n = 0; n < 16; n++)
#pragma unroll
            for (int j = 0; j < 4; j++) acc[n][j] = 0.f;
#pragma unroll
        for (int ks = 0; ks < 8; ks++) {
#pragma unroll
            for (int np = 0; np < 8; np++) {
                uint32_t b0, b1, b2, b3;
                ldsm4(b0, b1, b2, b3, bA + np * (16 * GXST) + ks * 32);
                mma16816h(acc[2 * np],     aH[ks][0], aH[ks][1], aH[ks][2], aH[ks][3], b0, b1);
                mma16816h(acc[2 * np + 1], aH[ks][0], aH[ks][1], aH[ks][2], aH[ks][3], b2, b3);
            }
        }
        float* out = half ? g_P3 : g_P1;
#pragma unroll
        for (int nt = 0; nt < 16; nt++) {
            int col = nt * 8 + cb;
            if (row0 < NN)
                *(float2*)&out[(size_t)row0 * HID + col] = make_float2(acc[nt][0], acc[nt][1]);
            if (row1 < NN)
                *(float2*)&out[(size_t)row1 * HID + col] = make_float2(acc[nt][2], acc[nt][3]);
        }
    }
}

// ---------------- fp16 update GEMM: hout = relu([hn|agg] @ Wu + b), K=256
#define UP_A 0
#define UP_W 67584            // [128][264 fp16]
#define UP_B 135168           // bias 512B
#define UP_TOTAL 135680
#define UPST 528

__global__ void __launch_bounds__(256)
upd_h(int layer, const float* __restrict__ bias)
{
    extern __shared__ __align__(16) char smem[];
    const uint32_t sb = smem_u32(smem);
    const float* __restrict__ hn   = layer ? g_hn1 : g_hn0;
    float*       __restrict__ hout = layer ? g_hn0 : g_hn1;
    const int tid = threadIdx.x;
    const int wid = tid >> 5, lane = tid & 31;
    const int nBase = blockIdx.x * 128;
    float* sB = (float*)(smem + UP_B);

    if (tid < 128) sB[tid] = bias[tid];
    // stage A = [hn | agg] fp16 [128][264]
    {
        int r = tid >> 1, u = tid & 1;
        int nrow = min(nBase + r, NN - 1);
        const float4* src = (const float4*)((u ? g_agg : hn) + (size_t)nrow * HID);
        uint32_t dbase = (uint32_t)(UP_A + r * UPST + u * 256);
#pragma unroll
        for (int q = 0; q < 16; q++) {
            float4 a = src[2 * q], bv = src[2 * q + 1];
            *(uint4*)(smem + dbase + q * 16) =
                make_uint4(pack2h(a.x, a.y), pack2h(a.z, a.w),
                           pack2h(bv.x, bv.y), pack2h(bv.z, bv.w));
        }
    }
    // stage W image [128][264] (copy)
    {
        const uint4* w = (const uint4*)g_Wu[layer];
#pragma unroll
        for (int i = 0; i < 16; i++) {
            int g = tid + i * 256;              // 0..4095
            int n = g >> 5, q = g & 31;
            *(uint4*)(smem + UP_W + n * UPST + q * 16) = w[g];
        }
    }
    __syncthreads();

    const int wm = wid * 16;
    const uint32_t aA = sb + UP_A + (uint32_t)((wm + (lane & 7) + ((lane >> 3) & 1) * 8) * UPST
                                               + (lane >> 4) * 16);
    const uint32_t bA = sb + UP_W + (uint32_t)(((lane & 7) + (lane >> 4) * 8) * UPST
                                               + (((lane >> 3) & 1) * 8) * 2);
    const int er0 = wm + (lane >> 2);
    const int cb  = (lane & 3) * 2;
    const int row0 = nBase + er0, row1 = row0 + 8;

    float acc[16][4];
#pragma unroll
    for (int n = 0; n < 16; n++)
#pragma unroll
        for (int j = 0; j < 4; j++) acc[n][j] = 0.f;

#pragma unroll
    for (int ks = 0; ks < 16; ks++) {
        uint32_t a0, a1, a2, a3;
        ldsm4(a0, a1, a2, a3, aA + ks * 32);
#pragma unroll
        for (int np = 0; np < 8; np++) {
            uint32_t b0, b1, b2, b3;
            ldsm4(b0, b1, b2, b3, bA + np * (16 * UPST) + ks * 32);
            mma16816h(acc[2 * np],     a0, a1, a2, a3, b0, b1);
            mma16816h(acc[2 * np + 1], a0, a1, a2, a3, b2, b3);
        }
    }

#pragma unroll
    for (int nt = 0; nt < 16; nt++) {
        int col = nt * 8 + cb;
        float b0 = sB[col], b1 = sB[col + 1];
        if (row0 < NN)
            *(float2*)&hout[(size_t)row0 * HID + col] =
                make_float2(fmaxf(acc[nt][0] + b0, 0.f), fmaxf(acc[nt][1] + b1, 0.f));
        if (row1 < NN)
            *(float2*)&hout[(size_t)row1 * HID + col] =
                make_float2(fmaxf(acc[nt][2] + b0, 0.f), fmaxf(acc[nt][3] + b1, 0.f));
    }
}

// ====================== pipelined fp16 MMA-chain edge kernel ================
// M=64 tile, 128 threads, 2 CTAs/SM, cp.async double-buffered staging
#define SM_BM    0
#define SM_BE    512
#define SM_IDX   1024           // 2 bufs x (src 256B + dst 256B)
#define SM_WEH   2048           // fp16 [128][24] (48B stride)
#define SM_EFH0  8192           // fp16 [64][24] x2 bufs
#define SM_EFH1  11264
#define SM_BW    14336          // fp16 [128][136] W_mid image
#define SM_OUT   49152          // fp32 [64][132] — doubles as P1 buffer
#define SM_TOTAL 82944
#define TSTRIDE  272
#define EFST     48

__global__ void __launch_bounds__(128, 2)
msg_v10(int layer, const float* __restrict__ We, const float* __restrict__ be,
        const float* __restrict__ bm)
{
    extern __shared__ __align__(16) char smem[];
    const uint32_t sb = smem_u32(smem);
    const int tid = threadIdx.x;
    const int wid = tid >> 5, lane = tid & 31;

    float* sBm = (float*)(smem + SM_BM);
    float* beS = (float*)(smem + SM_BE);
    float* OUT = (float*)(smem + SM_OUT);

    // ---- one-time setup
    sBm[tid] = bm[tid]; beS[tid] = be[tid];
    {   // stage We^T fp16: row n = tid, 16 k values (column n of We)
        int n = tid;
        uint32_t h8[8];
#pragma unroll
        for (int p = 0; p < 8; p++)
            h8[p] = pack2h(We[(2 * p) * 128 + n], We[(2 * p + 1) * 128 + n]);
        *(uint4*)(smem + SM_WEH + n * EFST)      = make_uint4(h8[0], h8[1], h8[2], h8[3]);
        *(uint4*)(smem + SM_WEH + n * EFST + 16) = make_uint4(h8[4], h8[5], h8[6], h8[7]);
    }
    {   // stage W_mid fp16 image [n][136]
        const uint4* wsrc = (const uint4*)g_Wh[layer];
#pragma unroll
        for (int u = 0; u < 16; u++) {
            int g = tid + u * 128;
            int n = g >> 4, q = g & 15;
            *(uint4*)(smem + SM_BW + n * TSTRIDE + q * 16) = wsrc[g];
        }
    }

    const int wm = wid * 16;
    const uint32_t aEfOff = (uint32_t)((wm + (lane & 7) + ((lane >> 3) & 1) * 8) * EFST
                                       + (lane >> 4) * 16);
    const uint32_t bEfOff = (uint32_t)(((lane & 7) + (lane >> 4) * 8) * EFST
                                       + ((lane >> 3) & 1) * 16);
    const uint32_t bMnOff = (uint32_t)(((lane & 7) + (lane >> 4) * 8) * TSTRIDE
                                       + (((lane >> 3) & 1) * 8) * 2);
    const uint32_t wehA = sb + SM_WEH + bEfOff;
    const uint32_t bwA  = sb + SM_BW + bMnOff;

    const int er0 = wm + (lane >> 2);
    const int cb  = (lane & 3) * 2;

    const int NT = NE / 64;

    auto stage_async = [&](int t, int b) {
        const int eBase = t * 64;
        uint32_t efh = sb + (b ? SM_EFH1 : SM_EFH0);
        {
            int r = tid >> 1, u = tid & 1;
            cp16(efh + r * EFST + u * 16, (const char*)(g_efh + (size_t)(eBase + r) * 16) + u * 16);
        }
        if (tid < 16)
            cp16(sb + SM_IDX + b * 512 + tid * 16, (const char*)(g_srcp + eBase) + tid * 16);
        else if (tid < 32)
            cp16(sb + SM_IDX + b * 512 + 256 + (tid - 16) * 16, (const char*)(g_dstp + eBase) + (tid - 16) * 16);
    };

    int t = blockIdx.x;
    int buf = 0;
    if (t < NT) stage_async(t, 0);
    CP_COMMIT();

    for (; t < NT; t += gridDim.x, buf ^= 1) {
        CP_WAIT(0);
        __syncthreads();

        int* sSrc = (int*)(smem + SM_IDX + buf * 512);
        int* sDst = (int*)(smem + SM_IDX + buf * 512 + 256);

        // ---- P1 gather prefetch into OUT buffer (oldest group)
        {
#pragma unroll
            for (int i = 0; i < 16; i++) {
                int g = tid + i * 128;
                int r = g >> 5, c = g & 31;
                const char* src = (const char*)(g_P1 + (size_t)sSrc[r] * HID) + c * 16;
                cp16(sb + SM_OUT + r * 528 + c * 16, src);
            }
        }
        CP_COMMIT();

        int tn = t + gridDim.x;
        if (tn < NT) stage_async(tn, buf ^ 1);
        CP_COMMIT();

        // ---- he GEMM (K=16, single fp16 product) -> acc2 registers
        const uint32_t efhA = sb + (buf ? SM_EFH1 : SM_EFH0) + aEfOff;
        float acc2[16][4];
#pragma unroll
        for (int n = 0; n < 16; n++)
#pragma unroll
            for (int j = 0; j < 4; j++) acc2[n][j] = 0.f;
        {
            uint32_t eh0, eh1, eh2, eh3;
            ldsm4(eh0, eh1, eh2, eh3, efhA);
#pragma unroll
            for (int g = 0; g < 8; g++) {
                uint32_t wh0, wh1, wh2, wh3;
                ldsm4(wh0, wh1, wh2, wh3, wehA + g * (16 * EFST));
                mma16816h(acc2[2 * g],     eh0, eh1, eh2, eh3, wh0, wh1);
                mma16816h(acc2[2 * g + 1], eh0, eh1, eh2, eh3, wh2, wh3);
            }
        }

        // ---- bias + relu + fp16 round -> main-GEMM A fragments
        uint32_t aH[8][4];
#pragma unroll
        for (int nt = 0; nt < 16; nt++) {
            int col = nt * 8 + cb;
            float be0 = beS[col], be1 = beS[col + 1];
            float v0 = fmaxf(acc2[nt][0] + be0, 0.f);
            float v1 = fmaxf(acc2[nt][1] + be1, 0.f);
            float v2 = fmaxf(acc2[nt][2] + be0, 0.f);
            float v3 = fmaxf(acc2[nt][3] + be1, 0.f);
            int ks = nt >> 1, j0 = (nt & 1) * 2;
            aH[ks][j0]     = pack2h(v0, v1);
            aH[ks][j0 + 1] = pack2h(v2, v3);
        }

        // ---- main GEMM: D = Ah*W
        float acc[16][4];
#pragma unroll
        for (int n = 0; n < 16; n++)
#pragma unroll
            for (int j = 0; j < 4; j++) acc[n][j] = 0.f;
#pragma unroll
        for (int ks = 0; ks < 8; ks++) {
#pragma unroll
            for (int np = 0; np < 8; np++) {
                uint32_t b0, b1, b2, b3;
                ldsm4(b0, b1, b2, b3, bwA + np * (16 * TSTRIDE) + ks * 32);
                mma16816h(acc[2 * np],     aH[ks][0], aH[ks][1], aH[ks][2], aH[ks][3], b0, b1);
                mma16816h(acc[2 * np + 1], aH[ks][0], aH[ks][1], aH[ks][2], aH[ks][3], b2, b3);
            }
        }

        CP_WAIT(1);
        __syncthreads();

        // ---- epilogue: P1 from smem, P3 from global (L1-hot), write OUT
        {
            int d0 = sDst[er0], d1 = sDst[er0 + 8];
            const float* p3a = g_P3 + (size_t)d0 * HID;
            const float* p3b = g_P3 + (size_t)d1 * HID;
            const float* p1a = &OUT[er0 * 132];
            const float* p1b = &OUT[(er0 + 8) * 132];
#pragma unroll
            for (int nt = 0; nt < 16; nt++) {
                int col = nt * 8 + cb;
                float2 q1 = *(const float2*)(p1a + col);
                float2 q3 = *(const float2*)(p3a + col);
                float2 o0;
                o0.x = fmaxf(acc[nt][0] + sBm[col]     + q1.x + q3.x, 0.f);
                o0.y = fmaxf(acc[nt][1] + sBm[col + 1] + q1.y + q3.y, 0.f);
                *(float2*)&OUT[er0 * 132 + col] = o0;
                float2 r1 = *(const float2*)(p1b + col);
                float2 r3 = *(const float2*)(p3b + col);
                float2 o1;
                o1.x = fmaxf(acc[nt][2] + sBm[col]     + r1.x + r3.x, 0.f);
                o1.y = fmaxf(acc[nt][3] + sBm[col + 1] + r1.y + r3.y, 0.f);
                *(float2*)&OUT[(er0 + 8) * 132 + col] = o1;
            }
        }
        __syncthreads();

        // ---- segmented reduction (dst-sorted)
        {
            int col = tid;
            float s = 0.f;
            int cur = sDst[0];
#pragma unroll 4
            for (int r2 = 0; r2 < 64; r2++) {
                int dn = sDst[r2];
                if (dn != cur) {
                    if (s != 0.f) atomicAdd(&g_agg[(size_t)cur * HID + col], s);
                    cur = dn; s = 0.f;
                }
                s += OUT[r2 * 132 + col];
            }
            if (s != 0.f) atomicAdd(&g_agg[(size_t)cur * HID + col], s);
        }
        __syncthreads();
    }
}

// --------------------------------------------- fused demand readout
__global__ void __launch_bounds__(256)
dem_v2(const int* __restrict__ pairs, const float* __restrict__ dfeat,
       const float* __restrict__ Wd, const float* __restrict__ br1,
       const float* __restrict__ w2, const float* __restrict__ b2,
       float* __restrict__ out)
{
    __shared__ __align__(16) float Wds[8][132];
    __shared__ float w2s[128], bs[128];
    int tid = threadIdx.x;
    if (tid < 128) { w2s[tid] = w2[tid]; bs[tid] = br1[tid]; }
    {
        int row = tid >> 5, c = (tid & 31) * 4;
        *(float4*)&Wds[row][c] = ((const float4*)Wd)[tid];
    }
    __syncthreads();

    int w = tid >> 5, lane = tid & 31;
    int d = blockIdx.x * 8 + w;
    int ds = pairs[2 * d], dd = pairs[2 * d + 1];
    int c0 = lane * 4;

    float4 q1 = *(const float4*)(g_P1 + (size_t)ds * HID + c0);
    float4 q2 = *(const float4*)(g_P3 + (size_t)dd * HID + c0);
    float s0 = bs[c0 + 0] + q1.x + q2.x;
    float s1 = bs[c0 + 1] + q1.y + q2.y;
    float s2 = bs[c0 + 2] + q1.z + q2.z;
    float s3 = bs[c0 + 3] + q1.w + q2.w;
#pragma unroll
    for (int q = 0; q < 8; q++) {
        float e = dfeat[(size_t)d * 8 + q];
        float4 wv = *(const float4*)&Wds[q][c0];
        s0 = fmaf(e, wv.x, s0); s1 = fmaf(e, wv.y, s1);
        s2 = fmaf(e, wv.z, s2); s3 = fmaf(e, wv.w, s3);
    }
    float p = fmaxf(s0, 0.f) * w2s[c0 + 0] + fmaxf(s1, 0.f) * w2s[c0 + 1]
            + fmaxf(s2, 0.f) * w2s[c0 + 2] + fmaxf(s3, 0.f) * w2s[c0 + 3];
#pragma unroll
    for (int o = 16; o > 0; o >>= 1) p += __shfl_xor_sync(0xffffffffu, p, o);
    if (lane == 0) out[d] = 1.f / (1.f + expf(-(p + b2[0])));
}

// ---------------------------------------------------------------- launch
extern "C" void kernel_launch(void* const* d_in, const int* in_sizes, int n_in,
                              void* d_out, int out_size)
{
    const float* node_feats = (const float*)d_in[0];
    const float* edge_feats = (const float*)d_in[1];
    const float* dem_feats  = (const float*)d_in[2];
    const int*   eidx       = (const int*)d_in[3];
    const int*   pairs      = (const int*)d_in[4];
    const float* W_node = (const float*)d_in[5];
    const float* b_node = (const float*)d_in[6];
    const float* W_edge = (const float*)d_in[7];
    const float* b_edge = (const float*)d_in[8];
    const float* W_msg0 = (const float*)d_in[9];
    const float* b_msg0 = (const float*)d_in[10];
    const float* W_upd0 = (const float*)d_in[11];
    const float* b_upd0 = (const float*)d_in[12];
    const float* W_msg1 = (const float*)d_in[13];
    const float* b_msg1 = (const float*)d_in[14];
    const float* W_upd1 = (const float*)d_in[15];
    const float* b_upd1 = (const float*)d_in[16];
    const float* W_r1   = (const float*)d_in[17];
    const float* b_r1   = (const float*)d_in[18];
    const float* W_r2   = (const float*)d_in[19];
    const float* b_r2   = (const float*)d_in[20];
    float* out = (float*)d_out;

    const int nTiles = (NN + 127) / 128;

    cudaFuncSetAttribute(msg_v10, cudaFuncAttributeMaxDynamicSharedMemorySize, SM_TOTAL);
    cudaFuncSetAttribute(gemmx2h, cudaFuncAttributeMaxDynamicSharedMemorySize, GX_TOTAL);
    cudaFuncSetAttribute(upd_h,   cudaFuncAttributeMaxDynamicSharedMemorySize, UP_TOTAL);

    // ---- edge sort by dst + ef fp16 pre-permute
    zcnt<<<(NN + 256) / 256, 256>>>();
    hist<<<NE / 256, 256>>>(eidx);
    scan20k<<<1, 1024>>>();
    scatter<<<NE / 256, 256>>>(eidx, edge_feats);

    node_embed<<<NN / 16, 128>>>(node_feats, W_node, b_node);
    prep_all<<<10, 256>>>(W_msg0, W_msg1, W_upd0, W_upd1, W_r1);

    // ---- layer 0
    gemmx2h<<<nTiles, 256, GX_TOTAL>>>(0, 0, 1);
    msg_v10<<<304, 128, SM_TOTAL>>>(0, W_edge, b_edge, b_msg0);
    upd_h<<<nTiles, 256, UP_TOTAL>>>(0, b_upd0);

    // ---- layer 1
    gemmx2h<<<nTiles, 256, GX_TOTAL>>>(1, 1, 1);
    msg_v10<<<304, 128, SM_TOTAL>>>(1, W_edge, b_edge, b_msg1);
    upd_h<<<nTiles, 256, UP_TOTAL>>>(1, b_upd1);

    // ---- readout
    gemmx2h<<<nTiles, 256, GX_TOTAL>>>(0, 2, 0);
    dem_v2<<<ND / 8, 256>>>(pairs, dem_feats, W_r1 + 256 * HID, b_r1, W_r2, b_r2, out);
}